// round 2
// baseline (speedup 1.0000x reference)
#include <cuda_runtime.h>
#include <math.h>

#define BDIM 1024
#define SEQ  1024
#define NB   4
#define NH   16
#define DHD  64

// ---------------- scratch (static device memory: allocation-free) ----------------
__device__ float g_Q[NB * SEQ * BDIM];
__device__ float g_K[NB * SEQ * BDIM];
__device__ float g_V[NB * SEQ * BDIM];
__device__ float g_O[NB * SEQ * BDIM];
__device__ float g_LG[NB * NH * SEQ];

// ---------------- generic 128x128x8 register-blocked SGEMM (row-major) ----------------
// C[M,N] = A[M,K] * B[K,N].  M,N multiples of 128; K multiple of 8. 256 threads.
__global__ __launch_bounds__(256) void sgemm128(const float* __restrict__ A,
                                                const float* __restrict__ B,
                                                float* __restrict__ C,
                                                int M, int N, int K)
{
    __shared__ float As[8][128];   // transposed A tile
    __shared__ float Bs[8][128];

    const int tid = threadIdx.x;
    const int tx  = tid & 15;      // 0..15  -> N direction (8 cols each)
    const int ty  = tid >> 4;      // 0..15  -> M direction (8 rows each)

    const float* Ab = A + (size_t)(blockIdx.y * 128) * K;
    const float* Bb = B + blockIdx.x * 128;

    float acc[8][8];
#pragma unroll
    for (int i = 0; i < 8; i++)
#pragma unroll
        for (int j = 0; j < 8; j++) acc[i][j] = 0.f;

    const int arow = tid >> 1;          // 0..127
    const int acol = (tid & 1) * 4;     // 0 or 4
    const int brow = tid >> 5;          // 0..7
    const int bcol = (tid & 31) * 4;    // 0..124

    for (int k0 = 0; k0 < K; k0 += 8) {
        float4 a4 = *(const float4*)(Ab + (size_t)arow * K + k0 + acol);
        As[acol + 0][arow] = a4.x;
        As[acol + 1][arow] = a4.y;
        As[acol + 2][arow] = a4.z;
        As[acol + 3][arow] = a4.w;
        float4 b4 = *(const float4*)(Bb + (size_t)(k0 + brow) * N + bcol);
        *(float4*)&Bs[brow][bcol] = b4;
        __syncthreads();

#pragma unroll
        for (int kk = 0; kk < 8; kk++) {
            float4 a0 = *(const float4*)&As[kk][ty * 8];
            float4 a1 = *(const float4*)&As[kk][ty * 8 + 4];
            float4 b0 = *(const float4*)&Bs[kk][tx * 8];
            float4 b1 = *(const float4*)&Bs[kk][tx * 8 + 4];
            float ra[8] = {a0.x, a0.y, a0.z, a0.w, a1.x, a1.y, a1.z, a1.w};
            float rb[8] = {b0.x, b0.y, b0.z, b0.w, b1.x, b1.y, b1.z, b1.w};
#pragma unroll
            for (int i = 0; i < 8; i++)
#pragma unroll
                for (int j = 0; j < 8; j++)
                    acc[i][j] = fmaf(ra[i], rb[j], acc[i][j]);
        }
        __syncthreads();
    }

    float* Cb = C + (size_t)(blockIdx.y * 128 + ty * 8) * N + blockIdx.x * 128 + tx * 8;
#pragma unroll
    for (int i = 0; i < 8; i++) {
        *(float4*)(Cb + (size_t)i * N)     = make_float4(acc[i][0], acc[i][1], acc[i][2], acc[i][3]);
        *(float4*)(Cb + (size_t)i * N + 4) = make_float4(acc[i][4], acc[i][5], acc[i][6], acc[i][7]);
    }
}

// ---------------- phase + per-head log-gate ----------------
// one block (128 threads) per token
__global__ __launch_bounds__(128) void phase_gate(const float* __restrict__ x,
                                                  const float* __restrict__ w_phase,
                                                  const float* __restrict__ carrier,
                                                  const float* __restrict__ lock,
                                                  const float* __restrict__ bw,
                                                  float* __restrict__ lg)
{
    const int token = blockIdx.x;
    const float* xr = x + (size_t)token * BDIM;
    const int tid = threadIdx.x;

    float p0 = 0.f, p1 = 0.f;
    for (int d = tid; d < BDIM; d += 128) {
        float xv = xr[d];
        p0 = fmaf(xv, w_phase[2 * d],     p0);
        p1 = fmaf(xv, w_phase[2 * d + 1], p1);
    }
#pragma unroll
    for (int o = 16; o > 0; o >>= 1) {
        p0 += __shfl_down_sync(0xffffffffu, p0, o);
        p1 += __shfl_down_sync(0xffffffffu, p1, o);
    }
    __shared__ float s0[4], s1[4];
    __shared__ float phs;
    if ((tid & 31) == 0) { s0[tid >> 5] = p0; s1[tid >> 5] = p1; }
    __syncthreads();
    if (tid == 0) {
        float a = s0[0] + s0[1] + s0[2] + s0[3];
        float b = s1[0] + s1[1] + s1[2] + s1[3];
        phs = atan2f(a, b);   // arctan2(ph0, ph1)
    }
    __syncthreads();
    if (tid < NH) {
        const int h = tid;
        float dphi = phs - carrier[h];
        float w = expf((cosf(dphi) - 1.f) / bw[h]);
        float g = lock[h] * w + (1.f - lock[h]);
        const int b = token / SEQ, s = token % SEQ;
        lg[((size_t)b * NH + h) * SEQ + s] = logf(g + 1e-6f);
    }
}

// ---------------- flash attention with resonance gate, causal, head-skip ----------------
// 64x64 tiles, 256 threads (16x16, each owning a 4x4 micro-tile)
// XOR swizzle to avoid bank conflicts on transposed stores
#define SWZ(d, c) ((c) ^ (((((unsigned)(d)) >> 2) & 15u) << 2))

__global__ __launch_bounds__(256) void attn_kernel(const int* __restrict__ active)
{
    __shared__ float Qs[64][64];   // [dh][q] swizzled
    __shared__ float KVs[64][64];  // K: [dh][k] swizzled, then V: [k][d] plain
    __shared__ float Ps[64][64];   // [k][q] swizzled

    const int q0  = blockIdx.x * 64;
    const int h   = blockIdx.y;
    const int b   = blockIdx.z;
    const int tid = threadIdx.x;
    const int tx  = tid & 15;   // key / dh-out direction (4 each)
    const int ty  = tid >> 4;   // query direction (4 each)

    const size_t base = ((size_t)b * SEQ) * BDIM + (size_t)h * DHD;

    if (active[h] == 0) {
        // dormant head: O tile = 0
        const int r0 = tid >> 4, d = (tid & 15) * 4;
#pragma unroll
        for (int rr = 0; rr < 4; rr++) {
            int r = r0 + rr * 16;
            *(float4*)(g_O + base + (size_t)(q0 + r) * BDIM + d) = make_float4(0.f, 0.f, 0.f, 0.f);
        }
        return;
    }

    // load Q tile transposed ([dh][q], swizzled)
    {
        const int dh = (tid & 15) * 4;
#pragma unroll
        for (int rr = 0; rr < 4; rr++) {
            int r = (tid >> 4) + rr * 16;
            float4 q4 = *(const float4*)(g_Q + base + (size_t)(q0 + r) * BDIM + dh);
            Qs[dh + 0][SWZ(dh + 0, r)] = q4.x;
            Qs[dh + 1][SWZ(dh + 1, r)] = q4.y;
            Qs[dh + 2][SWZ(dh + 2, r)] = q4.z;
            Qs[dh + 3][SWZ(dh + 3, r)] = q4.w;
        }
    }

    float m[4], l[4], o[4][4];
#pragma unroll
    for (int i = 0; i < 4; i++) {
        m[i] = -INFINITY; l[i] = 0.f;
#pragma unroll
        for (int j = 0; j < 4; j++) o[i][j] = 0.f;
    }

    const float* lgp = g_LG + ((size_t)b * NH + h) * SEQ;

    for (int k0 = 0; k0 <= q0; k0 += 64) {
        __syncthreads();   // everyone done with previous V in KVs (and Q stores visible on iter 0)

        // load K tile transposed ([dh][k], swizzled)
        {
            const int dh = (tid & 15) * 4;
#pragma unroll
            for (int cc = 0; cc < 4; cc++) {
                int c = (tid >> 4) + cc * 16;
                float4 k4 = *(const float4*)(g_K + base + (size_t)(k0 + c) * BDIM + dh);
                KVs[dh + 0][SWZ(dh + 0, c)] = k4.x;
                KVs[dh + 1][SWZ(dh + 1, c)] = k4.y;
                KVs[dh + 2][SWZ(dh + 2, c)] = k4.z;
                KVs[dh + 3][SWZ(dh + 3, c)] = k4.w;
            }
        }
        __syncthreads();

        // S = Q K^T
        float s[4][4];
#pragma unroll
        for (int i = 0; i < 4; i++)
#pragma unroll
            for (int j = 0; j < 4; j++) s[i][j] = 0.f;

#pragma unroll 8
        for (int dh = 0; dh < 64; dh++) {
            float4 qa = *(const float4*)&Qs[dh][SWZ(dh, ty * 4)];
            float4 kb = *(const float4*)&KVs[dh][SWZ(dh, tx * 4)];
            float ra[4] = {qa.x, qa.y, qa.z, qa.w};
            float rb[4] = {kb.x, kb.y, kb.z, kb.w};
#pragma unroll
            for (int i = 0; i < 4; i++)
#pragma unroll
                for (int j = 0; j < 4; j++)
                    s[i][j] = fmaf(ra[i], rb[j], s[i][j]);
        }

        // scale + gate + causal mask
        float lgv[4];
#pragma unroll
        for (int j = 0; j < 4; j++) lgv[j] = lgp[k0 + tx * 4 + j];
        const bool diag = (k0 == q0);
#pragma unroll
        for (int i = 0; i < 4; i++)
#pragma unroll
            for (int j = 0; j < 4; j++) {
                float v = s[i][j] * 0.125f + lgv[j];
                if (diag && (tx * 4 + j) > (ty * 4 + i)) v = -INFINITY;
                s[i][j] = v;
            }

        // online softmax (rows distributed over 16 consecutive lanes: xor-shfl <16 stays in-group)
        float fac[4];
#pragma unroll
        for (int i = 0; i < 4; i++) {
            float rm = fmaxf(fmaxf(s[i][0], s[i][1]), fmaxf(s[i][2], s[i][3]));
#pragma unroll
            for (int off = 8; off >= 1; off >>= 1)
                rm = fmaxf(rm, __shfl_xor_sync(0xffffffffu, rm, off));
            float mn = fmaxf(m[i], rm);
            fac[i] = expf(m[i] - mn);   // 0 when m[i] = -inf
            m[i] = mn;
        }
#pragma unroll
        for (int i = 0; i < 4; i++) {
            float rl = 0.f;
#pragma unroll
            for (int j = 0; j < 4; j++) {
                float p = expf(s[i][j] - m[i]);   // 0 for masked (-inf)
                s[i][j] = p;
                rl += p;
            }
#pragma unroll
            for (int off = 8; off >= 1; off >>= 1)
                rl += __shfl_xor_sync(0xffffffffu, rl, off);
            l[i] = l[i] * fac[i] + rl;
#pragma unroll
            for (int j = 0; j < 4; j++) o[i][j] *= fac[i];
        }

        // stash P ([k][q], swizzled)
#pragma unroll
        for (int i = 0; i < 4; i++)
#pragma unroll
            for (int j = 0; j < 4; j++)
                Ps[tx * 4 + j][SWZ(tx * 4 + j, ty * 4 + i)] = s[i][j];

        __syncthreads();   // done reading K, done writing P

        // load V tile ([k][d], plain, coalesced both ways)
        {
            const int d = (tid & 15) * 4;
#pragma unroll
            for (int cc = 0; cc < 4; cc++) {
                int c = (tid >> 4) + cc * 16;
                *(float4*)&KVs[c][d] =
                    *(const float4*)(g_V + base + (size_t)(k0 + c) * BDIM + d);
            }
        }
        __syncthreads();

        // O += P V
#pragma unroll 8
        for (int c = 0; c < 64; c++) {
            float4 pa = *(const float4*)&Ps[c][SWZ(c, ty * 4)];
            float4 vb = *(const float4*)&KVs[c][tx * 4];
            float rp[4] = {pa.x, pa.y, pa.z, pa.w};
            float rv[4] = {vb.x, vb.y, vb.z, vb.w};
#pragma unroll
            for (int i = 0; i < 4; i++)
#pragma unroll
                for (int j = 0; j < 4; j++)
                    o[i][j] = fmaf(rp[i], rv[j], o[i][j]);
        }
    }

    // normalize + write O (b,s,h,dh) -> free transpose for the output GEMM
#pragma unroll
    for (int i = 0; i < 4; i++) {
        float inv = 1.f / l[i];
        float4 ov = make_float4(o[i][0] * inv, o[i][1] * inv, o[i][2] * inv, o[i][3] * inv);
        *(float4*)(g_O + base + (size_t)(q0 + ty * 4 + i) * BDIM + tx * 4) = ov;
    }
}

// ---------------- launch ----------------
extern "C" void kernel_launch(void* const* d_in, const int* in_sizes, int n_in,
                              void* d_out, int out_size)
{
    const float* x        = (const float*)d_in[0];
    const float* wq       = (const float*)d_in[1];
    const float* wk       = (const float*)d_in[2];
    const float* wv       = (const float*)d_in[3];
    const float* wo       = (const float*)d_in[4];
    const float* w_phase  = (const float*)d_in[5];
    const float* carrier  = (const float*)d_in[6];
    const float* lock     = (const float*)d_in[7];
    const float* bw       = (const float*)d_in[8];
    const int*   amask    = (const int*)d_in[9];      // bool mask stored as int32
    float* out = (float*)d_out;

    float *Q, *K, *V, *O, *LG;
    cudaGetSymbolAddress((void**)&Q,  g_Q);
    cudaGetSymbolAddress((void**)&K,  g_K);
    cudaGetSymbolAddress((void**)&V,  g_V);
    cudaGetSymbolAddress((void**)&O,  g_O);
    cudaGetSymbolAddress((void**)&LG, g_LG);

    const int M = NB * SEQ;
    dim3 gg(BDIM / 128, M / 128);   // (8, 32)

    sgemm128<<<gg, 256>>>(x, wq, Q, M, BDIM, BDIM);
    sgemm128<<<gg, 256>>>(x, wk, K, M, BDIM, BDIM);
    sgemm128<<<gg, 256>>>(x, wv, V, M, BDIM, BDIM);
    phase_gate<<<M, 128>>>(x, w_phase, carrier, lock, bw, LG);
    attn_kernel<<<dim3(SEQ / 64, NH, NB), 256>>>(amask);
    sgemm128<<<gg, 256>>>(O, wo, out, M, BDIM, BDIM);
}

// round 5
// speedup vs baseline: 1.5361x; 1.5361x over previous
#include <cuda_runtime.h>
#include <cuda_bf16.h>
#include <math.h>
#include <stdint.h>

#define BDIM 1024
#define SEQ  1024
#define NB   4
#define NH   16
#define DHD  64
#define MTOT (NB * SEQ)   // 4096

// ---------------- scratch (static device memory: allocation-free) ----------------
__device__ float g_Q[MTOT * BDIM];
__device__ float g_K[MTOT * BDIM];
__device__ float g_V[MTOT * BDIM];
__device__ float g_O[MTOT * BDIM];
__device__ float g_LG[NB * NH * SEQ];
__device__ __nv_bfloat16 g_xh[MTOT * BDIM];
__device__ __nv_bfloat16 g_xl[MTOT * BDIM];
__device__ __nv_bfloat16 g_oh[MTOT * BDIM];
__device__ __nv_bfloat16 g_ol[MTOT * BDIM];
__device__ __nv_bfloat16 g_wh[4][BDIM * BDIM];   // transposed [N][K] hi
__device__ __nv_bfloat16 g_wl[4][BDIM * BDIM];   // transposed [N][K] lo

// ================= PTX helpers (compute_100-safe: cp.async / ldmatrix / mma.sync) =========
__device__ __forceinline__ uint32_t smem_u32(const void* p) {
    uint32_t a;
    asm("{ .reg .u64 t; cvta.to.shared.u64 t, %1; cvt.u32.u64 %0, t; }" : "=r"(a) : "l"(p));
    return a;
}
__device__ __forceinline__ void cpa16(uint32_t dst, const void* src) {
    asm volatile("cp.async.cg.shared.global [%0], [%1], 16;" :: "r"(dst), "l"(src));
}
#define CP_COMMIT() asm volatile("cp.async.commit_group;" ::: "memory")
#define CP_WAIT0()  asm volatile("cp.async.wait_group 0;" ::: "memory")

__device__ __forceinline__ void ldsm4(uint32_t a, uint32_t& r0, uint32_t& r1,
                                      uint32_t& r2, uint32_t& r3) {
    asm volatile("ldmatrix.sync.aligned.m8n8.x4.shared.b16 {%0,%1,%2,%3}, [%4];"
                 : "=r"(r0), "=r"(r1), "=r"(r2), "=r"(r3) : "r"(a));
}
__device__ __forceinline__ void mma16816(float* d, uint32_t a0, uint32_t a1, uint32_t a2,
                                         uint32_t a3, uint32_t b0, uint32_t b1) {
    asm volatile("mma.sync.aligned.m16n8k16.row.col.f32.bf16.bf16.f32 "
                 "{%0,%1,%2,%3}, {%4,%5,%6,%7}, {%8,%9}, {%0,%1,%2,%3};"
                 : "+f"(d[0]), "+f"(d[1]), "+f"(d[2]), "+f"(d[3])
                 : "r"(a0), "r"(a1), "r"(a2), "r"(a3), "r"(b0), "r"(b1));
}

// ================= split kernels =================
__global__ __launch_bounds__(256) void split_kernel(const float* __restrict__ src,
                                                    __nv_bfloat16* __restrict__ hi,
                                                    __nv_bfloat16* __restrict__ lo) {
    int i = (blockIdx.x * 256 + threadIdx.x) * 4;
    float4 v = *(const float4*)(src + i);
    __nv_bfloat16 h0 = __float2bfloat16(v.x);
    __nv_bfloat16 h1 = __float2bfloat16(v.y);
    __nv_bfloat16 h2 = __float2bfloat16(v.z);
    __nv_bfloat16 h3 = __float2bfloat16(v.w);
    __nv_bfloat16 l0 = __float2bfloat16(v.x - __bfloat162float(h0));
    __nv_bfloat16 l1 = __float2bfloat16(v.y - __bfloat162float(h1));
    __nv_bfloat16 l2 = __float2bfloat16(v.z - __bfloat162float(h2));
    __nv_bfloat16 l3 = __float2bfloat16(v.w - __bfloat162float(h3));
    *(__nv_bfloat162*)(hi + i)     = __nv_bfloat162(h0, h1);
    *(__nv_bfloat162*)(hi + i + 2) = __nv_bfloat162(h2, h3);
    *(__nv_bfloat162*)(lo + i)     = __nv_bfloat162(l0, l1);
    *(__nv_bfloat162*)(lo + i + 2) = __nv_bfloat162(l2, l3);
}

// w[K][N] fp32 -> wt_hi[N][K], wt_lo[N][K] bf16 (transpose + split)
__global__ __launch_bounds__(256) void tsplit_kernel(const float* __restrict__ w,
                                                     __nv_bfloat16* __restrict__ ht,
                                                     __nv_bfloat16* __restrict__ lt) {
    __shared__ float t[32][33];
    const int k0 = blockIdx.y * 32, n0 = blockIdx.x * 32;
    const int tx = threadIdx.x, ty = threadIdx.y;   // block (32, 8)
#pragma unroll
    for (int r = ty; r < 32; r += 8)
        t[r][tx] = w[(size_t)(k0 + r) * BDIM + n0 + tx];
    __syncthreads();
#pragma unroll
    for (int r = ty; r < 32; r += 8) {
        float x = t[tx][r];                           // = w[k0+tx][n0+r]
        __nv_bfloat16 h = __float2bfloat16(x);
        __nv_bfloat16 l = __float2bfloat16(x - __bfloat162float(h));
        ht[(size_t)(n0 + r) * BDIM + k0 + tx] = h;
        lt[(size_t)(n0 + r) * BDIM + k0 + tx] = l;
    }
}

// ================= HMMA bf16x3 GEMM =================
// C[4096,1024] = A[4096,1024]*B[1024,1024] via Ah*Bh + Al*Bh + Ah*Bl  (K extended to 3072)
// A row-major bf16 (Ah, Al); B transposed [N][K] bf16 (Bh_t, Bl_t).
// CTA tile 128x128, 8 warps (2x4), warp tile 64x32, mma.m16n8k16, cp.async double buffer.
#define BK      32
#define NCHUNK  96          // 3*1024/32
#define PITCH   40          // bf16 elems per SMEM row (80B: 16B-aligned, ldmatrix conflict-free)

__global__ __launch_bounds__(256) void gemm_hmma3(const __nv_bfloat16* __restrict__ Ah,
                                                  const __nv_bfloat16* __restrict__ Al,
                                                  const __nv_bfloat16* __restrict__ Bh,
                                                  const __nv_bfloat16* __restrict__ Bl,
                                                  float* __restrict__ C) {
    __shared__ __nv_bfloat16 sA[2][128 * PITCH];
    __shared__ __nv_bfloat16 sB[2][128 * PITCH];

    const int tid = threadIdx.x;
    const int ln  = tid & 31;
    const int wid = tid >> 5;
    const int wm  = wid >> 2;          // 0..1
    const int wn  = wid & 3;           // 0..3

    const int m0 = blockIdx.y * 128;
    const int n0 = blockIdx.x * 128;

    // per-thread cp.async source/dest offsets: 2 chunks of 16B each for A and B
    const int ld_row0 = tid >> 2;                 // 0..63
    const int ld_ch0  = tid & 3;
    const int ld_row1 = ld_row0 + 64;

    float acc[4][4][4];
#pragma unroll
    for (int i = 0; i < 4; i++)
#pragma unroll
        for (int j = 0; j < 4; j++)
#pragma unroll
            for (int r = 0; r < 4; r++) acc[i][j][r] = 0.f;

    const uint32_t sA0 = smem_u32(sA[0]), sA1 = smem_u32(sA[1]);
    const uint32_t sB0 = smem_u32(sB[0]), sB1 = smem_u32(sB[1]);

    auto issue = [&](int chunk, int buf) {
        const int seg  = chunk >> 5;                 // 0:Ah*Bh 1:Al*Bh 2:Ah*Bl
        const int kloc = (chunk & 31) * BK;
        const __nv_bfloat16* Ag = (seg == 1) ? Al : Ah;
        const __nv_bfloat16* Bg = (seg == 2) ? Bl : Bh;
        const uint32_t da = buf ? sA1 : sA0;
        const uint32_t db = buf ? sB1 : sB0;
        cpa16(da + (ld_row0 * PITCH + ld_ch0 * 8) * 2,
              Ag + (size_t)(m0 + ld_row0) * BDIM + kloc + ld_ch0 * 8);
        cpa16(da + (ld_row1 * PITCH + ld_ch0 * 8) * 2,
              Ag + (size_t)(m0 + ld_row1) * BDIM + kloc + ld_ch0 * 8);
        cpa16(db + (ld_row0 * PITCH + ld_ch0 * 8) * 2,
              Bg + (size_t)(n0 + ld_row0) * BDIM + kloc + ld_ch0 * 8);
        cpa16(db + (ld_row1 * PITCH + ld_ch0 * 8) * 2,
              Bg + (size_t)(n0 + ld_row1) * BDIM + kloc + ld_ch0 * 8);
        CP_COMMIT();
    };

    // ldmatrix per-lane row components (same for all tiles)
    const int lm_sub = ((ln >> 3) & 1) * 8 + (ln & 7);   // row within 16-row tile
    const int lm_kc  = ln >> 4;                          // 0/1: k-chunk select within k16 pair

    issue(0, 0);

    for (int chunk = 0; chunk < NCHUNK; chunk++) {
        CP_WAIT0();
        __syncthreads();
        if (chunk + 1 < NCHUNK) issue(chunk + 1, (chunk + 1) & 1);

        const uint32_t ba = (chunk & 1) ? sA1 : sA0;
        const uint32_t bb = (chunk & 1) ? sB1 : sB0;

#pragma unroll
        for (int ks = 0; ks < 2; ks++) {
            const int kc = ks * 2 + lm_kc;
            uint32_t a[4][4];
#pragma unroll
            for (int mi = 0; mi < 4; mi++) {
                const int row = wm * 64 + mi * 16 + lm_sub;
                ldsm4(ba + (row * PITCH + kc * 8) * 2,
                      a[mi][0], a[mi][1], a[mi][2], a[mi][3]);
            }
            uint32_t b[4][2];
#pragma unroll
            for (int nb = 0; nb < 2; nb++) {
                const int row = wn * 32 + nb * 16 + lm_sub;
                uint32_t r0, r1, r2, r3;
                ldsm4(bb + (row * PITCH + kc * 8) * 2, r0, r1, r2, r3);
                b[nb * 2 + 0][0] = r0; b[nb * 2 + 0][1] = r2;
                b[nb * 2 + 1][0] = r1; b[nb * 2 + 1][1] = r3;
            }
#pragma unroll
            for (int mi = 0; mi < 4; mi++)
#pragma unroll
                for (int ni = 0; ni < 4; ni++)
                    mma16816(acc[mi][ni], a[mi][0], a[mi][1], a[mi][2], a[mi][3],
                             b[ni][0], b[ni][1]);
        }
        __syncthreads();
    }

    // epilogue: c-frag layout: row = ln/4 (+8 for regs 2,3), col = (ln%4)*2 (+1)
    const int er = ln >> 2, ec = (ln & 3) * 2;
#pragma unroll
    for (int mi = 0; mi < 4; mi++) {
#pragma unroll
        for (int ni = 0; ni < 4; ni++) {
            const int m = m0 + wm * 64 + mi * 16 + er;
            const int n = n0 + wn * 32 + ni * 8 + ec;
            *(float2*)(C + (size_t)m * BDIM + n)       = make_float2(acc[mi][ni][0], acc[mi][ni][1]);
            *(float2*)(C + (size_t)(m + 8) * BDIM + n) = make_float2(acc[mi][ni][2], acc[mi][ni][3]);
        }
    }
}

// ---------------- phase + per-head log-gate (unchanged, passing) ----------------
__global__ __launch_bounds__(128) void phase_gate(const float* __restrict__ x,
                                                  const float* __restrict__ w_phase,
                                                  const float* __restrict__ carrier,
                                                  const float* __restrict__ lock,
                                                  const float* __restrict__ bw,
                                                  float* __restrict__ lg)
{
    const int token = blockIdx.x;
    const float* xr = x + (size_t)token * BDIM;
    const int tid = threadIdx.x;

    float p0 = 0.f, p1 = 0.f;
    for (int d = tid; d < BDIM; d += 128) {
        float xv = xr[d];
        p0 = fmaf(xv, w_phase[2 * d],     p0);
        p1 = fmaf(xv, w_phase[2 * d + 1], p1);
    }
#pragma unroll
    for (int o = 16; o > 0; o >>= 1) {
        p0 += __shfl_down_sync(0xffffffffu, p0, o);
        p1 += __shfl_down_sync(0xffffffffu, p1, o);
    }
    __shared__ float s0[4], s1[4];
    __shared__ float phs;
    if ((tid & 31) == 0) { s0[tid >> 5] = p0; s1[tid >> 5] = p1; }
    __syncthreads();
    if (tid == 0) {
        float a = s0[0] + s0[1] + s0[2] + s0[3];
        float b = s1[0] + s1[1] + s1[2] + s1[3];
        phs = atan2f(a, b);
    }
    __syncthreads();
    if (tid < NH) {
        const int h = tid;
        float dphi = phs - carrier[h];
        float w = expf((cosf(dphi) - 1.f) / bw[h]);
        float g = lock[h] * w + (1.f - lock[h]);
        const int b = token / SEQ, s = token % SEQ;
        lg[((size_t)b * NH + h) * SEQ + s] = logf(g + 1e-6f);
    }
}

// ---------------- flash attention (unchanged, passing) ----------------
#define SWZ(d, c) ((c) ^ (((((unsigned)(d)) >> 2) & 15u) << 2))

__global__ __launch_bounds__(256) void attn_kernel(const int* __restrict__ active)
{
    __shared__ float Qs[64][64];
    __shared__ float KVs[64][64];
    __shared__ float Ps[64][64];

    const int q0  = blockIdx.x * 64;
    const int h   = blockIdx.y;
    const int b   = blockIdx.z;
    const int tid = threadIdx.x;
    const int tx  = tid & 15;
    const int ty  = tid >> 4;

    const size_t base = ((size_t)b * SEQ) * BDIM + (size_t)h * DHD;

    if (active[h] == 0) {
        const int r0 = tid >> 4, d = (tid & 15) * 4;
#pragma unroll
        for (int rr = 0; rr < 4; rr++) {
            int r = r0 + rr * 16;
            *(float4*)(g_O + base + (size_t)(q0 + r) * BDIM + d) = make_float4(0.f, 0.f, 0.f, 0.f);
        }
        return;
    }

    {
        const int dh = (tid & 15) * 4;
#pragma unroll
        for (int rr = 0; rr < 4; rr++) {
            int r = (tid >> 4) + rr * 16;
            float4 q4 = *(const float4*)(g_Q + base + (size_t)(q0 + r) * BDIM + dh);
            Qs[dh + 0][SWZ(dh + 0, r)] = q4.x;
            Qs[dh + 1][SWZ(dh + 1, r)] = q4.y;
            Qs[dh + 2][SWZ(dh + 2, r)] = q4.z;
            Qs[dh + 3][SWZ(dh + 3, r)] = q4.w;
        }
    }

    float m[4], l[4], o[4][4];
#pragma unroll
    for (int i = 0; i < 4; i++) {
        m[i] = -INFINITY; l[i] = 0.f;
#pragma unroll
        for (int j = 0; j < 4; j++) o[i][j] = 0.f;
    }

    const float* lgp = g_LG + ((size_t)b * NH + h) * SEQ;

    for (int k0 = 0; k0 <= q0; k0 += 64) {
        __syncthreads();
        {
            const int dh = (tid & 15) * 4;
#pragma unroll
            for (int cc = 0; cc < 4; cc++) {
                int c = (tid >> 4) + cc * 16;
                float4 k4 = *(const float4*)(g_K + base + (size_t)(k0 + c) * BDIM + dh);
                KVs[dh + 0][SWZ(dh + 0, c)] = k4.x;
                KVs[dh + 1][SWZ(dh + 1, c)] = k4.y;
                KVs[dh + 2][SWZ(dh + 2, c)] = k4.z;
                KVs[dh + 3][SWZ(dh + 3, c)] = k4.w;
            }
        }
        __syncthreads();

        float s[4][4];
#pragma unroll
        for (int i = 0; i < 4; i++)
#pragma unroll
            for (int j = 0; j < 4; j++) s[i][j] = 0.f;

#pragma unroll 8
        for (int dh = 0; dh < 64; dh++) {
            float4 qa = *(const float4*)&Qs[dh][SWZ(dh, ty * 4)];
            float4 kb = *(const float4*)&KVs[dh][SWZ(dh, tx * 4)];
            float ra[4] = {qa.x, qa.y, qa.z, qa.w};
            float rb[4] = {kb.x, kb.y, kb.z, kb.w};
#pragma unroll
            for (int i = 0; i < 4; i++)
#pragma unroll
                for (int j = 0; j < 4; j++)
                    s[i][j] = fmaf(ra[i], rb[j], s[i][j]);
        }

        float lgv[4];
#pragma unroll
        for (int j = 0; j < 4; j++) lgv[j] = lgp[k0 + tx * 4 + j];
        const bool diag = (k0 == q0);
#pragma unroll
        for (int i = 0; i < 4; i++)
#pragma unroll
            for (int j = 0; j < 4; j++) {
                float v = s[i][j] * 0.125f + lgv[j];
                if (diag && (tx * 4 + j) > (ty * 4 + i)) v = -INFINITY;
                s[i][j] = v;
            }

        float fac[4];
#pragma unroll
        for (int i = 0; i < 4; i++) {
            float rm = fmaxf(fmaxf(s[i][0], s[i][1]), fmaxf(s[i][2], s[i][3]));
#pragma unroll
            for (int off = 8; off >= 1; off >>= 1)
                rm = fmaxf(rm, __shfl_xor_sync(0xffffffffu, rm, off));
            float mn = fmaxf(m[i], rm);
            fac[i] = expf(m[i] - mn);
            m[i] = mn;
        }
#pragma unroll
        for (int i = 0; i < 4; i++) {
            float rl = 0.f;
#pragma unroll
            for (int j = 0; j < 4; j++) {
                float p = expf(s[i][j] - m[i]);
                s[i][j] = p;
                rl += p;
            }
#pragma unroll
            for (int off = 8; off >= 1; off >>= 1)
                rl += __shfl_xor_sync(0xffffffffu, rl, off);
            l[i] = l[i] * fac[i] + rl;
#pragma unroll
            for (int j = 0; j < 4; j++) o[i][j] *= fac[i];
        }

#pragma unroll
        for (int i = 0; i < 4; i++)
#pragma unroll
            for (int j = 0; j < 4; j++)
                Ps[tx * 4 + j][SWZ(tx * 4 + j, ty * 4 + i)] = s[i][j];

        __syncthreads();

        {
            const int d = (tid & 15) * 4;
#pragma unroll
            for (int cc = 0; cc < 4; cc++) {
                int c = (tid >> 4) + cc * 16;
                *(float4*)&KVs[c][d] =
                    *(const float4*)(g_V + base + (size_t)(k0 + c) * BDIM + d);
            }
        }
        __syncthreads();

#pragma unroll 8
        for (int c = 0; c < 64; c++) {
            float4 pa = *(const float4*)&Ps[c][SWZ(c, ty * 4)];
            float4 vb = *(const float4*)&KVs[c][tx * 4];
            float rp[4] = {pa.x, pa.y, pa.z, pa.w};
            float rv[4] = {vb.x, vb.y, vb.z, vb.w};
#pragma unroll
            for (int i = 0; i < 4; i++)
#pragma unroll
                for (int j = 0; j < 4; j++)
                    o[i][j] = fmaf(rp[i], rv[j], o[i][j]);
        }
    }

#pragma unroll
    for (int i = 0; i < 4; i++) {
        float inv = 1.f / l[i];
        float4 ov = make_float4(o[i][0] * inv, o[i][1] * inv, o[i][2] * inv, o[i][3] * inv);
        *(float4*)(g_O + base + (size_t)(q0 + ty * 4 + i) * BDIM + tx * 4) = ov;
    }
}

// ---------------- launch ----------------
extern "C" void kernel_launch(void* const* d_in, const int* in_sizes, int n_in,
                              void* d_out, int out_size)
{
    const float* x        = (const float*)d_in[0];
    const float* wq       = (const float*)d_in[1];
    const float* wk       = (const float*)d_in[2];
    const float* wv       = (const float*)d_in[3];
    const float* wo       = (const float*)d_in[4];
    const float* w_phase  = (const float*)d_in[5];
    const float* carrier  = (const float*)d_in[6];
    const float* lock     = (const float*)d_in[7];
    const float* bw       = (const float*)d_in[8];
    const int*   amask    = (const int*)d_in[9];
    float* out = (float*)d_out;

    float *Q, *K, *V, *O, *LG;
    __nv_bfloat16 *xh, *xl, *oh, *ol, *wh, *wl;
    cudaGetSymbolAddress((void**)&Q,  g_Q);
    cudaGetSymbolAddress((void**)&K,  g_K);
    cudaGetSymbolAddress((void**)&V,  g_V);
    cudaGetSymbolAddress((void**)&O,  g_O);
    cudaGetSymbolAddress((void**)&LG, g_LG);
    cudaGetSymbolAddress((void**)&xh, g_xh);
    cudaGetSymbolAddress((void**)&xl, g_xl);
    cudaGetSymbolAddress((void**)&oh, g_oh);
    cudaGetSymbolAddress((void**)&ol, g_ol);
    cudaGetSymbolAddress((void**)&wh, g_wh);
    cudaGetSymbolAddress((void**)&wl, g_wl);

    const int NW = BDIM * BDIM;  // elements per weight matrix
    dim3 tg(32, 32), tb(32, 8);
    dim3 gg(BDIM / 128, MTOT / 128);   // (8, 32)

    // split inputs
    split_kernel<<<MTOT * BDIM / 1024, 256>>>(x, xh, xl);
    tsplit_kernel<<<tg, tb>>>(wq, wh + 0 * NW, wl + 0 * NW);
    tsplit_kernel<<<tg, tb>>>(wk, wh + 1 * NW, wl + 1 * NW);
    tsplit_kernel<<<tg, tb>>>(wv, wh + 2 * NW, wl + 2 * NW);
    tsplit_kernel<<<tg, tb>>>(wo, wh + 3 * NW, wl + 3 * NW);

    // projections (HMMA bf16x3)
    gemm_hmma3<<<gg, 256>>>(xh, xl, wh + 0 * NW, wl + 0 * NW, Q);
    gemm_hmma3<<<gg, 256>>>(xh, xl, wh + 1 * NW, wl + 1 * NW, K);
    gemm_hmma3<<<gg, 256>>>(xh, xl, wh + 2 * NW, wl + 2 * NW, V);

    phase_gate<<<MTOT, 128>>>(x, w_phase, carrier, lock, bw, LG);
    attn_kernel<<<dim3(SEQ / 64, NH, NB), 256>>>(amask);

    // output projection
    split_kernel<<<MTOT * BDIM / 1024, 256>>>(O, oh, ol);
    gemm_hmma3<<<gg, 256>>>(oh, ol, wh + 3 * NW, wl + 3 * NW, out);
}

// round 7
// speedup vs baseline: 1.9290x; 1.2557x over previous
#include <cuda_runtime.h>
#include <cuda_bf16.h>
#include <math.h>
#include <stdint.h>

#define BDIM 1024
#define SEQ  1024
#define NB   4
#define NH   16
#define DHD  64
#define MTOT (NB * SEQ)   // 4096

// ---------------- scratch (static device memory: allocation-free) ----------------
__device__ float g_LG[NB * NH * SEQ];
__device__ __nv_bfloat16 g_xh[MTOT * BDIM];
__device__ __nv_bfloat16 g_xl[MTOT * BDIM];
__device__ __nv_bfloat16 g_qh[MTOT * BDIM];
__device__ __nv_bfloat16 g_ql[MTOT * BDIM];
__device__ __nv_bfloat16 g_kh[MTOT * BDIM];
__device__ __nv_bfloat16 g_kl[MTOT * BDIM];
__device__ __nv_bfloat16 g_vh[MTOT * BDIM];
__device__ __nv_bfloat16 g_vl[MTOT * BDIM];
__device__ __nv_bfloat16 g_oh[MTOT * BDIM];
__device__ __nv_bfloat16 g_ol[MTOT * BDIM];
__device__ __nv_bfloat16 g_wh[4][BDIM * BDIM];   // transposed [N][K] hi
__device__ __nv_bfloat16 g_wl[4][BDIM * BDIM];   // transposed [N][K] lo

// ================= PTX helpers =================
__device__ __forceinline__ uint32_t smem_u32(const void* p) {
    uint32_t a;
    asm("{ .reg .u64 t; cvta.to.shared.u64 t, %1; cvt.u32.u64 %0, t; }" : "=r"(a) : "l"(p));
    return a;
}
__device__ __forceinline__ void cpa16(uint32_t dst, const void* src) {
    asm volatile("cp.async.cg.shared.global [%0], [%1], 16;" :: "r"(dst), "l"(src));
}
#define CP_COMMIT() asm volatile("cp.async.commit_group;" ::: "memory")
#define CP_WAIT0()  asm volatile("cp.async.wait_group 0;" ::: "memory")

__device__ __forceinline__ void ldsm4(uint32_t a, uint32_t& r0, uint32_t& r1,
                                      uint32_t& r2, uint32_t& r3) {
    asm volatile("ldmatrix.sync.aligned.m8n8.x4.shared.b16 {%0,%1,%2,%3}, [%4];"
                 : "=r"(r0), "=r"(r1), "=r"(r2), "=r"(r3) : "r"(a));
}
__device__ __forceinline__ void ldsm4t(uint32_t a, uint32_t& r0, uint32_t& r1,
                                       uint32_t& r2, uint32_t& r3) {
    asm volatile("ldmatrix.sync.aligned.m8n8.x4.trans.shared.b16 {%0,%1,%2,%3}, [%4];"
                 : "=r"(r0), "=r"(r1), "=r"(r2), "=r"(r3) : "r"(a));
}
__device__ __forceinline__ void mma16816(float* d, uint32_t a0, uint32_t a1, uint32_t a2,
                                         uint32_t a3, uint32_t b0, uint32_t b1) {
    asm volatile("mma.sync.aligned.m16n8k16.row.col.f32.bf16.bf16.f32 "
                 "{%0,%1,%2,%3}, {%4,%5,%6,%7}, {%8,%9}, {%0,%1,%2,%3};"
                 : "+f"(d[0]), "+f"(d[1]), "+f"(d[2]), "+f"(d[3])
                 : "r"(a0), "r"(a1), "r"(a2), "r"(a3), "r"(b0), "r"(b1));
}
// split a pair of floats into packed bf16 hi + bf16 residual
__device__ __forceinline__ void split2(float a, float b, uint32_t& h, uint32_t& l) {
    __nv_bfloat16 h0 = __float2bfloat16(a), h1 = __float2bfloat16(b);
    __nv_bfloat162 hh(h0, h1); h = *(uint32_t*)&hh;
    __nv_bfloat16 l0 = __float2bfloat16(a - __bfloat162float(h0));
    __nv_bfloat16 l1 = __float2bfloat16(b - __bfloat162float(h1));
    __nv_bfloat162 ll(l0, l1); l = *(uint32_t*)&ll;
}

// ================= split kernels =================
__global__ __launch_bounds__(256) void split_kernel(const float* __restrict__ src,
                                                    __nv_bfloat16* __restrict__ hi,
                                                    __nv_bfloat16* __restrict__ lo) {
    int i = (blockIdx.x * 256 + threadIdx.x) * 4;
    float4 v = *(const float4*)(src + i);
    uint32_t h0, l0, h1, l1;
    split2(v.x, v.y, h0, l0);
    split2(v.z, v.w, h1, l1);
    *(uint32_t*)(hi + i)     = h0;  *(uint32_t*)(hi + i + 2) = h1;
    *(uint32_t*)(lo + i)     = l0;  *(uint32_t*)(lo + i + 2) = l1;
}

__global__ __launch_bounds__(256) void tsplit_kernel(const float* __restrict__ w,
                                                     __nv_bfloat16* __restrict__ ht,
                                                     __nv_bfloat16* __restrict__ lt) {
    __shared__ float t[32][33];
    const int k0 = blockIdx.y * 32, n0 = blockIdx.x * 32;
    const int tx = threadIdx.x, ty = threadIdx.y;   // block (32, 8)
#pragma unroll
    for (int r = ty; r < 32; r += 8)
        t[r][tx] = w[(size_t)(k0 + r) * BDIM + n0 + tx];
    __syncthreads();
#pragma unroll
    for (int r = ty; r < 32; r += 8) {
        float x = t[tx][r];
        __nv_bfloat16 h = __float2bfloat16(x);
        __nv_bfloat16 l = __float2bfloat16(x - __bfloat162float(h));
        ht[(size_t)(n0 + r) * BDIM + k0 + tx] = h;
        lt[(size_t)(n0 + r) * BDIM + k0 + tx] = l;
    }
}

// ================= HMMA bf16x3 GEMM (template epilogue) =================
#define BK      32
#define NCHUNK  96          // 3*1024/32
#define PITCH   40

template <bool SPLIT>
__global__ __launch_bounds__(256) void gemm_hmma3(const __nv_bfloat16* __restrict__ Ah,
                                                  const __nv_bfloat16* __restrict__ Al,
                                                  const __nv_bfloat16* __restrict__ Bh,
                                                  const __nv_bfloat16* __restrict__ Bl,
                                                  float* __restrict__ C,
                                                  __nv_bfloat16* __restrict__ Ch,
                                                  __nv_bfloat16* __restrict__ Cl) {
    __shared__ __nv_bfloat16 sA[2][128 * PITCH];
    __shared__ __nv_bfloat16 sB[2][128 * PITCH];

    const int tid = threadIdx.x;
    const int ln  = tid & 31;
    const int wid = tid >> 5;
    const int wm  = wid >> 2;
    const int wn  = wid & 3;

    const int m0 = blockIdx.y * 128;
    const int n0 = blockIdx.x * 128;

    const int ld_row0 = tid >> 2;
    const int ld_ch0  = tid & 3;
    const int ld_row1 = ld_row0 + 64;

    float acc[4][4][4];
#pragma unroll
    for (int i = 0; i < 4; i++)
#pragma unroll
        for (int j = 0; j < 4; j++)
#pragma unroll
            for (int r = 0; r < 4; r++) acc[i][j][r] = 0.f;

    const uint32_t sA0 = smem_u32(sA[0]), sA1 = smem_u32(sA[1]);
    const uint32_t sB0 = smem_u32(sB[0]), sB1 = smem_u32(sB[1]);

    auto issue = [&](int chunk, int buf) {
        const int seg  = chunk >> 5;
        const int kloc = (chunk & 31) * BK;
        const __nv_bfloat16* Ag = (seg == 1) ? Al : Ah;
        const __nv_bfloat16* Bg = (seg == 2) ? Bl : Bh;
        const uint32_t da = buf ? sA1 : sA0;
        const uint32_t db = buf ? sB1 : sB0;
        cpa16(da + (ld_row0 * PITCH + ld_ch0 * 8) * 2,
              Ag + (size_t)(m0 + ld_row0) * BDIM + kloc + ld_ch0 * 8);
        cpa16(da + (ld_row1 * PITCH + ld_ch0 * 8) * 2,
              Ag + (size_t)(m0 + ld_row1) * BDIM + kloc + ld_ch0 * 8);
        cpa16(db + (ld_row0 * PITCH + ld_ch0 * 8) * 2,
              Bg + (size_t)(n0 + ld_row0) * BDIM + kloc + ld_ch0 * 8);
        cpa16(db + (ld_row1 * PITCH + ld_ch0 * 8) * 2,
              Bg + (size_t)(n0 + ld_row1) * BDIM + kloc + ld_ch0 * 8);
        CP_COMMIT();
    };

    const int lm_sub = ((ln >> 3) & 1) * 8 + (ln & 7);
    const int lm_kc  = ln >> 4;

    issue(0, 0);

    for (int chunk = 0; chunk < NCHUNK; chunk++) {
        CP_WAIT0();
        __syncthreads();
        if (chunk + 1 < NCHUNK) issue(chunk + 1, (chunk + 1) & 1);

        const uint32_t ba = (chunk & 1) ? sA1 : sA0;
        const uint32_t bb = (chunk & 1) ? sB1 : sB0;

#pragma unroll
        for (int ks = 0; ks < 2; ks++) {
            const int kc = ks * 2 + lm_kc;
            uint32_t a[4][4];
#pragma unroll
            for (int mi = 0; mi < 4; mi++) {
                const int row = wm * 64 + mi * 16 + lm_sub;
                ldsm4(ba + (row * PITCH + kc * 8) * 2,
                      a[mi][0], a[mi][1], a[mi][2], a[mi][3]);
            }
            uint32_t b[4][2];
#pragma unroll
            for (int nb = 0; nb < 2; nb++) {
                const int row = wn * 32 + nb * 16 + lm_sub;
                uint32_t r0, r1, r2, r3;
                ldsm4(bb + (row * PITCH + kc * 8) * 2, r0, r1, r2, r3);
                b[nb * 2 + 0][0] = r0; b[nb * 2 + 0][1] = r2;
                b[nb * 2 + 1][0] = r1; b[nb * 2 + 1][1] = r3;
            }
#pragma unroll
            for (int mi = 0; mi < 4; mi++)
#pragma unroll
                for (int ni = 0; ni < 4; ni++)
                    mma16816(acc[mi][ni], a[mi][0], a[mi][1], a[mi][2], a[mi][3],
                             b[ni][0], b[ni][1]);
        }
        __syncthreads();
    }

    const int er = ln >> 2, ec = (ln & 3) * 2;
#pragma unroll
    for (int mi = 0; mi < 4; mi++) {
#pragma unroll
        for (int ni = 0; ni < 4; ni++) {
            const int m = m0 + wm * 64 + mi * 16 + er;
            const int n = n0 + wn * 32 + ni * 8 + ec;
            if (SPLIT) {
                uint32_t h, l;
                split2(acc[mi][ni][0], acc[mi][ni][1], h, l);
                *(uint32_t*)(Ch + (size_t)m * BDIM + n) = h;
                *(uint32_t*)(Cl + (size_t)m * BDIM + n) = l;
                split2(acc[mi][ni][2], acc[mi][ni][3], h, l);
                *(uint32_t*)(Ch + (size_t)(m + 8) * BDIM + n) = h;
                *(uint32_t*)(Cl + (size_t)(m + 8) * BDIM + n) = l;
            } else {
                *(float2*)(C + (size_t)m * BDIM + n)       = make_float2(acc[mi][ni][0], acc[mi][ni][1]);
                *(float2*)(C + (size_t)(m + 8) * BDIM + n) = make_float2(acc[mi][ni][2], acc[mi][ni][3]);
            }
        }
    }
}

// ---------------- phase + per-head log-gate (unchanged) ----------------
__global__ __launch_bounds__(128) void phase_gate(const float* __restrict__ x,
                                                  const float* __restrict__ w_phase,
                                                  const float* __restrict__ carrier,
                                                  const float* __restrict__ lock,
                                                  const float* __restrict__ bw,
                                                  float* __restrict__ lg)
{
    const int token = blockIdx.x;
    const float* xr = x + (size_t)token * BDIM;
    const int tid = threadIdx.x;

    float p0 = 0.f, p1 = 0.f;
    for (int d = tid; d < BDIM; d += 128) {
        float xv = xr[d];
        p0 = fmaf(xv, w_phase[2 * d],     p0);
        p1 = fmaf(xv, w_phase[2 * d + 1], p1);
    }
#pragma unroll
    for (int o = 16; o > 0; o >>= 1) {
        p0 += __shfl_down_sync(0xffffffffu, p0, o);
        p1 += __shfl_down_sync(0xffffffffu, p1, o);
    }
    __shared__ float s0[4], s1[4];
    __shared__ float phs;
    if ((tid & 31) == 0) { s0[tid >> 5] = p0; s1[tid >> 5] = p1; }
    __syncthreads();
    if (tid == 0) {
        float a = s0[0] + s0[1] + s0[2] + s0[3];
        float b = s1[0] + s1[1] + s1[2] + s1[3];
        phs = atan2f(a, b);
    }
    __syncthreads();
    if (tid < NH) {
        const int h = tid;
        float dphi = phs - carrier[h];
        float w = expf((cosf(dphi) - 1.f) / bw[h]);
        float g = lock[h] * w + (1.f - lock[h]);
        const int b = token / SEQ, s = token % SEQ;
        lg[((size_t)b * NH + h) * SEQ + s] = logf(g + 1e-6f);
    }
}

// ================= HMMA flash attention =================
// q-tile 128, k-tile 64, 8 warps. S = QhKh + QlKh + QhKl; O += PhVh + PlVh + PhVl.
#define AP 72    // bf16 pitch for attention smem tiles (144B rows, ldsm conflict-free)
// smem byte offsets
#define OQH 0
#define OQL (128 * AP * 2)
#define OKH (2 * 128 * AP * 2)
#define OKL (OKH + 64 * AP * 2)
#define OVH (OKL + 64 * AP * 2)
#define OVL (OVH + 64 * AP * 2)
#define OLG (OVL + 64 * AP * 2)
#define ASMEM (OLG + 64 * 4)

__global__ __launch_bounds__(256) void attn_hmma(const int* __restrict__ active,
                                                 const __nv_bfloat16* __restrict__ Qh,
                                                 const __nv_bfloat16* __restrict__ Ql,
                                                 const __nv_bfloat16* __restrict__ Kh,
                                                 const __nv_bfloat16* __restrict__ Kl,
                                                 const __nv_bfloat16* __restrict__ Vh,
                                                 const __nv_bfloat16* __restrict__ Vl,
                                                 const float* __restrict__ LG,
                                                 __nv_bfloat16* __restrict__ Oh,
                                                 __nv_bfloat16* __restrict__ Ol)
{
    extern __shared__ __align__(16) char asmem[];
    const uint32_t ub = smem_u32(asmem);

    const int tid = threadIdx.x;
    const int ln  = tid & 31;
    const int w   = tid >> 5;
    const int qb  = blockIdx.x;
    const int h   = blockIdx.y;
    const int b   = blockIdx.z;
    const int q0  = qb * 128;
    const size_t gbase = ((size_t)b * SEQ) * BDIM + (size_t)h * DHD;

    if (active[h] == 0) {
        // zero O tile (hi and lo)
#pragma unroll
        for (int i = 0; i < 4; i++) {
            const int idx = tid + i * 256;         // 1024 chunks of 8 bf16
            const int row = idx >> 3, ch = idx & 7;
            *(uint4*)(Oh + gbase + (size_t)(q0 + row) * BDIM + ch * 8) = make_uint4(0, 0, 0, 0);
            *(uint4*)(Ol + gbase + (size_t)(q0 + row) * BDIM + ch * 8) = make_uint4(0, 0, 0, 0);
        }
        return;
    }

    // load Q tile (hi, lo): 128 rows x 64 cols
#pragma unroll
    for (int i = 0; i < 4; i++) {
        const int idx = tid + i * 256;
        const int row = idx >> 3, ch = idx & 7;
        cpa16(ub + OQH + (row * AP + ch * 8) * 2, Qh + gbase + (size_t)(q0 + row) * BDIM + ch * 8);
        cpa16(ub + OQL + (row * AP + ch * 8) * 2, Ql + gbase + (size_t)(q0 + row) * BDIM + ch * 8);
    }
    CP_COMMIT();

    const int lm_sub = ((ln >> 3) & 1) * 8 + (ln & 7);
    const int half   = ln >> 4;
    const int er = ln >> 2, ec = (ln & 3) * 2;
    const int rowg0 = q0 + 16 * w + er;
    const int rowg1 = rowg0 + 8;

    float m0 = -INFINITY, m1 = -INFINITY, l0 = 0.f, l1 = 0.f;
    float ofr[8][4];
#pragma unroll
    for (int j = 0; j < 8; j++)
#pragma unroll
        for (int r = 0; r < 4; r++) ofr[j][r] = 0.f;

    const float* lgp = LG + ((size_t)b * NH + h) * SEQ;
    const int ktiles = 2 * qb + 2;

    for (int t = 0; t < ktiles; t++) {
        const int k0 = t * 64;
        __syncthreads();   // previous tile's smem fully consumed
#pragma unroll
        for (int i = 0; i < 2; i++) {
            const int idx = tid + i * 256;         // 512 chunks per array
            const int row = idx >> 3, ch = idx & 7;
            const size_t g = gbase + (size_t)(k0 + row) * BDIM + ch * 8;
            const uint32_t s = (row * AP + ch * 8) * 2;
            cpa16(ub + OKH + s, Kh + g);
            cpa16(ub + OKL + s, Kl + g);
            cpa16(ub + OVH + s, Vh + g);
            cpa16(ub + OVL + s, Vl + g);
        }
        if (tid < 16) cpa16(ub + OLG + tid * 16, lgp + k0 + tid * 4);
        CP_COMMIT();
        CP_WAIT0();
        __syncthreads();

        if (k0 <= q0 + 16 * w + 15) {   // warp has at least one unmasked column
            // ---- S = Q K^T (bf16x3) ----
            float sf[8][4];
#pragma unroll
            for (int j = 0; j < 8; j++)
#pragma unroll
                for (int r = 0; r < 4; r++) sf[j][r] = 0.f;

#pragma unroll
            for (int kc = 0; kc < 4; kc++) {
                const uint32_t qoff = ((16 * w + lm_sub) * AP + kc * 16 + half * 8) * 2;
                uint32_t ah0, ah1, ah2, ah3, al0, al1, al2, al3;
                ldsm4(ub + OQH + qoff, ah0, ah1, ah2, ah3);
                ldsm4(ub + OQL + qoff, al0, al1, al2, al3);
#pragma unroll
                for (int g = 0; g < 4; g++) {
                    const uint32_t koff = ((g * 16 + lm_sub) * AP + kc * 16 + half * 8) * 2;
                    uint32_t bh0, bh1, bh2, bh3, bl0, bl1, bl2, bl3;
                    ldsm4(ub + OKH + koff, bh0, bh1, bh2, bh3);
                    ldsm4(ub + OKL + koff, bl0, bl1, bl2, bl3);
                    mma16816(sf[2 * g],     ah0, ah1, ah2, ah3, bh0, bh2);
                    mma16816(sf[2 * g + 1], ah0, ah1, ah2, ah3, bh1, bh3);
                    mma16816(sf[2 * g],     al0, al1, al2, al3, bh0, bh2);
                    mma16816(sf[2 * g + 1], al0, al1, al2, al3, bh1, bh3);
                    mma16816(sf[2 * g],     ah0, ah1, ah2, ah3, bl0, bl2);
                    mma16816(sf[2 * g + 1], ah0, ah1, ah2, ah3, bl1, bl3);
                }
            }

            // ---- scale + gate + causal, online softmax ----
            float* slg = (float*)(asmem + OLG);
            float mx0 = -INFINITY, mx1 = -INFINITY;
#pragma unroll
            for (int j = 0; j < 8; j++) {
                const int c0 = k0 + 8 * j + ec, c1 = c0 + 1;
                const float g0 = slg[8 * j + ec], g1 = slg[8 * j + ec + 1];
                float v0 = sf[j][0] * 0.125f + g0; if (c0 > rowg0) v0 = -INFINITY;
                float v1 = sf[j][1] * 0.125f + g1; if (c1 > rowg0) v1 = -INFINITY;
                float v2 = sf[j][2] * 0.125f + g0; if (c0 > rowg1) v2 = -INFINITY;
                float v3 = sf[j][3] * 0.125f + g1; if (c1 > rowg1) v3 = -INFINITY;
                sf[j][0] = v0; sf[j][1] = v1; sf[j][2] = v2; sf[j][3] = v3;
                mx0 = fmaxf(mx0, fmaxf(v0, v1));
                mx1 = fmaxf(mx1, fmaxf(v2, v3));
            }
            mx0 = fmaxf(mx0, __shfl_xor_sync(0xffffffffu, mx0, 1));
            mx0 = fmaxf(mx0, __shfl_xor_sync(0xffffffffu, mx0, 2));
            mx1 = fmaxf(mx1, __shfl_xor_sync(0xffffffffu, mx1, 1));
            mx1 = fmaxf(mx1, __shfl_xor_sync(0xffffffffu, mx1, 2));
            const float mn0 = fmaxf(m0, mx0), mn1 = fmaxf(m1, mx1);
            const float fac0 = expf(m0 - mn0), fac1 = expf(m1 - mn1);
            m0 = mn0; m1 = mn1;

            float sum0 = 0.f, sum1 = 0.f;
#pragma unroll
            for (int j = 0; j < 8; j++) {
                float p0 = expf(sf[j][0] - m0), p1 = expf(sf[j][1] - m0);
                float p2 = expf(sf[j][2] - m1), p3 = expf(sf[j][3] - m1);
                sf[j][0] = p0; sf[j][1] = p1; sf[j][2] = p2; sf[j][3] = p3;
                sum0 += p0 + p1; sum1 += p2 + p3;
            }
            sum0 += __shfl_xor_sync(0xffffffffu, sum0, 1);
            sum0 += __shfl_xor_sync(0xffffffffu, sum0, 2);
            sum1 += __shfl_xor_sync(0xffffffffu, sum1, 1);
            sum1 += __shfl_xor_sync(0xffffffffu, sum1, 2);
            l0 = l0 * fac0 + sum0;
            l1 = l1 * fac1 + sum1;
#pragma unroll
            for (int j = 0; j < 8; j++) {
                ofr[j][0] *= fac0; ofr[j][1] *= fac0;
                ofr[j][2] *= fac1; ofr[j][3] *= fac1;
            }

            // ---- P -> bf16 hi/lo A-fragments (register identity) ----
            uint32_t aph[4][4], apl[4][4];
#pragma unroll
            for (int tt = 0; tt < 4; tt++) {
                split2(sf[2 * tt][0],     sf[2 * tt][1],     aph[tt][0], apl[tt][0]);
                split2(sf[2 * tt][2],     sf[2 * tt][3],     aph[tt][1], apl[tt][1]);
                split2(sf[2 * tt + 1][0], sf[2 * tt + 1][1], aph[tt][2], apl[tt][2]);
                split2(sf[2 * tt + 1][2], sf[2 * tt + 1][3], aph[tt][3], apl[tt][3]);
            }

            // ---- O += P V (bf16x3) ----
#pragma unroll
            for (int tt = 0; tt < 4; tt++) {
#pragma unroll
                for (int g = 0; g < 4; g++) {
                    const uint32_t voff = ((tt * 16 + lm_sub) * AP + g * 16 + half * 8) * 2;
                    uint32_t vh0, vh1, vh2, vh3, vl0, vl1, vl2, vl3;
                    ldsm4t(ub + OVH + voff, vh0, vh1, vh2, vh3);
                    ldsm4t(ub + OVL + voff, vl0, vl1, vl2, vl3);
                    mma16816(ofr[2 * g],     aph[tt][0], aph[tt][1], aph[tt][2], aph[tt][3], vh0, vh1);
                    mma16816(ofr[2 * g + 1], aph[tt][0], aph[tt][1], aph[tt][2], aph[tt][3], vh2, vh3);
                    mma16816(ofr[2 * g],     apl[tt][0], apl[tt][1], apl[tt][2], apl[tt][3], vh0, vh1);
                    mma16816(ofr[2 * g + 1], apl[tt][0], apl[tt][1], apl[tt][2], apl[tt][3], vh2, vh3);
                    mma16816(ofr[2 * g],     aph[tt][0], aph[tt][1], aph[tt][2], aph[tt][3], vl0, vl1);
                    mma16816(ofr[2 * g + 1], aph[tt][0], aph[tt][1], aph[tt][2], aph[tt][3], vl2, vl3);
                }
            }
        }
    }

    // ---- epilogue: normalize, split to bf16 hi/lo ----
    const float inv0 = 1.f / l0, inv1 = 1.f / l1;
#pragma unroll
    for (int j = 0; j < 8; j++) {
        uint32_t hh, ll;
        split2(ofr[j][0] * inv0, ofr[j][1] * inv0, hh, ll);
        *(uint32_t*)(Oh + gbase + (size_t)rowg0 * BDIM + 8 * j + ec) = hh;
        *(uint32_t*)(Ol + gbase + (size_t)rowg0 * BDIM + 8 * j + ec) = ll;
        split2(ofr[j][2] * inv1, ofr[j][3] * inv1, hh, ll);
        *(uint32_t*)(Oh + gbase + (size_t)rowg1 * BDIM + 8 * j + ec) = hh;
        *(uint32_t*)(Ol + gbase + (size_t)rowg1 * BDIM + 8 * j + ec) = ll;
    }
}

// ---------------- launch ----------------
extern "C" void kernel_launch(void* const* d_in, const int* in_sizes, int n_in,
                              void* d_out, int out_size)
{
    const float* x        = (const float*)d_in[0];
    const float* wq       = (const float*)d_in[1];
    const float* wk       = (const float*)d_in[2];
    const float* wv       = (const float*)d_in[3];
    const float* wo       = (const float*)d_in[4];
    const float* w_phase  = (const float*)d_in[5];
    const float* carrier  = (const float*)d_in[6];
    const float* lock     = (const float*)d_in[7];
    const float* bw       = (const float*)d_in[8];
    const int*   amask    = (const int*)d_in[9];
    float* out = (float*)d_out;

    float *LG;
    __nv_bfloat16 *xh, *xl, *qh, *ql, *kh, *kl, *vh, *vl, *oh, *ol, *wh, *wl;
    cudaGetSymbolAddress((void**)&LG, g_LG);
    cudaGetSymbolAddress((void**)&xh, g_xh);
    cudaGetSymbolAddress((void**)&xl, g_xl);
    cudaGetSymbolAddress((void**)&qh, g_qh);
    cudaGetSymbolAddress((void**)&ql, g_ql);
    cudaGetSymbolAddress((void**)&kh, g_kh);
    cudaGetSymbolAddress((void**)&kl, g_kl);
    cudaGetSymbolAddress((void**)&vh, g_vh);
    cudaGetSymbolAddress((void**)&vl, g_vl);
    cudaGetSymbolAddress((void**)&oh, g_oh);
    cudaGetSymbolAddress((void**)&ol, g_ol);
    cudaGetSymbolAddress((void**)&wh, g_wh);
    cudaGetSymbolAddress((void**)&wl, g_wl);

    cudaFuncSetAttribute(attn_hmma, cudaFuncAttributeMaxDynamicSharedMemorySize, ASMEM);

    const int NW = BDIM * BDIM;
    dim3 tg(32, 32), tb(32, 8);
    dim3 gg(BDIM / 128, MTOT / 128);

    // split inputs
    split_kernel<<<MTOT * BDIM / 1024, 256>>>(x, xh, xl);
    tsplit_kernel<<<tg, tb>>>(wq, wh + 0 * NW, wl + 0 * NW);
    tsplit_kernel<<<tg, tb>>>(wk, wh + 1 * NW, wl + 1 * NW);
    tsplit_kernel<<<tg, tb>>>(wv, wh + 2 * NW, wl + 2 * NW);
    tsplit_kernel<<<tg, tb>>>(wo, wh + 3 * NW, wl + 3 * NW);

    // projections -> bf16 hi/lo directly
    gemm_hmma3<true><<<gg, 256>>>(xh, xl, wh + 0 * NW, wl + 0 * NW, nullptr, qh, ql);
    gemm_hmma3<true><<<gg, 256>>>(xh, xl, wh + 1 * NW, wl + 1 * NW, nullptr, kh, kl);
    gemm_hmma3<true><<<gg, 256>>>(xh, xl, wh + 2 * NW, wl + 2 * NW, nullptr, vh, vl);

    phase_gate<<<MTOT, 128>>>(x, w_phase, carrier, lock, bw, LG);

    attn_hmma<<<dim3(SEQ / 128, NH, NB), 256, ASMEM>>>(amask, qh, ql, kh, kl, vh, vl, LG, oh, ol);

    // output projection (fp32 out)
    gemm_hmma3<false><<<gg, 256>>>(oh, ol, wh + 3 * NW, wl + 3 * NW, out, nullptr, nullptr);
}

// round 8
// speedup vs baseline: 1.9479x; 1.0098x over previous
#include <cuda_runtime.h>
#include <cuda_bf16.h>
#include <math.h>
#include <stdint.h>

#define BDIM 1024
#define SEQ  1024
#define NB   4
#define NH   16
#define DHD  64
#define MTOT (NB * SEQ)   // 4096

// ---------------- scratch (static device memory: allocation-free) ----------------
__device__ float g_LG[NB * NH * SEQ];
__device__ __nv_bfloat16 g_xh[MTOT * BDIM];
__device__ __nv_bfloat16 g_xl[MTOT * BDIM];
__device__ __nv_bfloat16 g_qh[MTOT * BDIM];
__device__ __nv_bfloat16 g_ql[MTOT * BDIM];
__device__ __nv_bfloat16 g_kh[MTOT * BDIM];
__device__ __nv_bfloat16 g_kl[MTOT * BDIM];
__device__ __nv_bfloat16 g_vh[MTOT * BDIM];
__device__ __nv_bfloat16 g_vl[MTOT * BDIM];
__device__ __nv_bfloat16 g_oh[MTOT * BDIM];
__device__ __nv_bfloat16 g_ol[MTOT * BDIM];
__device__ __nv_bfloat16 g_wh[4][BDIM * BDIM];   // transposed [N][K] hi
__device__ __nv_bfloat16 g_wl[4][BDIM * BDIM];   // transposed [N][K] lo

// ================= PTX helpers =================
__device__ __forceinline__ uint32_t smem_u32(const void* p) {
    uint32_t a;
    asm("{ .reg .u64 t; cvta.to.shared.u64 t, %1; cvt.u32.u64 %0, t; }" : "=r"(a) : "l"(p));
    return a;
}
__device__ __forceinline__ void cpa16(uint32_t dst, const void* src) {
    asm volatile("cp.async.cg.shared.global [%0], [%1], 16;" :: "r"(dst), "l"(src));
}
#define CP_COMMIT() asm volatile("cp.async.commit_group;" ::: "memory")
#define CP_WAIT0()  asm volatile("cp.async.wait_group 0;" ::: "memory")
#define CP_WAIT2()  asm volatile("cp.async.wait_group 2;" ::: "memory")

__device__ __forceinline__ void ldsm4(uint32_t a, uint32_t& r0, uint32_t& r1,
                                      uint32_t& r2, uint32_t& r3) {
    asm volatile("ldmatrix.sync.aligned.m8n8.x4.shared.b16 {%0,%1,%2,%3}, [%4];"
                 : "=r"(r0), "=r"(r1), "=r"(r2), "=r"(r3) : "r"(a));
}
__device__ __forceinline__ void ldsm4t(uint32_t a, uint32_t& r0, uint32_t& r1,
                                       uint32_t& r2, uint32_t& r3) {
    asm volatile("ldmatrix.sync.aligned.m8n8.x4.trans.shared.b16 {%0,%1,%2,%3}, [%4];"
                 : "=r"(r0), "=r"(r1), "=r"(r2), "=r"(r3) : "r"(a));
}
__device__ __forceinline__ void mma16816(float* d, uint32_t a0, uint32_t a1, uint32_t a2,
                                         uint32_t a3, uint32_t b0, uint32_t b1) {
    asm volatile("mma.sync.aligned.m16n8k16.row.col.f32.bf16.bf16.f32 "
                 "{%0,%1,%2,%3}, {%4,%5,%6,%7}, {%8,%9}, {%0,%1,%2,%3};"
                 : "+f"(d[0]), "+f"(d[1]), "+f"(d[2]), "+f"(d[3])
                 : "r"(a0), "r"(a1), "r"(a2), "r"(a3), "r"(b0), "r"(b1));
}
// split a pair of floats into packed bf16 hi + bf16 residual
__device__ __forceinline__ void split2(float a, float b, uint32_t& h, uint32_t& l) {
    __nv_bfloat16 h0 = __float2bfloat16(a), h1 = __float2bfloat16(b);
    __nv_bfloat162 hh(h0, h1); h = *(uint32_t*)&hh;
    __nv_bfloat16 l0 = __float2bfloat16(a - __bfloat162float(h0));
    __nv_bfloat16 l1 = __float2bfloat16(b - __bfloat162float(h1));
    __nv_bfloat162 ll(l0, l1); l = *(uint32_t*)&ll;
}

// ================= fused x-split + phase/log-gate =================
// one block (256 thr) per token: block loads the full 1024-elem row once.
__global__ __launch_bounds__(256) void split_phase(const float* __restrict__ x,
                                                   const float* __restrict__ w_phase,
                                                   const float* __restrict__ carrier,
                                                   const float* __restrict__ lock,
                                                   const float* __restrict__ bwp,
                                                   __nv_bfloat16* __restrict__ hi,
                                                   __nv_bfloat16* __restrict__ lo,
                                                   float* __restrict__ lg)
{
    const int token = blockIdx.x;
    const int tid = threadIdx.x;
    const size_t i = (size_t)token * BDIM + tid * 4;
    float4 v = *(const float4*)(x + i);
    uint32_t h0, l0, h1, l1;
    split2(v.x, v.y, h0, l0);
    split2(v.z, v.w, h1, l1);
    *(uint32_t*)(hi + i)     = h0;  *(uint32_t*)(hi + i + 2) = h1;
    *(uint32_t*)(lo + i)     = l0;  *(uint32_t*)(lo + i + 2) = l1;

    // phase partial: elements d = tid*4..tid*4+3, w_phase[d][0..1]
    float4 wa = *(const float4*)(w_phase + tid * 8);
    float4 wb = *(const float4*)(w_phase + tid * 8 + 4);
    float p0 = v.x * wa.x + v.y * wa.z + v.z * wb.x + v.w * wb.z;
    float p1 = v.x * wa.y + v.y * wa.w + v.z * wb.y + v.w * wb.w;
#pragma unroll
    for (int o = 16; o > 0; o >>= 1) {
        p0 += __shfl_down_sync(0xffffffffu, p0, o);
        p1 += __shfl_down_sync(0xffffffffu, p1, o);
    }
    __shared__ float s0[8], s1[8];
    __shared__ float phs;
    if ((tid & 31) == 0) { s0[tid >> 5] = p0; s1[tid >> 5] = p1; }
    __syncthreads();
    if (tid == 0) {
        float a = 0.f, b = 0.f;
#pragma unroll
        for (int k = 0; k < 8; k++) { a += s0[k]; b += s1[k]; }
        phs = atan2f(a, b);
    }
    __syncthreads();
    if (tid < NH) {
        float dphi = phs - carrier[tid];
        float w = expf((cosf(dphi) - 1.f) / bwp[tid]);
        float g = lock[tid] * w + (1.f - lock[tid]);
        const int b2 = token / SEQ, s = token % SEQ;
        lg[((size_t)b2 * NH + tid) * SEQ + s] = logf(g + 1e-6f);
    }
}

// ================= weight transpose+split (all 4 matrices, z-indexed) =================
__global__ __launch_bounds__(256) void tsplit4(const float* __restrict__ w0,
                                               const float* __restrict__ w1,
                                               const float* __restrict__ w2,
                                               const float* __restrict__ w3,
                                               __nv_bfloat16* __restrict__ ht,
                                               __nv_bfloat16* __restrict__ lt) {
    const float* w = (blockIdx.z == 0) ? w0 : (blockIdx.z == 1) ? w1
                   : (blockIdx.z == 2) ? w2 : w3;
    __nv_bfloat16* hb = ht + (size_t)blockIdx.z * BDIM * BDIM;
    __nv_bfloat16* lb = lt + (size_t)blockIdx.z * BDIM * BDIM;
    __shared__ float t[32][33];
    const int k0 = blockIdx.y * 32, n0 = blockIdx.x * 32;
    const int tx = threadIdx.x, ty = threadIdx.y;   // block (32, 8)
#pragma unroll
    for (int r = ty; r < 32; r += 8)
        t[r][tx] = w[(size_t)(k0 + r) * BDIM + n0 + tx];
    __syncthreads();
#pragma unroll
    for (int r = ty; r < 32; r += 8) {
        float x = t[tx][r];
        __nv_bfloat16 h = __float2bfloat16(x);
        __nv_bfloat16 l = __float2bfloat16(x - __bfloat162float(h));
        hb[(size_t)(n0 + r) * BDIM + k0 + tx] = h;
        lb[(size_t)(n0 + r) * BDIM + k0 + tx] = l;
    }
}

// ================= HMMA bf16x3 GEMM — 4-stage cp.async pipeline =================
#define BK      32
#define NCHUNK  96          // 3*1024/32
#define PITCH   40
#define STGB    (128 * PITCH * 2)   // 10240 B per A or B buffer per stage
#define GSMEM   (4 * 2 * STGB)      // 81920 B

template <bool SPLIT>
__global__ __launch_bounds__(256) void gemm_hmma3(const __nv_bfloat16* __restrict__ Ah,
                                                  const __nv_bfloat16* __restrict__ Al,
                                                  const __nv_bfloat16* __restrict__ Bh,
                                                  const __nv_bfloat16* __restrict__ Bl,
                                                  float* __restrict__ C,
                                                  __nv_bfloat16* __restrict__ Ch,
                                                  __nv_bfloat16* __restrict__ Cl) {
    extern __shared__ __align__(16) char gsm[];
    const uint32_t base = smem_u32(gsm);

    const int tid = threadIdx.x;
    const int ln  = tid & 31;
    const int wid = tid >> 5;
    const int wm  = wid >> 2;
    const int wn  = wid & 3;

    const int m0 = blockIdx.y * 128;
    const int n0 = blockIdx.x * 128;

    const int ld_row0 = tid >> 2;
    const int ld_ch0  = tid & 3;
    const int ld_row1 = ld_row0 + 64;

    float acc[4][4][4];
#pragma unroll
    for (int i = 0; i < 4; i++)
#pragma unroll
        for (int j = 0; j < 4; j++)
#pragma unroll
            for (int r = 0; r < 4; r++) acc[i][j][r] = 0.f;

    auto issue = [&](int chunk) {
        const int buf  = chunk & 3;
        const int seg  = chunk >> 5;
        const int kloc = (chunk & 31) * BK;
        const __nv_bfloat16* Ag = (seg == 1) ? Al : Ah;
        const __nv_bfloat16* Bg = (seg == 2) ? Bl : Bh;
        const uint32_t da = base + buf * (2 * STGB);
        const uint32_t db = da + STGB;
        cpa16(da + (ld_row0 * PITCH + ld_ch0 * 8) * 2,
              Ag + (size_t)(m0 + ld_row0) * BDIM + kloc + ld_ch0 * 8);
        cpa16(da + (ld_row1 * PITCH + ld_ch0 * 8) * 2,
              Ag + (size_t)(m0 + ld_row1) * BDIM + kloc + ld_ch0 * 8);
        cpa16(db + (ld_row0 * PITCH + ld_ch0 * 8) * 2,
              Bg + (size_t)(n0 + ld_row0) * BDIM + kloc + ld_ch0 * 8);
        cpa16(db + (ld_row1 * PITCH + ld_ch0 * 8) * 2,
              Bg + (size_t)(n0 + ld_row1) * BDIM + kloc + ld_ch0 * 8);
        CP_COMMIT();
    };

    const int lm_sub = ((ln >> 3) & 1) * 8 + (ln & 7);
    const int lm_kc  = ln >> 4;

    issue(0); issue(1); issue(2);

    for (int chunk = 0; chunk < NCHUNK; chunk++) {
        CP_WAIT2();          // group `chunk` retired (empty commits keep count valid)
        __syncthreads();     // also proves all warps finished compute(chunk-1)
        if (chunk + 3 < NCHUNK) issue(chunk + 3);   // overwrites buffer (chunk-1)&3: safe
        else CP_COMMIT();                            // empty group keeps wait_group math exact

        const uint32_t ba = base + (chunk & 3) * (2 * STGB);
        const uint32_t bb = ba + STGB;

#pragma unroll
        for (int ks = 0; ks < 2; ks++) {
            const int kc = ks * 2 + lm_kc;
            uint32_t a[4][4];
#pragma unroll
            for (int mi = 0; mi < 4; mi++) {
                const int row = wm * 64 + mi * 16 + lm_sub;
                ldsm4(ba + (row * PITCH + kc * 8) * 2,
                      a[mi][0], a[mi][1], a[mi][2], a[mi][3]);
            }
            uint32_t b[4][2];
#pragma unroll
            for (int nb = 0; nb < 2; nb++) {
                const int row = wn * 32 + nb * 16 + lm_sub;
                uint32_t r0, r1, r2, r3;
                ldsm4(bb + (row * PITCH + kc * 8) * 2, r0, r1, r2, r3);
                b[nb * 2 + 0][0] = r0; b[nb * 2 + 0][1] = r2;
                b[nb * 2 + 1][0] = r1; b[nb * 2 + 1][1] = r3;
            }
#pragma unroll
            for (int mi = 0; mi < 4; mi++)
#pragma unroll
                for (int ni = 0; ni < 4; ni++)
                    mma16816(acc[mi][ni], a[mi][0], a[mi][1], a[mi][2], a[mi][3],
                             b[ni][0], b[ni][1]);
        }
    }

    const int er = ln >> 2, ec = (ln & 3) * 2;
#pragma unroll
    for (int mi = 0; mi < 4; mi++) {
#pragma unroll
        for (int ni = 0; ni < 4; ni++) {
            const int m = m0 + wm * 64 + mi * 16 + er;
            const int n = n0 + wn * 32 + ni * 8 + ec;
            if (SPLIT) {
                uint32_t h, l;
                split2(acc[mi][ni][0], acc[mi][ni][1], h, l);
                *(uint32_t*)(Ch + (size_t)m * BDIM + n) = h;
                *(uint32_t*)(Cl + (size_t)m * BDIM + n) = l;
                split2(acc[mi][ni][2], acc[mi][ni][3], h, l);
                *(uint32_t*)(Ch + (size_t)(m + 8) * BDIM + n) = h;
                *(uint32_t*)(Cl + (size_t)(m + 8) * BDIM + n) = l;
            } else {
                *(float2*)(C + (size_t)m * BDIM + n)       = make_float2(acc[mi][ni][0], acc[mi][ni][1]);
                *(float2*)(C + (size_t)(m + 8) * BDIM + n) = make_float2(acc[mi][ni][2], acc[mi][ni][3]);
            }
        }
    }
}

// ================= HMMA flash attention (byte-identical to round-7 passing version) ====
#define AP 72
#define OQH 0
#define OQL (128 * AP * 2)
#define OKH (2 * 128 * AP * 2)
#define OKL (OKH + 64 * AP * 2)
#define OVH (OKL + 64 * AP * 2)
#define OVL (OVH + 64 * AP * 2)
#define OLG (OVL + 64 * AP * 2)
#define ASMEM (OLG + 64 * 4)

__global__ __launch_bounds__(256) void attn_hmma(const int* __restrict__ active,
                                                 const __nv_bfloat16* __restrict__ Qh,
                                                 const __nv_bfloat16* __restrict__ Ql,
                                                 const __nv_bfloat16* __restrict__ Kh,
                                                 const __nv_bfloat16* __restrict__ Kl,
                                                 const __nv_bfloat16* __restrict__ Vh,
                                                 const __nv_bfloat16* __restrict__ Vl,
                                                 const float* __restrict__ LG,
                                                 __nv_bfloat16* __restrict__ Oh,
                                                 __nv_bfloat16* __restrict__ Ol)
{
    extern __shared__ __align__(16) char asmem[];
    const uint32_t ub = smem_u32(asmem);

    const int tid = threadIdx.x;
    const int ln  = tid & 31;
    const int w   = tid >> 5;
    const int qb  = blockIdx.x;
    const int h   = blockIdx.y;
    const int b   = blockIdx.z;
    const int q0  = qb * 128;
    const size_t gbase = ((size_t)b * SEQ) * BDIM + (size_t)h * DHD;

    if (active[h] == 0) {
#pragma unroll
        for (int i = 0; i < 4; i++) {
            const int idx = tid + i * 256;
            const int row = idx >> 3, ch = idx & 7;
            *(uint4*)(Oh + gbase + (size_t)(q0 + row) * BDIM + ch * 8) = make_uint4(0, 0, 0, 0);
            *(uint4*)(Ol + gbase + (size_t)(q0 + row) * BDIM + ch * 8) = make_uint4(0, 0, 0, 0);
        }
        return;
    }

#pragma unroll
    for (int i = 0; i < 4; i++) {
        const int idx = tid + i * 256;
        const int row = idx >> 3, ch = idx & 7;
        cpa16(ub + OQH + (row * AP + ch * 8) * 2, Qh + gbase + (size_t)(q0 + row) * BDIM + ch * 8);
        cpa16(ub + OQL + (row * AP + ch * 8) * 2, Ql + gbase + (size_t)(q0 + row) * BDIM + ch * 8);
    }
    CP_COMMIT();

    const int lm_sub = ((ln >> 3) & 1) * 8 + (ln & 7);
    const int half   = ln >> 4;
    const int er = ln >> 2, ec = (ln & 3) * 2;
    const int rowg0 = q0 + 16 * w + er;
    const int rowg1 = rowg0 + 8;

    float m0 = -INFINITY, m1 = -INFINITY, l0 = 0.f, l1 = 0.f;
    float ofr[8][4];
#pragma unroll
    for (int j = 0; j < 8; j++)
#pragma unroll
        for (int r = 0; r < 4; r++) ofr[j][r] = 0.f;

    const float* lgp = LG + ((size_t)b * NH + h) * SEQ;
    const int ktiles = 2 * qb + 2;

    for (int t = 0; t < ktiles; t++) {
        const int k0 = t * 64;
        __syncthreads();
#pragma unroll
        for (int i = 0; i < 2; i++) {
            const int idx = tid + i * 256;
            const int row = idx >> 3, ch = idx & 7;
            const size_t g = gbase + (size_t)(k0 + row) * BDIM + ch * 8;
            const uint32_t s = (row * AP + ch * 8) * 2;
            cpa16(ub + OKH + s, Kh + g);
            cpa16(ub + OKL + s, Kl + g);
            cpa16(ub + OVH + s, Vh + g);
            cpa16(ub + OVL + s, Vl + g);
        }
        if (tid < 16) cpa16(ub + OLG + tid * 16, lgp + k0 + tid * 4);
        CP_COMMIT();
        CP_WAIT0();
        __syncthreads();

        if (k0 <= q0 + 16 * w + 15) {
            float sf[8][4];
#pragma unroll
            for (int j = 0; j < 8; j++)
#pragma unroll
                for (int r = 0; r < 4; r++) sf[j][r] = 0.f;

#pragma unroll
            for (int kc = 0; kc < 4; kc++) {
                const uint32_t qoff = ((16 * w + lm_sub) * AP + kc * 16 + half * 8) * 2;
                uint32_t ah0, ah1, ah2, ah3, al0, al1, al2, al3;
                ldsm4(ub + OQH + qoff, ah0, ah1, ah2, ah3);
                ldsm4(ub + OQL + qoff, al0, al1, al2, al3);
#pragma unroll
                for (int g = 0; g < 4; g++) {
                    const uint32_t koff = ((g * 16 + lm_sub) * AP + kc * 16 + half * 8) * 2;
                    uint32_t bh0, bh1, bh2, bh3, bl0, bl1, bl2, bl3;
                    ldsm4(ub + OKH + koff, bh0, bh1, bh2, bh3);
                    ldsm4(ub + OKL + koff, bl0, bl1, bl2, bl3);
                    mma16816(sf[2 * g],     ah0, ah1, ah2, ah3, bh0, bh2);
                    mma16816(sf[2 * g + 1], ah0, ah1, ah2, ah3, bh1, bh3);
                    mma16816(sf[2 * g],     al0, al1, al2, al3, bh0, bh2);
                    mma16816(sf[2 * g + 1], al0, al1, al2, al3, bh1, bh3);
                    mma16816(sf[2 * g],     ah0, ah1, ah2, ah3, bl0, bl2);
                    mma16816(sf[2 * g + 1], ah0, ah1, ah2, ah3, bl1, bl3);
                }
            }

            float* slg = (float*)(asmem + OLG);
            float mx0 = -INFINITY, mx1 = -INFINITY;
#pragma unroll
            for (int j = 0; j < 8; j++) {
                const int c0 = k0 + 8 * j + ec, c1 = c0 + 1;
                const float g0 = slg[8 * j + ec], g1 = slg[8 * j + ec + 1];
                float v0 = sf[j][0] * 0.125f + g0; if (c0 > rowg0) v0 = -INFINITY;
                float v1 = sf[j][1] * 0.125f + g1; if (c1 > rowg0) v1 = -INFINITY;
                float v2 = sf[j][2] * 0.125f + g0; if (c0 > rowg1) v2 = -INFINITY;
                float v3 = sf[j][3] * 0.125f + g1; if (c1 > rowg1) v3 = -INFINITY;
                sf[j][0] = v0; sf[j][1] = v1; sf[j][2] = v2; sf[j][3] = v3;
                mx0 = fmaxf(mx0, fmaxf(v0, v1));
                mx1 = fmaxf(mx1, fmaxf(v2, v3));
            }
            mx0 = fmaxf(mx0, __shfl_xor_sync(0xffffffffu, mx0, 1));
            mx0 = fmaxf(mx0, __shfl_xor_sync(0xffffffffu, mx0, 2));
            mx1 = fmaxf(mx1, __shfl_xor_sync(0xffffffffu, mx1, 1));
            mx1 = fmaxf(mx1, __shfl_xor_sync(0xffffffffu, mx1, 2));
            const float mn0 = fmaxf(m0, mx0), mn1 = fmaxf(m1, mx1);
            const float fac0 = expf(m0 - mn0), fac1 = expf(m1 - mn1);
            m0 = mn0; m1 = mn1;

            float sum0 = 0.f, sum1 = 0.f;
#pragma unroll
            for (int j = 0; j < 8; j++) {
                float p0 = expf(sf[j][0] - m0), p1 = expf(sf[j][1] - m0);
                float p2 = expf(sf[j][2] - m1), p3 = expf(sf[j][3] - m1);
                sf[j][0] = p0; sf[j][1] = p1; sf[j][2] = p2; sf[j][3] = p3;
                sum0 += p0 + p1; sum1 += p2 + p3;
            }
            sum0 += __shfl_xor_sync(0xffffffffu, sum0, 1);
            sum0 += __shfl_xor_sync(0xffffffffu, sum0, 2);
            sum1 += __shfl_xor_sync(0xffffffffu, sum1, 1);
            sum1 += __shfl_xor_sync(0xffffffffu, sum1, 2);
            l0 = l0 * fac0 + sum0;
            l1 = l1 * fac1 + sum1;
#pragma unroll
            for (int j = 0; j < 8; j++) {
                ofr[j][0] *= fac0; ofr[j][1] *= fac0;
                ofr[j][2] *= fac1; ofr[j][3] *= fac1;
            }

            uint32_t aph[4][4], apl[4][4];
#pragma unroll
            for (int tt = 0; tt < 4; tt++) {
                split2(sf[2 * tt][0],     sf[2 * tt][1],     aph[tt][0], apl[tt][0]);
                split2(sf[2 * tt][2],     sf[2 * tt][3],     aph[tt][1], apl[tt][1]);
                split2(sf[2 * tt + 1][0], sf[2 * tt + 1][1], aph[tt][2], apl[tt][2]);
                split2(sf[2 * tt + 1][2], sf[2 * tt + 1][3], aph[tt][3], apl[tt][3]);
            }

#pragma unroll
            for (int tt = 0; tt < 4; tt++) {
#pragma unroll
                for (int g = 0; g < 4; g++) {
                    const uint32_t voff = ((tt * 16 + lm_sub) * AP + g * 16 + half * 8) * 2;
                    uint32_t vh0, vh1, vh2, vh3, vl0, vl1, vl2, vl3;
                    ldsm4t(ub + OVH + voff, vh0, vh1, vh2, vh3);
                    ldsm4t(ub + OVL + voff, vl0, vl1, vl2, vl3);
                    mma16816(ofr[2 * g],     aph[tt][0], aph[tt][1], aph[tt][2], aph[tt][3], vh0, vh1);
                    mma16816(ofr[2 * g + 1], aph[tt][0], aph[tt][1], aph[tt][2], aph[tt][3], vh2, vh3);
                    mma16816(ofr[2 * g],     apl[tt][0], apl[tt][1], apl[tt][2], apl[tt][3], vh0, vh1);
                    mma16816(ofr[2 * g + 1], apl[tt][0], apl[tt][1], apl[tt][2], apl[tt][3], vh2, vh3);
                    mma16816(ofr[2 * g],     aph[tt][0], aph[tt][1], aph[tt][2], aph[tt][3], vl0, vl1);
                    mma16816(ofr[2 * g + 1], aph[tt][0], aph[tt][1], aph[tt][2], aph[tt][3], vl2, vl3);
                }
            }
        }
    }

    const float inv0 = 1.f / l0, inv1 = 1.f / l1;
#pragma unroll
    for (int j = 0; j < 8; j++) {
        uint32_t hh, ll;
        split2(ofr[j][0] * inv0, ofr[j][1] * inv0, hh, ll);
        *(uint32_t*)(Oh + gbase + (size_t)rowg0 * BDIM + 8 * j + ec) = hh;
        *(uint32_t*)(Ol + gbase + (size_t)rowg0 * BDIM + 8 * j + ec) = ll;
        split2(ofr[j][2] * inv1, ofr[j][3] * inv1, hh, ll);
        *(uint32_t*)(Oh + gbase + (size_t)rowg1 * BDIM + 8 * j + ec) = hh;
        *(uint32_t*)(Ol + gbase + (size_t)rowg1 * BDIM + 8 * j + ec) = ll;
    }
}

// ---------------- launch ----------------
extern "C" void kernel_launch(void* const* d_in, const int* in_sizes, int n_in,
                              void* d_out, int out_size)
{
    const float* x        = (const float*)d_in[0];
    const float* wq       = (const float*)d_in[1];
    const float* wk       = (const float*)d_in[2];
    const float* wv       = (const float*)d_in[3];
    const float* wo       = (const float*)d_in[4];
    const float* w_phase  = (const float*)d_in[5];
    const float* carrier  = (const float*)d_in[6];
    const float* lock     = (const float*)d_in[7];
    const float* bw       = (const float*)d_in[8];
    const int*   amask    = (const int*)d_in[9];
    float* out = (float*)d_out;

    float *LG;
    __nv_bfloat16 *xh, *xl, *qh, *ql, *kh, *kl, *vh, *vl, *oh, *ol, *wh, *wl;
    cudaGetSymbolAddress((void**)&LG, g_LG);
    cudaGetSymbolAddress((void**)&xh, g_xh);
    cudaGetSymbolAddress((void**)&xl, g_xl);
    cudaGetSymbolAddress((void**)&qh, g_qh);
    cudaGetSymbolAddress((void**)&ql, g_ql);
    cudaGetSymbolAddress((void**)&kh, g_kh);
    cudaGetSymbolAddress((void**)&kl, g_kl);
    cudaGetSymbolAddress((void**)&vh, g_vh);
    cudaGetSymbolAddress((void**)&vl, g_vl);
    cudaGetSymbolAddress((void**)&oh, g_oh);
    cudaGetSymbolAddress((void**)&ol, g_ol);
    cudaGetSymbolAddress((void**)&wh, g_wh);
    cudaGetSymbolAddress((void**)&wl, g_wl);

    cudaFuncSetAttribute(attn_hmma, cudaFuncAttributeMaxDynamicSharedMemorySize, ASMEM);
    cudaFuncSetAttribute(gemm_hmma3<true>,  cudaFuncAttributeMaxDynamicSharedMemorySize, GSMEM);
    cudaFuncSetAttribute(gemm_hmma3<false>, cudaFuncAttributeMaxDynamicSharedMemorySize, GSMEM);

    const int NW = BDIM * BDIM;
    dim3 gg(BDIM / 128, MTOT / 128);

    // fused x split + phase/gate; weight transpose-splits in one launch
    split_phase<<<MTOT, 256>>>(x, w_phase, carrier, lock, bw, xh, xl, LG);
    tsplit4<<<dim3(32, 32, 4), dim3(32, 8)>>>(wq, wk, wv, wo, wh, wl);

    // projections -> bf16 hi/lo directly
    gemm_hmma3<true><<<gg, 256, GSMEM>>>(xh, xl, wh + 0 * NW, wl + 0 * NW, nullptr, qh, ql);
    gemm_hmma3<true><<<gg, 256, GSMEM>>>(xh, xl, wh + 1 * NW, wl + 1 * NW, nullptr, kh, kl);
    gemm_hmma3<true><<<gg, 256, GSMEM>>>(xh, xl, wh + 2 * NW, wl + 2 * NW, nullptr, vh, vl);

    attn_hmma<<<dim3(SEQ / 128, NH, NB), 256, ASMEM>>>(amask, qh, ql, kh, kl, vh, vl, LG, oh, ol);

    // output projection (fp32 out)
    gemm_hmma3<false><<<gg, 256, GSMEM>>>(oh, ol, wh + 3 * NW, wl + 3 * NW, out, nullptr, nullptr);
}

// round 11
// speedup vs baseline: 2.1109x; 1.0837x over previous
#include <cuda_runtime.h>
#include <cuda_bf16.h>
#include <math.h>
#include <stdint.h>

#define BDIM 1024
#define SEQ  1024
#define NB   4
#define NH   16
#define DHD  64
#define MTOT (NB * SEQ)   // 4096

// ---------------- scratch (static device memory: allocation-free) ----------------
__device__ float g_LG[NB * NH * SEQ];
__device__ __nv_bfloat16 g_xh[MTOT * BDIM];
__device__ __nv_bfloat16 g_xl[MTOT * BDIM];
__device__ __nv_bfloat16 g_qh[MTOT * BDIM];
__device__ __nv_bfloat16 g_ql[MTOT * BDIM];
__device__ __nv_bfloat16 g_kh[MTOT * BDIM];
__device__ __nv_bfloat16 g_kl[MTOT * BDIM];
__device__ __nv_bfloat16 g_vh[MTOT * BDIM];
__device__ __nv_bfloat16 g_vl[MTOT * BDIM];
__device__ __nv_bfloat16 g_oh[MTOT * BDIM];
__device__ __nv_bfloat16 g_ol[MTOT * BDIM];
__device__ __nv_bfloat16 g_wh[4][BDIM * BDIM];   // transposed [N][K] hi
__device__ __nv_bfloat16 g_wl[4][BDIM * BDIM];   // transposed [N][K] lo

// ================= PTX helpers =================
__device__ __forceinline__ uint32_t smem_u32(const void* p) {
    uint32_t a;
    asm("{ .reg .u64 t; cvta.to.shared.u64 t, %1; cvt.u32.u64 %0, t; }" : "=r"(a) : "l"(p));
    return a;
}
__device__ __forceinline__ void cpa16(uint32_t dst, const void* src) {
    asm volatile("cp.async.cg.shared.global [%0], [%1], 16;" :: "r"(dst), "l"(src));
}
#define CP_COMMIT() asm volatile("cp.async.commit_group;" ::: "memory")
#define CP_WAIT0()  asm volatile("cp.async.wait_group 0;" ::: "memory")
#define CP_WAIT1()  asm volatile("cp.async.wait_group 1;" ::: "memory")

__device__ __forceinline__ void ldsm4(uint32_t a, uint32_t& r0, uint32_t& r1,
                                      uint32_t& r2, uint32_t& r3) {
    asm volatile("ldmatrix.sync.aligned.m8n8.x4.shared.b16 {%0,%1,%2,%3}, [%4];"
                 : "=r"(r0), "=r"(r1), "=r"(r2), "=r"(r3) : "r"(a));
}
__device__ __forceinline__ void ldsm4t(uint32_t a, uint32_t& r0, uint32_t& r1,
                                       uint32_t& r2, uint32_t& r3) {
    asm volatile("ldmatrix.sync.aligned.m8n8.x4.trans.shared.b16 {%0,%1,%2,%3}, [%4];"
                 : "=r"(r0), "=r"(r1), "=r"(r2), "=r"(r3) : "r"(a));
}
__device__ __forceinline__ void mma16816(float* d, uint32_t a0, uint32_t a1, uint32_t a2,
                                         uint32_t a3, uint32_t b0, uint32_t b1) {
    asm volatile("mma.sync.aligned.m16n8k16.row.col.f32.bf16.bf16.f32 "
                 "{%0,%1,%2,%3}, {%4,%5,%6,%7}, {%8,%9}, {%0,%1,%2,%3};"
                 : "+f"(d[0]), "+f"(d[1]), "+f"(d[2]), "+f"(d[3])
                 : "r"(a0), "r"(a1), "r"(a2), "r"(a3), "r"(b0), "r"(b1));
}
// split a pair of floats into packed bf16 hi + bf16 residual
__device__ __forceinline__ void split2(float a, float b, uint32_t& h, uint32_t& l) {
    __nv_bfloat16 h0 = __float2bfloat16(a), h1 = __float2bfloat16(b);
    __nv_bfloat162 hh(h0, h1); h = *(uint32_t*)&hh;
    __nv_bfloat16 l0 = __float2bfloat16(a - __bfloat162float(h0));
    __nv_bfloat16 l1 = __float2bfloat16(b - __bfloat162float(h1));
    __nv_bfloat162 ll(l0, l1); l = *(uint32_t*)&ll;
}

// ================= fused x-split + phase/log-gate =================
__global__ __launch_bounds__(256) void split_phase(const float* __restrict__ x,
                                                   const float* __restrict__ w_phase,
                                                   const float* __restrict__ carrier,
                                                   const float* __restrict__ lock,
                                                   const float* __restrict__ bwp,
                                                   __nv_bfloat16* __restrict__ hi,
                                                   __nv_bfloat16* __restrict__ lo,
                                                   float* __restrict__ lg)
{
    const int token = blockIdx.x;
    const int tid = threadIdx.x;
    const size_t i = (size_t)token * BDIM + tid * 4;
    float4 v = *(const float4*)(x + i);
    uint32_t h0, l0, h1, l1;
    split2(v.x, v.y, h0, l0);
    split2(v.z, v.w, h1, l1);
    *(uint32_t*)(hi + i)     = h0;  *(uint32_t*)(hi + i + 2) = h1;
    *(uint32_t*)(lo + i)     = l0;  *(uint32_t*)(lo + i + 2) = l1;

    float4 wa = *(const float4*)(w_phase + tid * 8);
    float4 wb = *(const float4*)(w_phase + tid * 8 + 4);
    float p0 = v.x * wa.x + v.y * wa.z + v.z * wb.x + v.w * wb.z;
    float p1 = v.x * wa.y + v.y * wa.w + v.z * wb.y + v.w * wb.w;
#pragma unroll
    for (int o = 16; o > 0; o >>= 1) {
        p0 += __shfl_down_sync(0xffffffffu, p0, o);
        p1 += __shfl_down_sync(0xffffffffu, p1, o);
    }
    __shared__ float s0[8], s1[8];
    __shared__ float phs;
    if ((tid & 31) == 0) { s0[tid >> 5] = p0; s1[tid >> 5] = p1; }
    __syncthreads();
    if (tid == 0) {
        float a = 0.f, b = 0.f;
#pragma unroll
        for (int k = 0; k < 8; k++) { a += s0[k]; b += s1[k]; }
        phs = atan2f(a, b);
    }
    __syncthreads();
    if (tid < NH) {
        float dphi = phs - carrier[tid];
        float w = expf((cosf(dphi) - 1.f) / bwp[tid]);
        float g = lock[tid] * w + (1.f - lock[tid]);
        const int b2 = token / SEQ, s = token % SEQ;
        lg[((size_t)b2 * NH + tid) * SEQ + s] = logf(g + 1e-6f);
    }
}

// ================= weight transpose+split (all 4 matrices, z-indexed) =================
__global__ __launch_bounds__(256) void tsplit4(const float* __restrict__ w0,
                                               const float* __restrict__ w1,
                                               const float* __restrict__ w2,
                                               const float* __restrict__ w3,
                                               __nv_bfloat16* __restrict__ ht,
                                               __nv_bfloat16* __restrict__ lt) {
    const float* w = (blockIdx.z == 0) ? w0 : (blockIdx.z == 1) ? w1
                   : (blockIdx.z == 2) ? w2 : w3;
    __nv_bfloat16* hb = ht + (size_t)blockIdx.z * BDIM * BDIM;
    __nv_bfloat16* lb = lt + (size_t)blockIdx.z * BDIM * BDIM;
    __shared__ float t[32][33];
    const int k0 = blockIdx.y * 32, n0 = blockIdx.x * 32;
    const int tx = threadIdx.x, ty = threadIdx.y;
#pragma unroll
    for (int r = ty; r < 32; r += 8)
        t[r][tx] = w[(size_t)(k0 + r) * BDIM + n0 + tx];
    __syncthreads();
#pragma unroll
    for (int r = ty; r < 32; r += 8) {
        float x = t[tx][r];
        __nv_bfloat16 h = __float2bfloat16(x);
        __nv_bfloat16 l = __float2bfloat16(x - __bfloat162float(h));
        hb[(size_t)(n0 + r) * BDIM + k0 + tx] = h;
        lb[(size_t)(n0 + r) * BDIM + k0 + tx] = l;
    }
}

// ================= HMMA bf16x3 GEMM — fused-pass, 2-stage pipeline =================
// Per K-chunk (32 of K=1024): load Ah,Al,Bh,Bl tiles once; compute
// acc += Ah*Bh + Al*Bh + Ah*Bl from registers. 96 MMAs / 24 LDSM per warp per chunk.
#define BK     32
#define NK     32                   // 1024/32
#define PITCH  40
#define TILEB  (128 * PITCH * 2)    // 10240 B per tile
#define STG4   (4 * TILEB)          // 40960 B per stage (Ah|Al|Bh|Bl)
#define GSMEM  (2 * STG4)           // 81920 B

template <bool SPLIT>
__global__ __launch_bounds__(256, 2) void gemm_hmma3(const __nv_bfloat16* __restrict__ Ah,
                                                     const __nv_bfloat16* __restrict__ Al,
                                                     const __nv_bfloat16* __restrict__ Bh,
                                                     const __nv_bfloat16* __restrict__ Bl,
                                                     float* __restrict__ C,
                                                     __nv_bfloat16* __restrict__ Ch,
                                                     __nv_bfloat16* __restrict__ Cl) {
    extern __shared__ __align__(16) char gsm[];
    const uint32_t base = smem_u32(gsm);

    const int tid = threadIdx.x;
    const int ln  = tid & 31;
    const int wid = tid >> 5;
    const int wm  = wid >> 2;
    const int wn  = wid & 3;

    const int m0 = blockIdx.y * 128;
    const int n0 = blockIdx.x * 128;

    const int ld_row0 = tid >> 2;                // 0..63
    const int ld_ch0  = tid & 3;
    const int ld_row1 = ld_row0 + 64;
    const uint32_t sm_off0 = (ld_row0 * PITCH + ld_ch0 * 8) * 2;
    const uint32_t sm_off1 = (ld_row1 * PITCH + ld_ch0 * 8) * 2;

    // per-thread global pointers (advance by BK each chunk)
    const __nv_bfloat16* pAh0 = Ah + (size_t)(m0 + ld_row0) * BDIM + ld_ch0 * 8;
    const __nv_bfloat16* pAh1 = Ah + (size_t)(m0 + ld_row1) * BDIM + ld_ch0 * 8;
    const __nv_bfloat16* pAl0 = Al + (size_t)(m0 + ld_row0) * BDIM + ld_ch0 * 8;
    const __nv_bfloat16* pAl1 = Al + (size_t)(m0 + ld_row1) * BDIM + ld_ch0 * 8;
    const __nv_bfloat16* pBh0 = Bh + (size_t)(n0 + ld_row0) * BDIM + ld_ch0 * 8;
    const __nv_bfloat16* pBh1 = Bh + (size_t)(n0 + ld_row1) * BDIM + ld_ch0 * 8;
    const __nv_bfloat16* pBl0 = Bl + (size_t)(n0 + ld_row0) * BDIM + ld_ch0 * 8;
    const __nv_bfloat16* pBl1 = Bl + (size_t)(n0 + ld_row1) * BDIM + ld_ch0 * 8;

    float acc[4][4][4];
#pragma unroll
    for (int i = 0; i < 4; i++)
#pragma unroll
        for (int j = 0; j < 4; j++)
#pragma unroll
            for (int r = 0; r < 4; r++) acc[i][j][r] = 0.f;

    auto issue = [&](int chunk) {
        const int kloc = chunk * BK;
        const uint32_t st = base + (chunk & 1) * STG4;
        cpa16(st + 0 * TILEB + sm_off0, pAh0 + kloc);
        cpa16(st + 0 * TILEB + sm_off1, pAh1 + kloc);
        cpa16(st + 1 * TILEB + sm_off0, pAl0 + kloc);
        cpa16(st + 1 * TILEB + sm_off1, pAl1 + kloc);
        cpa16(st + 2 * TILEB + sm_off0, pBh0 + kloc);
        cpa16(st + 2 * TILEB + sm_off1, pBh1 + kloc);
        cpa16(st + 3 * TILEB + sm_off0, pBl0 + kloc);
        cpa16(st + 3 * TILEB + sm_off1, pBl1 + kloc);
        CP_COMMIT();
    };

    const int lm_sub = ((ln >> 3) & 1) * 8 + (ln & 7);
    const int lm_kc  = ln >> 4;

    issue(0); issue(1);

    for (int chunk = 0; chunk < NK; chunk++) {
        CP_WAIT1();          // group `chunk` retired (only chunk+1 may be pending)
        __syncthreads();

        const uint32_t st = base + (chunk & 1) * STG4;
        const uint32_t tAh = st, tAl = st + TILEB, tBh = st + 2 * TILEB, tBl = st + 3 * TILEB;

#pragma unroll
        for (int ks = 0; ks < 2; ks++) {
            const uint32_t ko = (ks * 2 + lm_kc) * 8;   // bf16-element column offset (verified round-8 scheme)
            uint32_t ah[4][4], al[4][4];
#pragma unroll
            for (int mi = 0; mi < 4; mi++) {
                const uint32_t ro = ((wm * 64 + mi * 16 + lm_sub) * PITCH + ko) * 2;
                ldsm4(tAh + ro, ah[mi][0], ah[mi][1], ah[mi][2], ah[mi][3]);
                ldsm4(tAl + ro, al[mi][0], al[mi][1], al[mi][2], al[mi][3]);
            }
            uint32_t bh[4][2], bl[4][2];
#pragma unroll
            for (int nb = 0; nb < 2; nb++) {
                const uint32_t ro = ((wn * 32 + nb * 16 + lm_sub) * PITCH + ko) * 2;
                uint32_t r0, r1, r2, r3;
                ldsm4(tBh + ro, r0, r1, r2, r3);
                bh[nb * 2 + 0][0] = r0; bh[nb * 2 + 0][1] = r2;
                bh[nb * 2 + 1][0] = r1; bh[nb * 2 + 1][1] = r3;
                ldsm4(tBl + ro, r0, r1, r2, r3);
                bl[nb * 2 + 0][0] = r0; bl[nb * 2 + 0][1] = r2;
                bl[nb * 2 + 1][0] = r1; bl[nb * 2 + 1][1] = r3;
            }
#pragma unroll
            for (int mi = 0; mi < 4; mi++)
#pragma unroll
                for (int ni = 0; ni < 4; ni++) {
                    mma16816(acc[mi][ni], ah[mi][0], ah[mi][1], ah[mi][2], ah[mi][3],
                             bh[ni][0], bh[ni][1]);
                    mma16816(acc[mi][ni], al[mi][0], al[mi][1], al[mi][2], al[mi][3],
                             bh[ni][0], bh[ni][1]);
                    mma16816(acc[mi][ni], ah[mi][0], ah[mi][1], ah[mi][2], ah[mi][3],
                             bl[ni][0], bl[ni][1]);
                }
        }

        __syncthreads();     // all warps done reading buffer (chunk&1)
        if (chunk + 2 < NK) issue(chunk + 2);
        else CP_COMMIT();    // empty group keeps wait_group arithmetic exact
    }

    const int er = ln >> 2, ec = (ln & 3) * 2;
#pragma unroll
    for (int mi = 0; mi < 4; mi++) {
#pragma unroll
        for (int ni = 0; ni < 4; ni++) {
            const int m = m0 + wm * 64 + mi * 16 + er;
            const int n = n0 + wn * 32 + ni * 8 + ec;
            if (SPLIT) {
                uint32_t h, l;
                split2(acc[mi][ni][0], acc[mi][ni][1], h, l);
                *(uint32_t*)(Ch + (size_t)m * BDIM + n) = h;
                *(uint32_t*)(Cl + (size_t)m * BDIM + n) = l;
                split2(acc[mi][ni][2], acc[mi][ni][3], h, l);
                *(uint32_t*)(Ch + (size_t)(m + 8) * BDIM + n) = h;
                *(uint32_t*)(Cl + (size_t)(m + 8) * BDIM + n) = l;
            } else {
                *(float2*)(C + (size_t)m * BDIM + n)       = make_float2(acc[mi][ni][0], acc[mi][ni][1]);
                *(float2*)(C + (size_t)(m + 8) * BDIM + n) = make_float2(acc[mi][ni][2], acc[mi][ni][3]);
            }
        }
    }
}

// ================= HMMA flash attention (byte-identical to round-8 passing version) ====
#define AP 72
#define OQH 0
#define OQL (128 * AP * 2)
#define OKH (2 * 128 * AP * 2)
#define OKL (OKH + 64 * AP * 2)
#define OVH (OKL + 64 * AP * 2)
#define OVL (OVH + 64 * AP * 2)
#define OLG (OVL + 64 * AP * 2)
#define ASMEM (OLG + 64 * 4)

__global__ __launch_bounds__(256) void attn_hmma(const int* __restrict__ active,
                                                 const __nv_bfloat16* __restrict__ Qh,
                                                 const __nv_bfloat16* __restrict__ Ql,
                                                 const __nv_bfloat16* __restrict__ Kh,
                                                 const __nv_bfloat16* __restrict__ Kl,
                                                 const __nv_bfloat16* __restrict__ Vh,
                                                 const __nv_bfloat16* __restrict__ Vl,
                                                 const float* __restrict__ LG,
                                                 __nv_bfloat16* __restrict__ Oh,
                                                 __nv_bfloat16* __restrict__ Ol)
{
    extern __shared__ __align__(16) char asmem[];
    const uint32_t ub = smem_u32(asmem);

    const int tid = threadIdx.x;
    const int ln  = tid & 31;
    const int w   = tid >> 5;
    const int qb  = blockIdx.x;
    const int h   = blockIdx.y;
    const int b   = blockIdx.z;
    const int q0  = qb * 128;
    const size_t gbase = ((size_t)b * SEQ) * BDIM + (size_t)h * DHD;

    if (active[h] == 0) {
#pragma unroll
        for (int i = 0; i < 4; i++) {
            const int idx = tid + i * 256;
            const int row = idx >> 3, ch = idx & 7;
            *(uint4*)(Oh + gbase + (size_t)(q0 + row) * BDIM + ch * 8) = make_uint4(0, 0, 0, 0);
            *(uint4*)(Ol + gbase + (size_t)(q0 + row) * BDIM + ch * 8) = make_uint4(0, 0, 0, 0);
        }
        return;
    }

#pragma unroll
    for (int i = 0; i < 4; i++) {
        const int idx = tid + i * 256;
        const int row = idx >> 3, ch = idx & 7;
        cpa16(ub + OQH + (row * AP + ch * 8) * 2, Qh + gbase + (size_t)(q0 + row) * BDIM + ch * 8);
        cpa16(ub + OQL + (row * AP + ch * 8) * 2, Ql + gbase + (size_t)(q0 + row) * BDIM + ch * 8);
    }
    CP_COMMIT();

    const int lm_sub = ((ln >> 3) & 1) * 8 + (ln & 7);
    const int half   = ln >> 4;
    const int er = ln >> 2, ec = (ln & 3) * 2;
    const int rowg0 = q0 + 16 * w + er;
    const int rowg1 = rowg0 + 8;

    float m0 = -INFINITY, m1 = -INFINITY, l0 = 0.f, l1 = 0.f;
    float ofr[8][4];
#pragma unroll
    for (int j = 0; j < 8; j++)
#pragma unroll
        for (int r = 0; r < 4; r++) ofr[j][r] = 0.f;

    const float* lgp = LG + ((size_t)b * NH + h) * SEQ;
    const int ktiles = 2 * qb + 2;

    for (int t = 0; t < ktiles; t++) {
        const int k0 = t * 64;
        __syncthreads();
#pragma unroll
        for (int i = 0; i < 2; i++) {
            const int idx = tid + i * 256;
            const int row = idx >> 3, ch = idx & 7;
            const size_t g = gbase + (size_t)(k0 + row) * BDIM + ch * 8;
            const uint32_t s = (row * AP + ch * 8) * 2;
            cpa16(ub + OKH + s, Kh + g);
            cpa16(ub + OKL + s, Kl + g);
            cpa16(ub + OVH + s, Vh + g);
            cpa16(ub + OVL + s, Vl + g);
        }
        if (tid < 16) cpa16(ub + OLG + tid * 16, lgp + k0 + tid * 4);
        CP_COMMIT();
        CP_WAIT0();
        __syncthreads();

        if (k0 <= q0 + 16 * w + 15) {
            float sf[8][4];
#pragma unroll
            for (int j = 0; j < 8; j++)
#pragma unroll
                for (int r = 0; r < 4; r++) sf[j][r] = 0.f;

#pragma unroll
            for (int kc = 0; kc < 4; kc++) {
                const uint32_t qoff = ((16 * w + lm_sub) * AP + kc * 16 + half * 8) * 2;
                uint32_t ah0, ah1, ah2, ah3, al0, al1, al2, al3;
                ldsm4(ub + OQH + qoff, ah0, ah1, ah2, ah3);
                ldsm4(ub + OQL + qoff, al0, al1, al2, al3);
#pragma unroll
                for (int g = 0; g < 4; g++) {
                    const uint32_t koff = ((g * 16 + lm_sub) * AP + kc * 16 + half * 8) * 2;
                    uint32_t bh0, bh1, bh2, bh3, bl0, bl1, bl2, bl3;
                    ldsm4(ub + OKH + koff, bh0, bh1, bh2, bh3);
                    ldsm4(ub + OKL + koff, bl0, bl1, bl2, bl3);
                    mma16816(sf[2 * g],     ah0, ah1, ah2, ah3, bh0, bh2);
                    mma16816(sf[2 * g + 1], ah0, ah1, ah2, ah3, bh1, bh3);
                    mma16816(sf[2 * g],     al0, al1, al2, al3, bh0, bh2);
                    mma16816(sf[2 * g + 1], al0, al1, al2, al3, bh1, bh3);
                    mma16816(sf[2 * g],     ah0, ah1, ah2, ah3, bl0, bl2);
                    mma16816(sf[2 * g + 1], ah0, ah1, ah2, ah3, bl1, bl3);
                }
            }

            float* slg = (float*)(asmem + OLG);
            float mx0 = -INFINITY, mx1 = -INFINITY;
#pragma unroll
            for (int j = 0; j < 8; j++) {
                const int c0 = k0 + 8 * j + ec, c1 = c0 + 1;
                const float g0 = slg[8 * j + ec], g1 = slg[8 * j + ec + 1];
                float v0 = sf[j][0] * 0.125f + g0; if (c0 > rowg0) v0 = -INFINITY;
                float v1 = sf[j][1] * 0.125f + g1; if (c1 > rowg0) v1 = -INFINITY;
                float v2 = sf[j][2] * 0.125f + g0; if (c0 > rowg1) v2 = -INFINITY;
                float v3 = sf[j][3] * 0.125f + g1; if (c1 > rowg1) v3 = -INFINITY;
                sf[j][0] = v0; sf[j][1] = v1; sf[j][2] = v2; sf[j][3] = v3;
                mx0 = fmaxf(mx0, fmaxf(v0, v1));
                mx1 = fmaxf(mx1, fmaxf(v2, v3));
            }
            mx0 = fmaxf(mx0, __shfl_xor_sync(0xffffffffu, mx0, 1));
            mx0 = fmaxf(mx0, __shfl_xor_sync(0xffffffffu, mx0, 2));
            mx1 = fmaxf(mx1, __shfl_xor_sync(0xffffffffu, mx1, 1));
            mx1 = fmaxf(mx1, __shfl_xor_sync(0xffffffffu, mx1, 2));
            const float mn0 = fmaxf(m0, mx0), mn1 = fmaxf(m1, mx1);
            const float fac0 = expf(m0 - mn0), fac1 = expf(m1 - mn1);
            m0 = mn0; m1 = mn1;

            float sum0 = 0.f, sum1 = 0.f;
#pragma unroll
            for (int j = 0; j < 8; j++) {
                float p0 = expf(sf[j][0] - m0), p1 = expf(sf[j][1] - m0);
                float p2 = expf(sf[j][2] - m1), p3 = expf(sf[j][3] - m1);
                sf[j][0] = p0; sf[j][1] = p1; sf[j][2] = p2; sf[j][3] = p3;
                sum0 += p0 + p1; sum1 += p2 + p3;
            }
            sum0 += __shfl_xor_sync(0xffffffffu, sum0, 1);
            sum0 += __shfl_xor_sync(0xffffffffu, sum0, 2);
            sum1 += __shfl_xor_sync(0xffffffffu, sum1, 1);
            sum1 += __shfl_xor_sync(0xffffffffu, sum1, 2);
            l0 = l0 * fac0 + sum0;
            l1 = l1 * fac1 + sum1;
#pragma unroll
            for (int j = 0; j < 8; j++) {
                ofr[j][0] *= fac0; ofr[j][1] *= fac0;
                ofr[j][2] *= fac1; ofr[j][3] *= fac1;
            }

            uint32_t aph[4][4], apl[4][4];
#pragma unroll
            for (int tt = 0; tt < 4; tt++) {
                split2(sf[2 * tt][0],     sf[2 * tt][1],     aph[tt][0], apl[tt][0]);
                split2(sf[2 * tt][2],     sf[2 * tt][3],     aph[tt][1], apl[tt][1]);
                split2(sf[2 * tt + 1][0], sf[2 * tt + 1][1], aph[tt][2], apl[tt][2]);
                split2(sf[2 * tt + 1][2], sf[2 * tt + 1][3], aph[tt][3], apl[tt][3]);
            }

#pragma unroll
            for (int tt = 0; tt < 4; tt++) {
#pragma unroll
                for (int g = 0; g < 4; g++) {
                    const uint32_t voff = ((tt * 16 + lm_sub) * AP + g * 16 + half * 8) * 2;
                    uint32_t vh0, vh1, vh2, vh3, vl0, vl1, vl2, vl3;
                    ldsm4t(ub + OVH + voff, vh0, vh1, vh2, vh3);
                    ldsm4t(ub + OVL + voff, vl0, vl1, vl2, vl3);
                    mma16816(ofr[2 * g],     aph[tt][0], aph[tt][1], aph[tt][2], aph[tt][3], vh0, vh1);
                    mma16816(ofr[2 * g + 1], aph[tt][0], aph[tt][1], aph[tt][2], aph[tt][3], vh2, vh3);
                    mma16816(ofr[2 * g],     apl[tt][0], apl[tt][1], apl[tt][2], apl[tt][3], vh0, vh1);
                    mma16816(ofr[2 * g + 1], apl[tt][0], apl[tt][1], apl[tt][2], apl[tt][3], vh2, vh3);
                    mma16816(ofr[2 * g],     aph[tt][0], aph[tt][1], aph[tt][2], aph[tt][3], vl0, vl1);
                    mma16816(ofr[2 * g + 1], aph[tt][0], aph[tt][1], aph[tt][2], aph[tt][3], vl2, vl3);
                }
            }
        }
    }

    const float inv0 = 1.f / l0, inv1 = 1.f / l1;
#pragma unroll
    for (int j = 0; j < 8; j++) {
        uint32_t hh, ll;
        split2(ofr[j][0] * inv0, ofr[j][1] * inv0, hh, ll);
        *(uint32_t*)(Oh + gbase + (size_t)rowg0 * BDIM + 8 * j + ec) = hh;
        *(uint32_t*)(Ol + gbase + (size_t)rowg0 * BDIM + 8 * j + ec) = ll;
        split2(ofr[j][2] * inv1, ofr[j][3] * inv1, hh, ll);
        *(uint32_t*)(Oh + gbase + (size_t)rowg1 * BDIM + 8 * j + ec) = hh;
        *(uint32_t*)(Ol + gbase + (size_t)rowg1 * BDIM + 8 * j + ec) = ll;
    }
}

// ---------------- launch ----------------
extern "C" void kernel_launch(void* const* d_in, const int* in_sizes, int n_in,
                              void* d_out, int out_size)
{
    const float* x        = (const float*)d_in[0];
    const float* wq       = (const float*)d_in[1];
    const float* wk       = (const float*)d_in[2];
    const float* wv       = (const float*)d_in[3];
    const float* wo       = (const float*)d_in[4];
    const float* w_phase  = (const float*)d_in[5];
    const float* carrier  = (const float*)d_in[6];
    const float* lock     = (const float*)d_in[7];
    const float* bw       = (const float*)d_in[8];
    const int*   amask    = (const int*)d_in[9];
    float* out = (float*)d_out;

    float *LG;
    __nv_bfloat16 *xh, *xl, *qh, *ql, *kh, *kl, *vh, *vl, *oh, *ol, *wh, *wl;
    cudaGetSymbolAddress((void**)&LG, g_LG);
    cudaGetSymbolAddress((void**)&xh, g_xh);
    cudaGetSymbolAddress((void**)&xl, g_xl);
    cudaGetSymbolAddress((void**)&qh, g_qh);
    cudaGetSymbolAddress((void**)&ql, g_ql);
    cudaGetSymbolAddress((void**)&kh, g_kh);
    cudaGetSymbolAddress((void**)&kl, g_kl);
    cudaGetSymbolAddress((void**)&vh, g_vh);
    cudaGetSymbolAddress((void**)&vl, g_vl);
    cudaGetSymbolAddress((void**)&oh, g_oh);
    cudaGetSymbolAddress((void**)&ol, g_ol);
    cudaGetSymbolAddress((void**)&wh, g_wh);
    cudaGetSymbolAddress((void**)&wl, g_wl);

    cudaFuncSetAttribute(attn_hmma, cudaFuncAttributeMaxDynamicSharedMemorySize, ASMEM);
    cudaFuncSetAttribute(gemm_hmma3<true>,  cudaFuncAttributeMaxDynamicSharedMemorySize, GSMEM);
    cudaFuncSetAttribute(gemm_hmma3<false>, cudaFuncAttributeMaxDynamicSharedMemorySize, GSMEM);

    const int NW = BDIM * BDIM;
    dim3 gg(BDIM / 128, MTOT / 128);

    split_phase<<<MTOT, 256>>>(x, w_phase, carrier, lock, bw, xh, xl, LG);
    tsplit4<<<dim3(32, 32, 4), dim3(32, 8)>>>(wq, wk, wv, wo, wh, wl);

    gemm_hmma3<true><<<gg, 256, GSMEM>>>(xh, xl, wh + 0 * NW, wl + 0 * NW, nullptr, qh, ql);
    gemm_hmma3<true><<<gg, 256, GSMEM>>>(xh, xl, wh + 1 * NW, wl + 1 * NW, nullptr, kh, kl);
    gemm_hmma3<true><<<gg, 256, GSMEM>>>(xh, xl, wh + 2 * NW, wl + 2 * NW, nullptr, vh, vl);

    attn_hmma<<<dim3(SEQ / 128, NH, NB), 256, ASMEM>>>(amask, qh, ql, kh, kl, vh, vl, LG, oh, ol);

    gemm_hmma3<false><<<gg, 256, GSMEM>>>(oh, ol, wh + 3 * NW, wl + 3 * NW, out, nullptr, nullptr);
}

// round 12
// speedup vs baseline: 2.1753x; 1.0305x over previous
#include <cuda_runtime.h>
#include <cuda_bf16.h>
#include <math.h>
#include <stdint.h>

#define BDIM 1024
#define SEQ  1024
#define NB   4
#define NH   16
#define DHD  64
#define MTOT (NB * SEQ)   // 4096
#define NW   (BDIM * BDIM)

// ---------------- scratch (static device memory: allocation-free) ----------------
__device__ float g_LG[NB * NH * SEQ];
__device__ __nv_bfloat16 g_xh[MTOT * BDIM];
__device__ __nv_bfloat16 g_xl[MTOT * BDIM];
__device__ __nv_bfloat16 g_qh[MTOT * BDIM];
__device__ __nv_bfloat16 g_ql[MTOT * BDIM];
__device__ __nv_bfloat16 g_kh[MTOT * BDIM];
__device__ __nv_bfloat16 g_kl[MTOT * BDIM];
__device__ __nv_bfloat16 g_vh[MTOT * BDIM];
__device__ __nv_bfloat16 g_vl[MTOT * BDIM];
__device__ __nv_bfloat16 g_oh[MTOT * BDIM];
__device__ __nv_bfloat16 g_ol[MTOT * BDIM];
__device__ __nv_bfloat16 g_wh[4][NW];   // transposed [N][K] hi
__device__ __nv_bfloat16 g_wl[4][NW];   // transposed [N][K] lo

// ================= PTX helpers =================
__device__ __forceinline__ uint32_t smem_u32(const void* p) {
    uint32_t a;
    asm("{ .reg .u64 t; cvta.to.shared.u64 t, %1; cvt.u32.u64 %0, t; }" : "=r"(a) : "l"(p));
    return a;
}
__device__ __forceinline__ void cpa16(uint32_t dst, const void* src) {
    asm volatile("cp.async.cg.shared.global [%0], [%1], 16;" :: "r"(dst), "l"(src));
}
#define CP_COMMIT() asm volatile("cp.async.commit_group;" ::: "memory")
#define CP_WAIT1()  asm volatile("cp.async.wait_group 1;" ::: "memory")

__device__ __forceinline__ void ldsm4(uint32_t a, uint32_t& r0, uint32_t& r1,
                                      uint32_t& r2, uint32_t& r3) {
    asm volatile("ldmatrix.sync.aligned.m8n8.x4.shared.b16 {%0,%1,%2,%3}, [%4];"
                 : "=r"(r0), "=r"(r1), "=r"(r2), "=r"(r3) : "r"(a));
}
__device__ __forceinline__ void ldsm4t(uint32_t a, uint32_t& r0, uint32_t& r1,
                                       uint32_t& r2, uint32_t& r3) {
    asm volatile("ldmatrix.sync.aligned.m8n8.x4.trans.shared.b16 {%0,%1,%2,%3}, [%4];"
                 : "=r"(r0), "=r"(r1), "=r"(r2), "=r"(r3) : "r"(a));
}
__device__ __forceinline__ void mma16816(float* d, uint32_t a0, uint32_t a1, uint32_t a2,
                                         uint32_t a3, uint32_t b0, uint32_t b1) {
    asm volatile("mma.sync.aligned.m16n8k16.row.col.f32.bf16.bf16.f32 "
                 "{%0,%1,%2,%3}, {%4,%5,%6,%7}, {%8,%9}, {%0,%1,%2,%3};"
                 : "+f"(d[0]), "+f"(d[1]), "+f"(d[2]), "+f"(d[3])
                 : "r"(a0), "r"(a1), "r"(a2), "r"(a3), "r"(b0), "r"(b1));
}
__device__ __forceinline__ void split2(float a, float b, uint32_t& h, uint32_t& l) {
    __nv_bfloat16 h0 = __float2bfloat16(a), h1 = __float2bfloat16(b);
    __nv_bfloat162 hh(h0, h1); h = *(uint32_t*)&hh;
    __nv_bfloat16 l0 = __float2bfloat16(a - __bfloat162float(h0));
    __nv_bfloat16 l1 = __float2bfloat16(b - __bfloat162float(h1));
    __nv_bfloat162 ll(l0, l1); l = *(uint32_t*)&ll;
}

// ================= fused x-split + phase/log-gate =================
__global__ __launch_bounds__(256) void split_phase(const float* __restrict__ x,
                                                   const float* __restrict__ w_phase,
                                                   const float* __restrict__ carrier,
                                                   const float* __restrict__ lock,
                                                   const float* __restrict__ bwp,
                                                   __nv_bfloat16* __restrict__ hi,
                                                   __nv_bfloat16* __restrict__ lo,
                                                   float* __restrict__ lg)
{
    const int token = blockIdx.x;
    const int tid = threadIdx.x;
    const size_t i = (size_t)token * BDIM + tid * 4;
    float4 v = *(const float4*)(x + i);
    uint32_t h0, l0, h1, l1;
    split2(v.x, v.y, h0, l0);
    split2(v.z, v.w, h1, l1);
    *(uint32_t*)(hi + i)     = h0;  *(uint32_t*)(hi + i + 2) = h1;
    *(uint32_t*)(lo + i)     = l0;  *(uint32_t*)(lo + i + 2) = l1;

    float4 wa = *(const float4*)(w_phase + tid * 8);
    float4 wb = *(const float4*)(w_phase + tid * 8 + 4);
    float p0 = v.x * wa.x + v.y * wa.z + v.z * wb.x + v.w * wb.z;
    float p1 = v.x * wa.y + v.y * wa.w + v.z * wb.y + v.w * wb.w;
#pragma unroll
    for (int o = 16; o > 0; o >>= 1) {
        p0 += __shfl_down_sync(0xffffffffu, p0, o);
        p1 += __shfl_down_sync(0xffffffffu, p1, o);
    }
    __shared__ float s0[8], s1[8];
    __shared__ float phs;
    if ((tid & 31) == 0) { s0[tid >> 5] = p0; s1[tid >> 5] = p1; }
    __syncthreads();
    if (tid == 0) {
        float a = 0.f, b = 0.f;
#pragma unroll
        for (int k = 0; k < 8; k++) { a += s0[k]; b += s1[k]; }
        phs = atan2f(a, b);
    }
    __syncthreads();
    if (tid < NH) {
        float dphi = phs - carrier[tid];
        float w = expf((cosf(dphi) - 1.f) / bwp[tid]);
        float g = lock[tid] * w + (1.f - lock[tid]);
        const int b2 = token / SEQ, s = token % SEQ;
        lg[((size_t)b2 * NH + tid) * SEQ + s] = logf(g + 1e-6f);
    }
}

// ================= weight transpose+split (all 4 matrices, z-indexed) =================
__global__ __launch_bounds__(256) void tsplit4(const float* __restrict__ w0,
                                               const float* __restrict__ w1,
                                               const float* __restrict__ w2,
                                               const float* __restrict__ w3,
                                               __nv_bfloat16* __restrict__ ht,
                                               __nv_bfloat16* __restrict__ lt) {
    const float* w = (blockIdx.z == 0) ? w0 : (blockIdx.z == 1) ? w1
                   : (blockIdx.z == 2) ? w2 : w3;
    __nv_bfloat16* hb = ht + (size_t)blockIdx.z * NW;
    __nv_bfloat16* lb = lt + (size_t)blockIdx.z * NW;
    __shared__ float t[32][33];
    const int k0 = blockIdx.y * 32, n0 = blockIdx.x * 32;
    const int tx = threadIdx.x, ty = threadIdx.y;
#pragma unroll
    for (int r = ty; r < 32; r += 8)
        t[r][tx] = w[(size_t)(k0 + r) * BDIM + n0 + tx];
    __syncthreads();
#pragma unroll
    for (int r = ty; r < 32; r += 8) {
        float x = t[tx][r];
        __nv_bfloat16 h = __float2bfloat16(x);
        __nv_bfloat16 l = __float2bfloat16(x - __bfloat162float(h));
        hb[(size_t)(n0 + r) * BDIM + k0 + tx] = h;
        lb[(size_t)(n0 + r) * BDIM + k0 + tx] = l;
    }
}

// ================= HMMA bf16x3 GEMM mainloop (shared by qkv / wo kernels) =============
#define BK     32
#define NK     32                   // 1024/32
#define PITCH  40
#define TILEB  (128 * PITCH * 2)    // 10240 B per tile
#define STG4   (4 * TILEB)          // 40960 B per stage (Ah|Al|Bh|Bl)
#define GSMEM  (2 * STG4)           // 81920 B

struct GemmCtx {
    uint32_t base;
    int tid, ln, wm, wn, m0, n0;
    uint32_t sm_off0, sm_off1;
    const __nv_bfloat16 *pAh0, *pAh1, *pAl0, *pAl1, *pBh0, *pBh1, *pBl0, *pBl1;
};

__device__ __forceinline__ void gemm_mainloop(GemmCtx& c, float acc[4][4][4]) {
    const int ln = c.ln;
    const int lm_sub = ((ln >> 3) & 1) * 8 + (ln & 7);
    const int lm_kc  = ln >> 4;

    auto issue = [&](int chunk) {
        const int kloc = chunk * BK;
        const uint32_t st = c.base + (chunk & 1) * STG4;
        cpa16(st + 0 * TILEB + c.sm_off0, c.pAh0 + kloc);
        cpa16(st + 0 * TILEB + c.sm_off1, c.pAh1 + kloc);
        cpa16(st + 1 * TILEB + c.sm_off0, c.pAl0 + kloc);
        cpa16(st + 1 * TILEB + c.sm_off1, c.pAl1 + kloc);
        cpa16(st + 2 * TILEB + c.sm_off0, c.pBh0 + kloc);
        cpa16(st + 2 * TILEB + c.sm_off1, c.pBh1 + kloc);
        cpa16(st + 3 * TILEB + c.sm_off0, c.pBl0 + kloc);
        cpa16(st + 3 * TILEB + c.sm_off1, c.pBl1 + kloc);
        CP_COMMIT();
    };

    issue(0); issue(1);

    for (int chunk = 0; chunk < NK; chunk++) {
        CP_WAIT1();
        __syncthreads();

        const uint32_t st = c.base + (chunk & 1) * STG4;
        const uint32_t tAh = st, tAl = st + TILEB, tBh = st + 2 * TILEB, tBl = st + 3 * TILEB;

#pragma unroll
        for (int ks = 0; ks < 2; ks++) {
            const uint32_t ko = (ks * 2 + lm_kc) * 8;
            uint32_t ah[4][4], al[4][4];
#pragma unroll
            for (int mi = 0; mi < 4; mi++) {
                const uint32_t ro = ((c.wm * 64 + mi * 16 + lm_sub) * PITCH + ko) * 2;
                ldsm4(tAh + ro, ah[mi][0], ah[mi][1], ah[mi][2], ah[mi][3]);
                ldsm4(tAl + ro, al[mi][0], al[mi][1], al[mi][2], al[mi][3]);
            }
            uint32_t bh[4][2], bl[4][2];
#pragma unroll
            for (int nb = 0; nb < 2; nb++) {
                const uint32_t ro = ((c.wn * 32 + nb * 16 + lm_sub) * PITCH + ko) * 2;
                uint32_t r0, r1, r2, r3;
                ldsm4(tBh + ro, r0, r1, r2, r3);
                bh[nb * 2 + 0][0] = r0; bh[nb * 2 + 0][1] = r2;
                bh[nb * 2 + 1][0] = r1; bh[nb * 2 + 1][1] = r3;
                ldsm4(tBl + ro, r0, r1, r2, r3);
                bl[nb * 2 + 0][0] = r0; bl[nb * 2 + 0][1] = r2;
                bl[nb * 2 + 1][0] = r1; bl[nb * 2 + 1][1] = r3;
            }
#pragma unroll
            for (int mi = 0; mi < 4; mi++)
#pragma unroll
                for (int ni = 0; ni < 4; ni++) {
                    mma16816(acc[mi][ni], ah[mi][0], ah[mi][1], ah[mi][2], ah[mi][3],
                             bh[ni][0], bh[ni][1]);
                    mma16816(acc[mi][ni], al[mi][0], al[mi][1], al[mi][2], al[mi][3],
                             bh[ni][0], bh[ni][1]);
                    mma16816(acc[mi][ni], ah[mi][0], ah[mi][1], ah[mi][2], ah[mi][3],
                             bl[ni][0], bl[ni][1]);
                }
        }

        __syncthreads();
        if (chunk + 2 < NK) issue(chunk + 2);
        else CP_COMMIT();
    }
}

__device__ __forceinline__ void gemm_setup(GemmCtx& c, char* gsm,
                                           const __nv_bfloat16* Ah, const __nv_bfloat16* Al,
                                           const __nv_bfloat16* Bh, const __nv_bfloat16* Bl) {
    c.base = smem_u32(gsm);
    c.tid = threadIdx.x;
    c.ln  = c.tid & 31;
    const int wid = c.tid >> 5;
    c.wm  = wid >> 2;
    c.wn  = wid & 3;
    c.m0 = blockIdx.y * 128;
    c.n0 = blockIdx.x * 128;
    const int ld_row0 = c.tid >> 2;
    const int ld_ch0  = c.tid & 3;
    const int ld_row1 = ld_row0 + 64;
    c.sm_off0 = (ld_row0 * PITCH + ld_ch0 * 8) * 2;
    c.sm_off1 = (ld_row1 * PITCH + ld_ch0 * 8) * 2;
    c.pAh0 = Ah + (size_t)(c.m0 + ld_row0) * BDIM + ld_ch0 * 8;
    c.pAh1 = Ah + (size_t)(c.m0 + ld_row1) * BDIM + ld_ch0 * 8;
    c.pAl0 = Al + (size_t)(c.m0 + ld_row0) * BDIM + ld_ch0 * 8;
    c.pAl1 = Al + (size_t)(c.m0 + ld_row1) * BDIM + ld_ch0 * 8;
    c.pBh0 = Bh + (size_t)(c.n0 + ld_row0) * BDIM + ld_ch0 * 8;
    c.pBh1 = Bh + (size_t)(c.n0 + ld_row1) * BDIM + ld_ch0 * 8;
    c.pBl0 = Bl + (size_t)(c.n0 + ld_row0) * BDIM + ld_ch0 * 8;
    c.pBl1 = Bl + (size_t)(c.n0 + ld_row1) * BDIM + ld_ch0 * 8;
}

// fused QKV GEMM: blockIdx.z selects weight matrix + split output
__global__ __launch_bounds__(256, 2) void gemm_qkv(const __nv_bfloat16* __restrict__ xh,
                                                   const __nv_bfloat16* __restrict__ xl,
                                                   const __nv_bfloat16* __restrict__ whB,
                                                   const __nv_bfloat16* __restrict__ wlB,
                                                   __nv_bfloat16* __restrict__ qh,
                                                   __nv_bfloat16* __restrict__ ql,
                                                   __nv_bfloat16* __restrict__ kh,
                                                   __nv_bfloat16* __restrict__ kl,
                                                   __nv_bfloat16* __restrict__ vh,
                                                   __nv_bfloat16* __restrict__ vl) {
    extern __shared__ __align__(16) char gsm[];
    const int z = blockIdx.z;
    __nv_bfloat16* Ch = (z == 0) ? qh : (z == 1) ? kh : vh;
    __nv_bfloat16* Cl = (z == 0) ? ql : (z == 1) ? kl : vl;

    GemmCtx c;
    gemm_setup(c, gsm, xh, xl, whB + (size_t)z * NW, wlB + (size_t)z * NW);

    float acc[4][4][4];
#pragma unroll
    for (int i = 0; i < 4; i++)
#pragma unroll
        for (int j = 0; j < 4; j++)
#pragma unroll
            for (int r = 0; r < 4; r++) acc[i][j][r] = 0.f;

    gemm_mainloop(c, acc);

    const int er = c.ln >> 2, ec = (c.ln & 3) * 2;
#pragma unroll
    for (int mi = 0; mi < 4; mi++)
#pragma unroll
        for (int ni = 0; ni < 4; ni++) {
            const int m = c.m0 + c.wm * 64 + mi * 16 + er;
            const int n = c.n0 + c.wn * 32 + ni * 8 + ec;
            uint32_t h, l;
            split2(acc[mi][ni][0], acc[mi][ni][1], h, l);
            *(uint32_t*)(Ch + (size_t)m * BDIM + n) = h;
            *(uint32_t*)(Cl + (size_t)m * BDIM + n) = l;
            split2(acc[mi][ni][2], acc[mi][ni][3], h, l);
            *(uint32_t*)(Ch + (size_t)(m + 8) * BDIM + n) = h;
            *(uint32_t*)(Cl + (size_t)(m + 8) * BDIM + n) = l;
        }
}

// output projection: fp32 result
__global__ __launch_bounds__(256, 2) void gemm_wo(const __nv_bfloat16* __restrict__ Ah,
                                                  const __nv_bfloat16* __restrict__ Al,
                                                  const __nv_bfloat16* __restrict__ Bh,
                                                  const __nv_bfloat16* __restrict__ Bl,
                                                  float* __restrict__ C) {
    extern __shared__ __align__(16) char gsm[];
    GemmCtx c;
    gemm_setup(c, gsm, Ah, Al, Bh, Bl);

    float acc[4][4][4];
#pragma unroll
    for (int i = 0; i < 4; i++)
#pragma unroll
        for (int j = 0; j < 4; j++)
#pragma unroll
            for (int r = 0; r < 4; r++) acc[i][j][r] = 0.f;

    gemm_mainloop(c, acc);

    const int er = c.ln >> 2, ec = (c.ln & 3) * 2;
#pragma unroll
    for (int mi = 0; mi < 4; mi++)
#pragma unroll
        for (int ni = 0; ni < 4; ni++) {
            const int m = c.m0 + c.wm * 64 + mi * 16 + er;
            const int n = c.n0 + c.wn * 32 + ni * 8 + ec;
            *(float2*)(C + (size_t)m * BDIM + n)       = make_float2(acc[mi][ni][0], acc[mi][ni][1]);
            *(float2*)(C + (size_t)(m + 8) * BDIM + n) = make_float2(acc[mi][ni][2], acc[mi][ni][3]);
        }
}

// ================= HMMA flash attention — double-buffered K/V =================
#define AP     72
#define QBYTES (128 * AP * 2)          // 18432 per Q tile
#define KVT    (64 * AP * 2)           // 9216 per KV tile
#define STAGEB (4 * KVT + 256)         // 37120 per stage (Kh|Kl|Vh|Vl|LG)
#define ASMEM  (2 * QBYTES + 2 * STAGEB)   // 111104

__global__ __launch_bounds__(256) void attn_hmma(const int* __restrict__ active,
                                                 const __nv_bfloat16* __restrict__ Qh,
                                                 const __nv_bfloat16* __restrict__ Ql,
                                                 const __nv_bfloat16* __restrict__ Kh,
                                                 const __nv_bfloat16* __restrict__ Kl,
                                                 const __nv_bfloat16* __restrict__ Vh,
                                                 const __nv_bfloat16* __restrict__ Vl,
                                                 const float* __restrict__ LG,
                                                 __nv_bfloat16* __restrict__ Oh,
                                                 __nv_bfloat16* __restrict__ Ol)
{
    extern __shared__ __align__(16) char asmem[];
    const uint32_t ub = smem_u32(asmem);

    const int tid = threadIdx.x;
    const int ln  = tid & 31;
    const int w   = tid >> 5;
    const int qb  = blockIdx.x;
    const int h   = blockIdx.y;
    const int b   = blockIdx.z;
    const int q0  = qb * 128;
    const size_t gbase = ((size_t)b * SEQ) * BDIM + (size_t)h * DHD;

    if (active[h] == 0) {
#pragma unroll
        for (int i = 0; i < 4; i++) {
            const int idx = tid + i * 256;
            const int row = idx >> 3, ch = idx & 7;
            *(uint4*)(Oh + gbase + (size_t)(q0 + row) * BDIM + ch * 8) = make_uint4(0, 0, 0, 0);
            *(uint4*)(Ol + gbase + (size_t)(q0 + row) * BDIM + ch * 8) = make_uint4(0, 0, 0, 0);
        }
        return;
    }

    const float* lgp = LG + ((size_t)b * NH + h) * SEQ;
    const int ktiles = 2 * qb + 2;

    // Q tile (hi, lo) -> group 0
#pragma unroll
    for (int i = 0; i < 4; i++) {
        const int idx = tid + i * 256;
        const int row = idx >> 3, ch = idx & 7;
        cpa16(ub + (row * AP + ch * 8) * 2,          Qh + gbase + (size_t)(q0 + row) * BDIM + ch * 8);
        cpa16(ub + QBYTES + (row * AP + ch * 8) * 2, Ql + gbase + (size_t)(q0 + row) * BDIM + ch * 8);
    }
    CP_COMMIT();

    auto issueKV = [&](int t) {
        const int k0 = t * 64;
        const uint32_t sb = ub + 2 * QBYTES + (t & 1) * STAGEB;
#pragma unroll
        for (int i = 0; i < 2; i++) {
            const int idx = tid + i * 256;
            const int row = idx >> 3, ch = idx & 7;
            const size_t g = gbase + (size_t)(k0 + row) * BDIM + ch * 8;
            const uint32_t s = (row * AP + ch * 8) * 2;
            cpa16(sb + 0 * KVT + s, Kh + g);
            cpa16(sb + 1 * KVT + s, Kl + g);
            cpa16(sb + 2 * KVT + s, Vh + g);
            cpa16(sb + 3 * KVT + s, Vl + g);
        }
        if (tid < 16) cpa16(sb + 4 * KVT + tid * 16, lgp + k0 + tid * 4);
        CP_COMMIT();
    };

    issueKV(0);

    const int lm_sub = ((ln >> 3) & 1) * 8 + (ln & 7);
    const int half   = ln >> 4;
    const int er = ln >> 2, ec = (ln & 3) * 2;
    const int rowg0 = q0 + 16 * w + er;
    const int rowg1 = rowg0 + 8;

    float m0 = -INFINITY, m1 = -INFINITY, l0 = 0.f, l1 = 0.f;
    float ofr[8][4];
#pragma unroll
    for (int j = 0; j < 8; j++)
#pragma unroll
        for (int r = 0; r < 4; r++) ofr[j][r] = 0.f;

    for (int t = 0; t < ktiles; t++) {
        const int k0 = t * 64;
        if (t + 1 < ktiles) issueKV(t + 1);
        else CP_COMMIT();               // keep wait_group arithmetic exact
        CP_WAIT1();                     // Q + KV(t) retired (only KV(t+1) may pend)
        __syncthreads();

        const uint32_t sb = ub + 2 * QBYTES + (t & 1) * STAGEB;
        const uint32_t sKH = sb, sKL = sb + KVT, sVH = sb + 2 * KVT, sVL = sb + 3 * KVT;
        float* slg = (float*)(asmem + 2 * QBYTES + (t & 1) * STAGEB + 4 * KVT);

        if (k0 <= q0 + 16 * w + 15) {
            float sf[8][4];
#pragma unroll
            for (int j = 0; j < 8; j++)
#pragma unroll
                for (int r = 0; r < 4; r++) sf[j][r] = 0.f;

#pragma unroll
            for (int kc = 0; kc < 4; kc++) {
                const uint32_t qoff = ((16 * w + lm_sub) * AP + kc * 16 + half * 8) * 2;
                uint32_t ah0, ah1, ah2, ah3, al0, al1, al2, al3;
                ldsm4(ub + qoff, ah0, ah1, ah2, ah3);
                ldsm4(ub + QBYTES + qoff, al0, al1, al2, al3);
#pragma unroll
                for (int g = 0; g < 4; g++) {
                    const uint32_t koff = ((g * 16 + lm_sub) * AP + kc * 16 + half * 8) * 2;
                    uint32_t bh0, bh1, bh2, bh3, bl0, bl1, bl2, bl3;
                    ldsm4(sKH + koff, bh0, bh1, bh2, bh3);
                    ldsm4(sKL + koff, bl0, bl1, bl2, bl3);
                    mma16816(sf[2 * g],     ah0, ah1, ah2, ah3, bh0, bh2);
                    mma16816(sf[2 * g + 1], ah0, ah1, ah2, ah3, bh1, bh3);
                    mma16816(sf[2 * g],     al0, al1, al2, al3, bh0, bh2);
                    mma16816(sf[2 * g + 1], al0, al1, al2, al3, bh1, bh3);
                    mma16816(sf[2 * g],     ah0, ah1, ah2, ah3, bl0, bl2);
                    mma16816(sf[2 * g + 1], ah0, ah1, ah2, ah3, bl1, bl3);
                }
            }

            float mx0 = -INFINITY, mx1 = -INFINITY;
#pragma unroll
            for (int j = 0; j < 8; j++) {
                const int c0 = k0 + 8 * j + ec, c1 = c0 + 1;
                const float g0 = slg[8 * j + ec], g1 = slg[8 * j + ec + 1];
                float v0 = sf[j][0] * 0.125f + g0; if (c0 > rowg0) v0 = -INFINITY;
                float v1 = sf[j][1] * 0.125f + g1; if (c1 > rowg0) v1 = -INFINITY;
                float v2 = sf[j][2] * 0.125f + g0; if (c0 > rowg1) v2 = -INFINITY;
                float v3 = sf[j][3] * 0.125f + g1; if (c1 > rowg1) v3 = -INFINITY;
                sf[j][0] = v0; sf[j][1] = v1; sf[j][2] = v2; sf[j][3] = v3;
                mx0 = fmaxf(mx0, fmaxf(v0, v1));
                mx1 = fmaxf(mx1, fmaxf(v2, v3));
            }
            mx0 = fmaxf(mx0, __shfl_xor_sync(0xffffffffu, mx0, 1));
            mx0 = fmaxf(mx0, __shfl_xor_sync(0xffffffffu, mx0, 2));
            mx1 = fmaxf(mx1, __shfl_xor_sync(0xffffffffu, mx1, 1));
            mx1 = fmaxf(mx1, __shfl_xor_sync(0xffffffffu, mx1, 2));
            const float mn0 = fmaxf(m0, mx0), mn1 = fmaxf(m1, mx1);
            const float fac0 = expf(m0 - mn0), fac1 = expf(m1 - mn1);
            m0 = mn0; m1 = mn1;

            float sum0 = 0.f, sum1 = 0.f;
#pragma unroll
            for (int j = 0; j < 8; j++) {
                float p0 = expf(sf[j][0] - m0), p1 = expf(sf[j][1] - m0);
                float p2 = expf(sf[j][2] - m1), p3 = expf(sf[j][3] - m1);
                sf[j][0] = p0; sf[j][1] = p1; sf[j][2] = p2; sf[j][3] = p3;
                sum0 += p0 + p1; sum1 += p2 + p3;
            }
            sum0 += __shfl_xor_sync(0xffffffffu, sum0, 1);
            sum0 += __shfl_xor_sync(0xffffffffu, sum0, 2);
            sum1 += __shfl_xor_sync(0xffffffffu, sum1, 1);
            sum1 += __shfl_xor_sync(0xffffffffu, sum1, 2);
            l0 = l0 * fac0 + sum0;
            l1 = l1 * fac1 + sum1;
#pragma unroll
            for (int j = 0; j < 8; j++) {
                ofr[j][0] *= fac0; ofr[j][1] *= fac0;
                ofr[j][2] *= fac1; ofr[j][3] *= fac1;
            }

            uint32_t aph[4][4], apl[4][4];
#pragma unroll
            for (int tt = 0; tt < 4; tt++) {
                split2(sf[2 * tt][0],     sf[2 * tt][1],     aph[tt][0], apl[tt][0]);
                split2(sf[2 * tt][2],     sf[2 * tt][3],     aph[tt][1], apl[tt][1]);
                split2(sf[2 * tt + 1][0], sf[2 * tt + 1][1], aph[tt][2], apl[tt][2]);
                split2(sf[2 * tt + 1][2], sf[2 * tt + 1][3], aph[tt][3], apl[tt][3]);
            }

#pragma unroll
            for (int tt = 0; tt < 4; tt++) {
#pragma unroll
                for (int g = 0; g < 4; g++) {
                    const uint32_t voff = ((tt * 16 + lm_sub) * AP + g * 16 + half * 8) * 2;
                    uint32_t vh0, vh1, vh2, vh3, vl0, vl1, vl2, vl3;
                    ldsm4t(sVH + voff, vh0, vh1, vh2, vh3);
                    ldsm4t(sVL + voff, vl0, vl1, vl2, vl3);
                    mma16816(ofr[2 * g],     aph[tt][0], aph[tt][1], aph[tt][2], aph[tt][3], vh0, vh1);
                    mma16816(ofr[2 * g + 1], aph[tt][0], aph[tt][1], aph[tt][2], aph[tt][3], vh2, vh3);
                    mma16816(ofr[2 * g],     apl[tt][0], apl[tt][1], apl[tt][2], apl[tt][3], vh0, vh1);
                    mma16816(ofr[2 * g + 1], apl[tt][0], apl[tt][1], apl[tt][2], apl[tt][3], vh2, vh3);
                    mma16816(ofr[2 * g],     aph[tt][0], aph[tt][1], aph[tt][2], aph[tt][3], vl0, vl1);
                    mma16816(ofr[2 * g + 1], aph[tt][0], aph[tt][1], aph[tt][2], aph[tt][3], vl2, vl3);
                }
            }
        }
        __syncthreads();    // all warps done with stage (t&1) before overwrite at t+1's issue
    }

    const float inv0 = 1.f / l0, inv1 = 1.f / l1;
#pragma unroll
    for (int j = 0; j < 8; j++) {
        uint32_t hh, ll;
        split2(ofr[j][0] * inv0, ofr[j][1] * inv0, hh, ll);
        *(uint32_t*)(Oh + gbase + (size_t)rowg0 * BDIM + 8 * j + ec) = hh;
        *(uint32_t*)(Ol + gbase + (size_t)rowg0 * BDIM + 8 * j + ec) = ll;
        split2(ofr[j][2] * inv1, ofr[j][3] * inv1, hh, ll);
        *(uint32_t*)(Oh + gbase + (size_t)rowg1 * BDIM + 8 * j + ec) = hh;
        *(uint32_t*)(Ol + gbase + (size_t)rowg1 * BDIM + 8 * j + ec) = ll;
    }
}

// ---------------- launch ----------------
extern "C" void kernel_launch(void* const* d_in, const int* in_sizes, int n_in,
                              void* d_out, int out_size)
{
    const float* x        = (const float*)d_in[0];
    const float* wq       = (const float*)d_in[1];
    const float* wk       = (const float*)d_in[2];
    const float* wv       = (const float*)d_in[3];
    const float* wo       = (const float*)d_in[4];
    const float* w_phase  = (const float*)d_in[5];
    const float* carrier  = (const float*)d_in[6];
    const float* lock     = (const float*)d_in[7];
    const float* bw       = (const float*)d_in[8];
    const int*   amask    = (const int*)d_in[9];
    float* out = (float*)d_out;

    float *LG;
    __nv_bfloat16 *xh, *xl, *qh, *ql, *kh, *kl, *vh, *vl, *oh, *ol, *wh, *wl;
    cudaGetSymbolAddress((void**)&LG, g_LG);
    cudaGetSymbolAddress((void**)&xh, g_xh);
    cudaGetSymbolAddress((void**)&xl, g_xl);
    cudaGetSymbolAddress((void**)&qh, g_qh);
    cudaGetSymbolAddress((void**)&ql, g_ql);
    cudaGetSymbolAddress((void**)&kh, g_kh);
    cudaGetSymbolAddress((void**)&kl, g_kl);
    cudaGetSymbolAddress((void**)&vh, g_vh);
    cudaGetSymbolAddress((void**)&vl, g_vl);
    cudaGetSymbolAddress((void**)&oh, g_oh);
    cudaGetSymbolAddress((void**)&ol, g_ol);
    cudaGetSymbolAddress((void**)&wh, g_wh);
    cudaGetSymbolAddress((void**)&wl, g_wl);

    cudaFuncSetAttribute(attn_hmma, cudaFuncAttributeMaxDynamicSharedMemorySize, ASMEM);
    cudaFuncSetAttribute(gemm_qkv,  cudaFuncAttributeMaxDynamicSharedMemorySize, GSMEM);
    cudaFuncSetAttribute(gemm_wo,   cudaFuncAttributeMaxDynamicSharedMemorySize, GSMEM);

    dim3 gg3(BDIM / 128, MTOT / 128, 3);   // fused QKV
    dim3 gg(BDIM / 128, MTOT / 128);

    split_phase<<<MTOT, 256>>>(x, w_phase, carrier, lock, bw, xh, xl, LG);
    tsplit4<<<dim3(32, 32, 4), dim3(32, 8)>>>(wq, wk, wv, wo, wh, wl);

    gemm_qkv<<<gg3, 256, GSMEM>>>(xh, xl, wh, wl, qh, ql, kh, kl, vh, vl);

    attn_hmma<<<dim3(SEQ / 128, NH, NB), 256, ASMEM>>>(amask, qh, ql, kh, kl, vh, vl, LG, oh, ol);

    gemm_wo<<<gg, 256, GSMEM>>>(oh, ol, wh + 3 * (size_t)NW, wl + 3 * (size_t)NW, out);
}

// round 14
// speedup vs baseline: 2.1990x; 1.0109x over previous
#include <cuda_runtime.h>
#include <cuda_bf16.h>
#include <math.h>
#include <stdint.h>

#define BDIM 1024
#define SEQ  1024
#define NB   4
#define NH   16
#define DHD  64
#define MTOT (NB * SEQ)   // 4096
#define NW   (BDIM * BDIM)

// ---------------- scratch (static device memory: allocation-free) ----------------
__device__ float g_LG[NB * NH * SEQ];
__device__ __nv_bfloat16 g_xh[MTOT * BDIM];
__device__ __nv_bfloat16 g_xl[MTOT * BDIM];
__device__ __nv_bfloat16 g_qh[MTOT * BDIM];
__device__ __nv_bfloat16 g_ql[MTOT * BDIM];
__device__ __nv_bfloat16 g_kh[MTOT * BDIM];
__device__ __nv_bfloat16 g_kl[MTOT * BDIM];
__device__ __nv_bfloat16 g_vh[MTOT * BDIM];
__device__ __nv_bfloat16 g_vl[MTOT * BDIM];
__device__ __nv_bfloat16 g_oh[MTOT * BDIM];
__device__ __nv_bfloat16 g_ol[MTOT * BDIM];
__device__ __nv_bfloat16 g_wh[4][NW];   // transposed [N][K] hi
__device__ __nv_bfloat16 g_wl[4][NW];   // transposed [N][K] lo

// ================= PTX helpers =================
__device__ __forceinline__ uint32_t smem_u32(const void* p) {
    uint32_t a;
    asm("{ .reg .u64 t; cvta.to.shared.u64 t, %1; cvt.u32.u64 %0, t; }" : "=r"(a) : "l"(p));
    return a;
}
__device__ __forceinline__ void cpa16(uint32_t dst, const void* src) {
    asm volatile("cp.async.cg.shared.global [%0], [%1], 16;" :: "r"(dst), "l"(src));
}
#define CP_COMMIT() asm volatile("cp.async.commit_group;" ::: "memory")
#define CP_WAIT1()  asm volatile("cp.async.wait_group 1;" ::: "memory")

__device__ __forceinline__ void ldsm4(uint32_t a, uint32_t& r0, uint32_t& r1,
                                      uint32_t& r2, uint32_t& r3) {
    asm volatile("ldmatrix.sync.aligned.m8n8.x4.shared.b16 {%0,%1,%2,%3}, [%4];"
                 : "=r"(r0), "=r"(r1), "=r"(r2), "=r"(r3) : "r"(a));
}
__device__ __forceinline__ void ldsm4t(uint32_t a, uint32_t& r0, uint32_t& r1,
                                       uint32_t& r2, uint32_t& r3) {
    asm volatile("ldmatrix.sync.aligned.m8n8.x4.trans.shared.b16 {%0,%1,%2,%3}, [%4];"
                 : "=r"(r0), "=r"(r1), "=r"(r2), "=r"(r3) : "r"(a));
}
__device__ __forceinline__ void mma16816(float* d, uint32_t a0, uint32_t a1, uint32_t a2,
                                         uint32_t a3, uint32_t b0, uint32_t b1) {
    asm volatile("mma.sync.aligned.m16n8k16.row.col.f32.bf16.bf16.f32 "
                 "{%0,%1,%2,%3}, {%4,%5,%6,%7}, {%8,%9}, {%0,%1,%2,%3};"
                 : "+f"(d[0]), "+f"(d[1]), "+f"(d[2]), "+f"(d[3])
                 : "r"(a0), "r"(a1), "r"(a2), "r"(a3), "r"(b0), "r"(b1));
}
__device__ __forceinline__ void split2(float a, float b, uint32_t& h, uint32_t& l) {
    __nv_bfloat16 h0 = __float2bfloat16(a), h1 = __float2bfloat16(b);
    __nv_bfloat162 hh(h0, h1); h = *(uint32_t*)&hh;
    __nv_bfloat16 l0 = __float2bfloat16(a - __bfloat162float(h0));
    __nv_bfloat16 l1 = __float2bfloat16(b - __bfloat162float(h1));
    __nv_bfloat162 ll(l0, l1); l = *(uint32_t*)&ll;
}

// ================= fused x-split + phase/log-gate =================
__global__ __launch_bounds__(256) void split_phase(const float* __restrict__ x,
                                                   const float* __restrict__ w_phase,
                                                   const float* __restrict__ carrier,
                                                   const float* __restrict__ lock,
                                                   const float* __restrict__ bwp,
                                                   __nv_bfloat16* __restrict__ hi,
                                                   __nv_bfloat16* __restrict__ lo,
                                                   float* __restrict__ lg)
{
    const int token = blockIdx.x;
    const int tid = threadIdx.x;
    const size_t i = (size_t)token * BDIM + tid * 4;
    float4 v = *(const float4*)(x + i);
    uint32_t h0, l0, h1, l1;
    split2(v.x, v.y, h0, l0);
    split2(v.z, v.w, h1, l1);
    *(uint32_t*)(hi + i)     = h0;  *(uint32_t*)(hi + i + 2) = h1;
    *(uint32_t*)(lo + i)     = l0;  *(uint32_t*)(lo + i + 2) = l1;

    float4 wa = *(const float4*)(w_phase + tid * 8);
    float4 wb = *(const float4*)(w_phase + tid * 8 + 4);
    float p0 = v.x * wa.x + v.y * wa.z + v.z * wb.x + v.w * wb.z;
    float p1 = v.x * wa.y + v.y * wa.w + v.z * wb.y + v.w * wb.w;
#pragma unroll
    for (int o = 16; o > 0; o >>= 1) {
        p0 += __shfl_down_sync(0xffffffffu, p0, o);
        p1 += __shfl_down_sync(0xffffffffu, p1, o);
    }
    __shared__ float s0[8], s1[8];
    __shared__ float phs;
    if ((tid & 31) == 0) { s0[tid >> 5] = p0; s1[tid >> 5] = p1; }
    __syncthreads();
    if (tid == 0) {
        float a = 0.f, b = 0.f;
#pragma unroll
        for (int k = 0; k < 8; k++) { a += s0[k]; b += s1[k]; }
        phs = atan2f(a, b);
    }
    __syncthreads();
    if (tid < NH) {
        float dphi = phs - carrier[tid];
        float w = __expf((cosf(dphi) - 1.f) / bwp[tid]);   // __expf: arg <= 0, rel err 2^-21
        float g = lock[tid] * w + (1.f - lock[tid]);
        const int b2 = token / SEQ, s = token % SEQ;
        lg[((size_t)b2 * NH + tid) * SEQ + s] = __logf(g + 1e-6f);
    }
}

// ================= weight transpose+split (all 4 matrices, z-indexed) =================
__global__ __launch_bounds__(256) void tsplit4(const float* __restrict__ w0,
                                               const float* __restrict__ w1,
                                               const float* __restrict__ w2,
                                               const float* __restrict__ w3,
                                               __nv_bfloat16* __restrict__ ht,
                                               __nv_bfloat16* __restrict__ lt) {
    const float* w = (blockIdx.z == 0) ? w0 : (blockIdx.z == 1) ? w1
                   : (blockIdx.z == 2) ? w2 : w3;
    __nv_bfloat16* hb = ht + (size_t)blockIdx.z * NW;
    __nv_bfloat16* lb = lt + (size_t)blockIdx.z * NW;
    __shared__ float t[32][33];
    const int k0 = blockIdx.y * 32, n0 = blockIdx.x * 32;
    const int tx = threadIdx.x, ty = threadIdx.y;
#pragma unroll
    for (int r = ty; r < 32; r += 8)
        t[r][tx] = w[(size_t)(k0 + r) * BDIM + n0 + tx];
    __syncthreads();
#pragma unroll
    for (int r = ty; r < 32; r += 8) {
        float x = t[tx][r];
        __nv_bfloat16 h = __float2bfloat16(x);
        __nv_bfloat16 l = __float2bfloat16(x - __bfloat162float(h));
        hb[(size_t)(n0 + r) * BDIM + k0 + tx] = h;
        lb[(size_t)(n0 + r) * BDIM + k0 + tx] = l;
    }
}

// ================= HMMA bf16x3 GEMM mainloop (shared by qkv / wo kernels) =============
#define BK     32
#define NK     32                   // 1024/32
#define PITCH  40
#define TILEB  (128 * PITCH * 2)    // 10240 B per tile
#define STG4   (4 * TILEB)          // 40960 B per stage (Ah|Al|Bh|Bl)
#define GSMEM  (2 * STG4)           // 81920 B

struct GemmCtx {
    uint32_t base;
    int tid, ln, wm, wn, m0, n0;
    uint32_t sm_off0, sm_off1;
    const __nv_bfloat16 *pAh0, *pAh1, *pAl0, *pAl1, *pBh0, *pBh1, *pBl0, *pBl1;
};

__device__ __forceinline__ void gemm_mainloop(GemmCtx& c, float acc[4][4][4]) {
    const int ln = c.ln;
    const int lm_sub = ((ln >> 3) & 1) * 8 + (ln & 7);
    const int lm_kc  = ln >> 4;

    auto issue = [&](int chunk) {
        const int kloc = chunk * BK;
        const uint32_t st = c.base + (chunk & 1) * STG4;
        cpa16(st + 0 * TILEB + c.sm_off0, c.pAh0 + kloc);
        cpa16(st + 0 * TILEB + c.sm_off1, c.pAh1 + kloc);
        cpa16(st + 1 * TILEB + c.sm_off0, c.pAl0 + kloc);
        cpa16(st + 1 * TILEB + c.sm_off1, c.pAl1 + kloc);
        cpa16(st + 2 * TILEB + c.sm_off0, c.pBh0 + kloc);
        cpa16(st + 2 * TILEB + c.sm_off1, c.pBh1 + kloc);
        cpa16(st + 3 * TILEB + c.sm_off0, c.pBl0 + kloc);
        cpa16(st + 3 * TILEB + c.sm_off1, c.pBl1 + kloc);
        CP_COMMIT();
    };

    issue(0); issue(1);

    for (int chunk = 0; chunk < NK; chunk++) {
        CP_WAIT1();
        __syncthreads();

        const uint32_t st = c.base + (chunk & 1) * STG4;
        const uint32_t tAh = st, tAl = st + TILEB, tBh = st + 2 * TILEB, tBl = st + 3 * TILEB;

#pragma unroll
        for (int ks = 0; ks < 2; ks++) {
            const uint32_t ko = (ks * 2 + lm_kc) * 8;
            uint32_t ah[4][4], al[4][4];
#pragma unroll
            for (int mi = 0; mi < 4; mi++) {
                const uint32_t ro = ((c.wm * 64 + mi * 16 + lm_sub) * PITCH + ko) * 2;
                ldsm4(tAh + ro, ah[mi][0], ah[mi][1], ah[mi][2], ah[mi][3]);
                ldsm4(tAl + ro, al[mi][0], al[mi][1], al[mi][2], al[mi][3]);
            }
            uint32_t bh[4][2], bl[4][2];
#pragma unroll
            for (int nb = 0; nb < 2; nb++) {
                const uint32_t ro = ((c.wn * 32 + nb * 16 + lm_sub) * PITCH + ko) * 2;
                uint32_t r0, r1, r2, r3;
                ldsm4(tBh + ro, r0, r1, r2, r3);
                bh[nb * 2 + 0][0] = r0; bh[nb * 2 + 0][1] = r2;
                bh[nb * 2 + 1][0] = r1; bh[nb * 2 + 1][1] = r3;
                ldsm4(tBl + ro, r0, r1, r2, r3);
                bl[nb * 2 + 0][0] = r0; bl[nb * 2 + 0][1] = r2;
                bl[nb * 2 + 1][0] = r1; bl[nb * 2 + 1][1] = r3;
            }
#pragma unroll
            for (int mi = 0; mi < 4; mi++)
#pragma unroll
                for (int ni = 0; ni < 4; ni++) {
                    mma16816(acc[mi][ni], ah[mi][0], ah[mi][1], ah[mi][2], ah[mi][3],
                             bh[ni][0], bh[ni][1]);
                    mma16816(acc[mi][ni], al[mi][0], al[mi][1], al[mi][2], al[mi][3],
                             bh[ni][0], bh[ni][1]);
                    mma16816(acc[mi][ni], ah[mi][0], ah[mi][1], ah[mi][2], ah[mi][3],
                             bl[ni][0], bl[ni][1]);
                }
        }

        __syncthreads();
        if (chunk + 2 < NK) issue(chunk + 2);
        else CP_COMMIT();
    }
}

__device__ __forceinline__ void gemm_setup(GemmCtx& c, char* gsm,
                                           const __nv_bfloat16* Ah, const __nv_bfloat16* Al,
                                           const __nv_bfloat16* Bh, const __nv_bfloat16* Bl) {
    c.base = smem_u32(gsm);
    c.tid = threadIdx.x;
    c.ln  = c.tid & 31;
    const int wid = c.tid >> 5;
    c.wm  = wid >> 2;
    c.wn  = wid & 3;
    c.m0 = blockIdx.y * 128;
    c.n0 = blockIdx.x * 128;
    const int ld_row0 = c.tid >> 2;
    const int ld_ch0  = c.tid & 3;
    const int ld_row1 = ld_row0 + 64;
    c.sm_off0 = (ld_row0 * PITCH + ld_ch0 * 8) * 2;
    c.sm_off1 = (ld_row1 * PITCH + ld_ch0 * 8) * 2;
    c.pAh0 = Ah + (size_t)(c.m0 + ld_row0) * BDIM + ld_ch0 * 8;
    c.pAh1 = Ah + (size_t)(c.m0 + ld_row1) * BDIM + ld_ch0 * 8;
    c.pAl0 = Al + (size_t)(c.m0 + ld_row0) * BDIM + ld_ch0 * 8;
    c.pAl1 = Al + (size_t)(c.m0 + ld_row1) * BDIM + ld_ch0 * 8;
    c.pBh0 = Bh + (size_t)(c.n0 + ld_row0) * BDIM + ld_ch0 * 8;
    c.pBh1 = Bh + (size_t)(c.n0 + ld_row1) * BDIM + ld_ch0 * 8;
    c.pBl0 = Bl + (size_t)(c.n0 + ld_row0) * BDIM + ld_ch0 * 8;
    c.pBl1 = Bl + (size_t)(c.n0 + ld_row1) * BDIM + ld_ch0 * 8;
}

// fused QKV GEMM: blockIdx.z selects weight matrix + split output
__global__ __launch_bounds__(256, 2) void gemm_qkv(const __nv_bfloat16* __restrict__ xh,
                                                   const __nv_bfloat16* __restrict__ xl,
                                                   const __nv_bfloat16* __restrict__ whB,
                                                   const __nv_bfloat16* __restrict__ wlB,
                                                   __nv_bfloat16* __restrict__ qh,
                                                   __nv_bfloat16* __restrict__ ql,
                                                   __nv_bfloat16* __restrict__ kh,
                                                   __nv_bfloat16* __restrict__ kl,
                                                   __nv_bfloat16* __restrict__ vh,
                                                   __nv_bfloat16* __restrict__ vl) {
    extern __shared__ __align__(16) char gsm[];
    const int z = blockIdx.z;
    __nv_bfloat16* Ch = (z == 0) ? qh : (z == 1) ? kh : vh;
    __nv_bfloat16* Cl = (z == 0) ? ql : (z == 1) ? kl : vl;

    GemmCtx c;
    gemm_setup(c, gsm, xh, xl, whB + (size_t)z * NW, wlB + (size_t)z * NW);

    float acc[4][4][4];
#pragma unroll
    for (int i = 0; i < 4; i++)
#pragma unroll
        for (int j = 0; j < 4; j++)
#pragma unroll
            for (int r = 0; r < 4; r++) acc[i][j][r] = 0.f;

    gemm_mainloop(c, acc);

    const int er = c.ln >> 2, ec = (c.ln & 3) * 2;
#pragma unroll
    for (int mi = 0; mi < 4; mi++)
#pragma unroll
        for (int ni = 0; ni < 4; ni++) {
            const int m = c.m0 + c.wm * 64 + mi * 16 + er;
            const int n = c.n0 + c.wn * 32 + ni * 8 + ec;
            uint32_t h, l;
            split2(acc[mi][ni][0], acc[mi][ni][1], h, l);
            *(uint32_t*)(Ch + (size_t)m * BDIM + n) = h;
            *(uint32_t*)(Cl + (size_t)m * BDIM + n) = l;
            split2(acc[mi][ni][2], acc[mi][ni][3], h, l);
            *(uint32_t*)(Ch + (size_t)(m + 8) * BDIM + n) = h;
            *(uint32_t*)(Cl + (size_t)(m + 8) * BDIM + n) = l;
        }
}

// output projection: fp32 result
__global__ __launch_bounds__(256, 2) void gemm_wo(const __nv_bfloat16* __restrict__ Ah,
                                                  const __nv_bfloat16* __restrict__ Al,
                                                  const __nv_bfloat16* __restrict__ Bh,
                                                  const __nv_bfloat16* __restrict__ Bl,
                                                  float* __restrict__ C) {
    extern __shared__ __align__(16) char gsm[];
    GemmCtx c;
    gemm_setup(c, gsm, Ah, Al, Bh, Bl);

    float acc[4][4][4];
#pragma unroll
    for (int i = 0; i < 4; i++)
#pragma unroll
        for (int j = 0; j < 4; j++)
#pragma unroll
            for (int r = 0; r < 4; r++) acc[i][j][r] = 0.f;

    gemm_mainloop(c, acc);

    const int er = c.ln >> 2, ec = (c.ln & 3) * 2;
#pragma unroll
    for (int mi = 0; mi < 4; mi++)
#pragma unroll
        for (int ni = 0; ni < 4; ni++) {
            const int m = c.m0 + c.wm * 64 + mi * 16 + er;
            const int n = c.n0 + c.wn * 32 + ni * 8 + ec;
            *(float2*)(C + (size_t)m * BDIM + n)       = make_float2(acc[mi][ni][0], acc[mi][ni][1]);
            *(float2*)(C + (size_t)(m + 8) * BDIM + n) = make_float2(acc[mi][ni][2], acc[mi][ni][3]);
        }
}

// ================= HMMA flash attention — double-buffered K/V, fast-exp softmax =========
#define AP     72
#define QBYTES (128 * AP * 2)          // 18432 per Q tile
#define KVT    (64 * AP * 2)           // 9216 per KV tile
#define STAGEB (4 * KVT + 256)         // 37120 per stage (Kh|Kl|Vh|Vl|LG)
#define ASMEM  (2 * QBYTES + 2 * STAGEB)   // 111104

__global__ __launch_bounds__(256) void attn_hmma(const int* __restrict__ active,
                                                 const __nv_bfloat16* __restrict__ Qh,
                                                 const __nv_bfloat16* __restrict__ Ql,
                                                 const __nv_bfloat16* __restrict__ Kh,
                                                 const __nv_bfloat16* __restrict__ Kl,
                                                 const __nv_bfloat16* __restrict__ Vh,
                                                 const __nv_bfloat16* __restrict__ Vl,
                                                 const float* __restrict__ LG,
                                                 __nv_bfloat16* __restrict__ Oh,
                                                 __nv_bfloat16* __restrict__ Ol)
{
    extern __shared__ __align__(16) char asmem[];
    const uint32_t ub = smem_u32(asmem);

    const int tid = threadIdx.x;
    const int ln  = tid & 31;
    const int w   = tid >> 5;
    const int qb  = blockIdx.x;
    const int h   = blockIdx.y;
    const int b   = blockIdx.z;
    const int q0  = qb * 128;
    const size_t gbase = ((size_t)b * SEQ) * BDIM + (size_t)h * DHD;

    if (active[h] == 0) {
#pragma unroll
        for (int i = 0; i < 4; i++) {
            const int idx = tid + i * 256;
            const int row = idx >> 3, ch = idx & 7;
            *(uint4*)(Oh + gbase + (size_t)(q0 + row) * BDIM + ch * 8) = make_uint4(0, 0, 0, 0);
            *(uint4*)(Ol + gbase + (size_t)(q0 + row) * BDIM + ch * 8) = make_uint4(0, 0, 0, 0);
        }
        return;
    }

    const float* lgp = LG + ((size_t)b * NH + h) * SEQ;
    const int ktiles = 2 * qb + 2;

    // Q tile (hi, lo) -> group 0
#pragma unroll
    for (int i = 0; i < 4; i++) {
        const int idx = tid + i * 256;
        const int row = idx >> 3, ch = idx & 7;
        cpa16(ub + (row * AP + ch * 8) * 2,          Qh + gbase + (size_t)(q0 + row) * BDIM + ch * 8);
        cpa16(ub + QBYTES + (row * AP + ch * 8) * 2, Ql + gbase + (size_t)(q0 + row) * BDIM + ch * 8);
    }
    CP_COMMIT();

    auto issueKV = [&](int t) {
        const int k0 = t * 64;
        const uint32_t sb = ub + 2 * QBYTES + (t & 1) * STAGEB;
#pragma unroll
        for (int i = 0; i < 2; i++) {
            const int idx = tid + i * 256;
            const int row = idx >> 3, ch = idx & 7;
            const size_t g = gbase + (size_t)(k0 + row) * BDIM + ch * 8;
            const uint32_t s = (row * AP + ch * 8) * 2;
            cpa16(sb + 0 * KVT + s, Kh + g);
            cpa16(sb + 1 * KVT + s, Kl + g);
            cpa16(sb + 2 * KVT + s, Vh + g);
            cpa16(sb + 3 * KVT + s, Vl + g);
        }
        if (tid < 16) cpa16(sb + 4 * KVT + tid * 16, lgp + k0 + tid * 4);
        CP_COMMIT();
    };

    issueKV(0);

    const int lm_sub = ((ln >> 3) & 1) * 8 + (ln & 7);
    const int half   = ln >> 4;
    const int er = ln >> 2, ec = (ln & 3) * 2;
    const int rowg0 = q0 + 16 * w + er;
    const int rowg1 = rowg0 + 8;

    float m0 = -INFINITY, m1 = -INFINITY, l0 = 0.f, l1 = 0.f;
    float ofr[8][4];
#pragma unroll
    for (int j = 0; j < 8; j++)
#pragma unroll
        for (int r = 0; r < 4; r++) ofr[j][r] = 0.f;

    for (int t = 0; t < ktiles; t++) {
        const int k0 = t * 64;
        if (t + 1 < ktiles) issueKV(t + 1);
        else CP_COMMIT();               // keep wait_group arithmetic exact
        CP_WAIT1();                     // Q + KV(t) retired (only KV(t+1) may pend)
        __syncthreads();

        const uint32_t sb = ub + 2 * QBYTES + (t & 1) * STAGEB;
        const uint32_t sKH = sb, sKL = sb + KVT, sVH = sb + 2 * KVT, sVL = sb + 3 * KVT;
        float* slg = (float*)(asmem + 2 * QBYTES + (t & 1) * STAGEB + 4 * KVT);

        if (k0 <= q0 + 16 * w + 15) {
            float sf[8][4];
#pragma unroll
            for (int j = 0; j < 8; j++)
#pragma unroll
                for (int r = 0; r < 4; r++) sf[j][r] = 0.f;

#pragma unroll
            for (int kc = 0; kc < 4; kc++) {
                const uint32_t qoff = ((16 * w + lm_sub) * AP + kc * 16 + half * 8) * 2;
                uint32_t ah0, ah1, ah2, ah3, al0, al1, al2, al3;
                ldsm4(ub + qoff, ah0, ah1, ah2, ah3);
                ldsm4(ub + QBYTES + qoff, al0, al1, al2, al3);
#pragma unroll
                for (int g = 0; g < 4; g++) {
                    const uint32_t koff = ((g * 16 + lm_sub) * AP + kc * 16 + half * 8) * 2;
                    uint32_t bh0, bh1, bh2, bh3, bl0, bl1, bl2, bl3;
                    ldsm4(sKH + koff, bh0, bh1, bh2, bh3);
                    ldsm4(sKL + koff, bl0, bl1, bl2, bl3);
                    mma16816(sf[2 * g],     ah0, ah1, ah2, ah3, bh0, bh2);
                    mma16816(sf[2 * g + 1], ah0, ah1, ah2, ah3, bh1, bh3);
                    mma16816(sf[2 * g],     al0, al1, al2, al3, bh0, bh2);
                    mma16816(sf[2 * g + 1], al0, al1, al2, al3, bh1, bh3);
                    mma16816(sf[2 * g],     ah0, ah1, ah2, ah3, bl0, bl2);
                    mma16816(sf[2 * g + 1], ah0, ah1, ah2, ah3, bl1, bl3);
                }
            }

            float mx0 = -INFINITY, mx1 = -INFINITY;
#pragma unroll
            for (int j = 0; j < 8; j++) {
                const int c0 = k0 + 8 * j + ec, c1 = c0 + 1;
                const float g0 = slg[8 * j + ec], g1 = slg[8 * j + ec + 1];
                float v0 = sf[j][0] * 0.125f + g0; if (c0 > rowg0) v0 = -INFINITY;
                float v1 = sf[j][1] * 0.125f + g1; if (c1 > rowg0) v1 = -INFINITY;
                float v2 = sf[j][2] * 0.125f + g0; if (c0 > rowg1) v2 = -INFINITY;
                float v3 = sf[j][3] * 0.125f + g1; if (c1 > rowg1) v3 = -INFINITY;
                sf[j][0] = v0; sf[j][1] = v1; sf[j][2] = v2; sf[j][3] = v3;
                mx0 = fmaxf(mx0, fmaxf(v0, v1));
                mx1 = fmaxf(mx1, fmaxf(v2, v3));
            }
            mx0 = fmaxf(mx0, __shfl_xor_sync(0xffffffffu, mx0, 1));
            mx0 = fmaxf(mx0, __shfl_xor_sync(0xffffffffu, mx0, 2));
            mx1 = fmaxf(mx1, __shfl_xor_sync(0xffffffffu, mx1, 1));
            mx1 = fmaxf(mx1, __shfl_xor_sync(0xffffffffu, mx1, 2));
            const float mn0 = fmaxf(m0, mx0), mn1 = fmaxf(m1, mx1);
            const float fac0 = __expf(m0 - mn0), fac1 = __expf(m1 - mn1);  // __expf(-inf)=0
            m0 = mn0; m1 = mn1;

            float sum0 = 0.f, sum1 = 0.f;
#pragma unroll
            for (int j = 0; j < 8; j++) {
                float p0 = __expf(sf[j][0] - m0), p1 = __expf(sf[j][1] - m0);
                float p2 = __expf(sf[j][2] - m1), p3 = __expf(sf[j][3] - m1);
                sf[j][0] = p0; sf[j][1] = p1; sf[j][2] = p2; sf[j][3] = p3;
                sum0 += p0 + p1; sum1 += p2 + p3;
            }
            sum0 += __shfl_xor_sync(0xffffffffu, sum0, 1);
            sum0 += __shfl_xor_sync(0xffffffffu, sum0, 2);
            sum1 += __shfl_xor_sync(0xffffffffu, sum1, 1);
            sum1 += __shfl_xor_sync(0xffffffffu, sum1, 2);
            l0 = l0 * fac0 + sum0;
            l1 = l1 * fac1 + sum1;
#pragma unroll
            for (int j = 0; j < 8; j++) {
                ofr[j][0] *= fac0; ofr[j][1] *= fac0;
                ofr[j][2] *= fac1; ofr[j][3] *= fac1;
            }

            uint32_t aph[4][4], apl[4][4];
#pragma unroll
            for (int tt = 0; tt < 4; tt++) {
                split2(sf[2 * tt][0],     sf[2 * tt][1],     aph[tt][0], apl[tt][0]);
                split2(sf[2 * tt][2],     sf[2 * tt][3],     aph[tt][1], apl[tt][1]);
                split2(sf[2 * tt + 1][0], sf[2 * tt + 1][1], aph[tt][2], apl[tt][2]);
                split2(sf[2 * tt + 1][2], sf[2 * tt + 1][3], aph[tt][3], apl[tt][3]);
            }

#pragma unroll
            for (int tt = 0; tt < 4; tt++) {
#pragma unroll
                for (int g = 0; g < 4; g++) {
                    const uint32_t voff = ((tt * 16 + lm_sub) * AP + g * 16 + half * 8) * 2;
                    uint32_t vh0, vh1, vh2, vh3, vl0, vl1, vl2, vl3;
                    ldsm4t(sVH + voff, vh0, vh1, vh2, vh3);
                    ldsm4t(sVL + voff, vl0, vl1, vl2, vl3);
                    mma16816(ofr[2 * g],     aph[tt][0], aph[tt][1], aph[tt][2], aph[tt][3], vh0, vh1);
                    mma16816(ofr[2 * g + 1], aph[tt][0], aph[tt][1], aph[tt][2], aph[tt][3], vh2, vh3);
                    mma16816(ofr[2 * g],     apl[tt][0], apl[tt][1], apl[tt][2], apl[tt][3], vh0, vh1);
                    mma16816(ofr[2 * g + 1], apl[tt][0], apl[tt][1], apl[tt][2], apl[tt][3], vh2, vh3);
                    mma16816(ofr[2 * g],     aph[tt][0], aph[tt][1], aph[tt][2], aph[tt][3], vl0, vl1);
                    mma16816(ofr[2 * g + 1], aph[tt][0], aph[tt][1], aph[tt][2], aph[tt][3], vl2, vl3);
                }
            }
        }
        __syncthreads();    // all warps done with stage (t&1) before overwrite at t+1's issue
    }

    const float inv0 = 1.f / l0, inv1 = 1.f / l1;
#pragma unroll
    for (int j = 0; j < 8; j++) {
        uint32_t hh, ll;
        split2(ofr[j][0] * inv0, ofr[j][1] * inv0, hh, ll);
        *(uint32_t*)(Oh + gbase + (size_t)rowg0 * BDIM + 8 * j + ec) = hh;
        *(uint32_t*)(Ol + gbase + (size_t)rowg0 * BDIM + 8 * j + ec) = ll;
        split2(ofr[j][2] * inv1, ofr[j][3] * inv1, hh, ll);
        *(uint32_t*)(Oh + gbase + (size_t)rowg1 * BDIM + 8 * j + ec) = hh;
        *(uint32_t*)(Ol + gbase + (size_t)rowg1 * BDIM + 8 * j + ec) = ll;
    }
}

// ---------------- launch ----------------
extern "C" void kernel_launch(void* const* d_in, const int* in_sizes, int n_in,
                              void* d_out, int out_size)
{
    const float* x        = (const float*)d_in[0];
    const float* wq       = (const float*)d_in[1];
    const float* wk       = (const float*)d_in[2];
    const float* wv       = (const float*)d_in[3];
    const float* wo       = (const float*)d_in[4];
    const float* w_phase  = (const float*)d_in[5];
    const float* carrier  = (const float*)d_in[6];
    const float* lock     = (const float*)d_in[7];
    const float* bw       = (const float*)d_in[8];
    const int*   amask    = (const int*)d_in[9];
    float* out = (float*)d_out;

    float *LG;
    __nv_bfloat16 *xh, *xl, *qh, *ql, *kh, *kl, *vh, *vl, *oh, *ol, *wh, *wl;
    cudaGetSymbolAddress((void**)&LG, g_LG);
    cudaGetSymbolAddress((void**)&xh, g_xh);
    cudaGetSymbolAddress((void**)&xl, g_xl);
    cudaGetSymbolAddress((void**)&qh, g_qh);
    cudaGetSymbolAddress((void**)&ql, g_ql);
    cudaGetSymbolAddress((void**)&kh, g_kh);
    cudaGetSymbolAddress((void**)&kl, g_kl);
    cudaGetSymbolAddress((void**)&vh, g_vh);
    cudaGetSymbolAddress((void**)&vl, g_vl);
    cudaGetSymbolAddress((void**)&oh, g_oh);
    cudaGetSymbolAddress((void**)&ol, g_ol);
    cudaGetSymbolAddress((void**)&wh, g_wh);
    cudaGetSymbolAddress((void**)&wl, g_wl);

    cudaFuncSetAttribute(attn_hmma, cudaFuncAttributeMaxDynamicSharedMemorySize, ASMEM);
    cudaFuncSetAttribute(gemm_qkv,  cudaFuncAttributeMaxDynamicSharedMemorySize, GSMEM);
    cudaFuncSetAttribute(gemm_wo,   cudaFuncAttributeMaxDynamicSharedMemorySize, GSMEM);

    dim3 gg3(BDIM / 128, MTOT / 128, 3);   // fused QKV
    dim3 gg(BDIM / 128, MTOT / 128);

    split_phase<<<MTOT, 256>>>(x, w_phase, carrier, lock, bw, xh, xl, LG);
    tsplit4<<<dim3(32, 32, 4), dim3(32, 8)>>>(wq, wk, wv, wo, wh, wl);

    gemm_qkv<<<gg3, 256, GSMEM>>>(xh, xl, wh, wl, qh, ql, kh, kl, vh, vl);

    attn_hmma<<<dim3(SEQ / 128, NH, NB), 256, ASMEM>>>(amask, qh, ql, kh, kl, vh, vl, LG, oh, ol);

    gemm_wo<<<gg, 256, GSMEM>>>(oh, ol, wh + 3 * (size_t)NW, wl + 3 * (size_t)NW, out);
}

// round 16
// speedup vs baseline: 2.4032x; 1.0929x over previous
#include <cuda_runtime.h>
#include <cuda_bf16.h>
#include <math.h>
#include <stdint.h>

#define BDIM 1024
#define SEQ  1024
#define NB   4
#define NH   16
#define DHD  64
#define MTOT (NB * SEQ)   // 4096
#define NW   (BDIM * BDIM)

// ---------------- scratch (static device memory: allocation-free) ----------------
__device__ float g_LG[NB * NH * SEQ];
__device__ __nv_bfloat16 g_xh[MTOT * BDIM];
__device__ __nv_bfloat16 g_xl[MTOT * BDIM];
__device__ __nv_bfloat16 g_qh[MTOT * BDIM];
__device__ __nv_bfloat16 g_ql[MTOT * BDIM];
__device__ __nv_bfloat16 g_kh[MTOT * BDIM];
__device__ __nv_bfloat16 g_kl[MTOT * BDIM];
__device__ __nv_bfloat16 g_vh[MTOT * BDIM];
__device__ __nv_bfloat16 g_vl[MTOT * BDIM];
__device__ __nv_bfloat16 g_oh[MTOT * BDIM];
__device__ __nv_bfloat16 g_ol[MTOT * BDIM];
__device__ __nv_bfloat16 g_wh[4][NW];   // transposed [N][K] hi
__device__ __nv_bfloat16 g_wl[4][NW];   // transposed [N][K] lo

// ================= PTX helpers =================
__device__ __forceinline__ uint32_t smem_u32(const void* p) {
    uint32_t a;
    asm("{ .reg .u64 t; cvta.to.shared.u64 t, %1; cvt.u32.u64 %0, t; }" : "=r"(a) : "l"(p));
    return a;
}
__device__ __forceinline__ void cpa16(uint32_t dst, const void* src) {
    asm volatile("cp.async.cg.shared.global [%0], [%1], 16;" :: "r"(dst), "l"(src));
}
#define CP_COMMIT() asm volatile("cp.async.commit_group;" ::: "memory")
#define CP_WAIT0()  asm volatile("cp.async.wait_group 0;" ::: "memory")

__device__ __forceinline__ void ldsm4(uint32_t a, uint32_t& r0, uint32_t& r1,
                                      uint32_t& r2, uint32_t& r3) {
    asm volatile("ldmatrix.sync.aligned.m8n8.x4.shared.b16 {%0,%1,%2,%3}, [%4];"
                 : "=r"(r0), "=r"(r1), "=r"(r2), "=r"(r3) : "r"(a));
}
__device__ __forceinline__ void ldsm4t(uint32_t a, uint32_t& r0, uint32_t& r1,
                                       uint32_t& r2, uint32_t& r3) {
    asm volatile("ldmatrix.sync.aligned.m8n8.x4.trans.shared.b16 {%0,%1,%2,%3}, [%4];"
                 : "=r"(r0), "=r"(r1), "=r"(r2), "=r"(r3) : "r"(a));
}
__device__ __forceinline__ void mma16816(float* d, uint32_t a0, uint32_t a1, uint32_t a2,
                                         uint32_t a3, uint32_t b0, uint32_t b1) {
    asm volatile("mma.sync.aligned.m16n8k16.row.col.f32.bf16.bf16.f32 "
                 "{%0,%1,%2,%3}, {%4,%5,%6,%7}, {%8,%9}, {%0,%1,%2,%3};"
                 : "+f"(d[0]), "+f"(d[1]), "+f"(d[2]), "+f"(d[3])
                 : "r"(a0), "r"(a1), "r"(a2), "r"(a3), "r"(b0), "r"(b1));
}
__device__ __forceinline__ void split2(float a, float b, uint32_t& h, uint32_t& l) {
    __nv_bfloat16 h0 = __float2bfloat16(a), h1 = __float2bfloat16(b);
    __nv_bfloat162 hh(h0, h1); h = *(uint32_t*)&hh;
    __nv_bfloat16 l0 = __float2bfloat16(a - __bfloat162float(h0));
    __nv_bfloat16 l1 = __float2bfloat16(b - __bfloat162float(h1));
    __nv_bfloat162 ll(l0, l1); l = *(uint32_t*)&ll;
}

// ================= fused x-split + phase/log-gate =================
__global__ __launch_bounds__(256) void split_phase(const float* __restrict__ x,
                                                   const float* __restrict__ w_phase,
                                                   const float* __restrict__ carrier,
                                                   const float* __restrict__ lock,
                                                   const float* __restrict__ bwp,
                                                   __nv_bfloat16* __restrict__ hi,
                                                   __nv_bfloat16* __restrict__ lo,
                                                   float* __restrict__ lg)
{
    const int token = blockIdx.x;
    const int tid = threadIdx.x;
    const size_t i = (size_t)token * BDIM + tid * 4;
    float4 v = *(const float4*)(x + i);
    uint32_t h0, l0, h1, l1;
    split2(v.x, v.y, h0, l0);
    split2(v.z, v.w, h1, l1);
    *(uint32_t*)(hi + i)     = h0;  *(uint32_t*)(hi + i + 2) = h1;
    *(uint32_t*)(lo + i)     = l0;  *(uint32_t*)(lo + i + 2) = l1;

    float4 wa = *(const float4*)(w_phase + tid * 8);
    float4 wb = *(const float4*)(w_phase + tid * 8 + 4);
    float p0 = v.x * wa.x + v.y * wa.z + v.z * wb.x + v.w * wb.z;
    float p1 = v.x * wa.y + v.y * wa.w + v.z * wb.y + v.w * wb.w;
#pragma unroll
    for (int o = 16; o > 0; o >>= 1) {
        p0 += __shfl_down_sync(0xffffffffu, p0, o);
        p1 += __shfl_down_sync(0xffffffffu, p1, o);
    }
    __shared__ float s0[8], s1[8];
    __shared__ float phs;
    if ((tid & 31) == 0) { s0[tid >> 5] = p0; s1[tid >> 5] = p1; }
    __syncthreads();
    if (tid == 0) {
        float a = 0.f, b = 0.f;
#pragma unroll
        for (int k = 0; k < 8; k++) { a += s0[k]; b += s1[k]; }
        phs = atan2f(a, b);
    }
    __syncthreads();
    if (tid < NH) {
        float dphi = phs - carrier[tid];
        float w = __expf((cosf(dphi) - 1.f) / bwp[tid]);
        float g = lock[tid] * w + (1.f - lock[tid]);
        const int b2 = token / SEQ, s = token % SEQ;
        lg[((size_t)b2 * NH + tid) * SEQ + s] = __logf(g + 1e-6f);
    }
}

// ================= weight transpose+split (all 4 matrices, z-indexed) =================
__global__ __launch_bounds__(256) void tsplit4(const float* __restrict__ w0,
                                               const float* __restrict__ w1,
                                               const float* __restrict__ w2,
                                               const float* __restrict__ w3,
                                               __nv_bfloat16* __restrict__ ht,
                                               __nv_bfloat16* __restrict__ lt) {
    const float* w = (blockIdx.z == 0) ? w0 : (blockIdx.z == 1) ? w1
                   : (blockIdx.z == 2) ? w2 : w3;
    __nv_bfloat16* hb = ht + (size_t)blockIdx.z * NW;
    __nv_bfloat16* lb = lt + (size_t)blockIdx.z * NW;
    __shared__ float t[32][33];
    const int k0 = blockIdx.y * 32, n0 = blockIdx.x * 32;
    const int tx = threadIdx.x, ty = threadIdx.y;
#pragma unroll
    for (int r = ty; r < 32; r += 8)
        t[r][tx] = w[(size_t)(k0 + r) * BDIM + n0 + tx];
    __syncthreads();
#pragma unroll
    for (int r = ty; r < 32; r += 8) {
        float x = t[tx][r];
        __nv_bfloat16 h = __float2bfloat16(x);
        __nv_bfloat16 l = __float2bfloat16(x - __bfloat162float(h));
        hb[(size_t)(n0 + r) * BDIM + k0 + tx] = h;
        lb[(size_t)(n0 + r) * BDIM + k0 + tx] = l;
    }
}

// ================= HMMA bf16x3 GEMM — single-barrier pipeline, issue-under-compute ====
#define BK     32
#define NK     32                   // 1024/32
#define PITCH  40
#define TILEB  (128 * PITCH * 2)    // 10240 B per tile
#define STG4   (4 * TILEB)          // 40960 B per stage (Ah|Al|Bh|Bl)
#define GSMEM  (2 * STG4)           // 81920 B

struct GemmCtx {
    uint32_t base;
    int tid, ln, wm, wn, m0, n0;
    uint32_t sm_off0, sm_off1;
    const __nv_bfloat16 *pAh0, *pAh1, *pAl0, *pAl1, *pBh0, *pBh1, *pBl0, *pBl1;
};

__device__ __forceinline__ void gemm_mainloop(GemmCtx& c, float acc[4][4][4]) {
    const int ln = c.ln;
    const int lm_sub = ((ln >> 3) & 1) * 8 + (ln & 7);
    const int lm_kc  = ln >> 4;

    auto issueA = [&](int chunk) {
        const int kloc = chunk * BK;
        const uint32_t st = c.base + (chunk & 1) * STG4;
        cpa16(st + 0 * TILEB + c.sm_off0, c.pAh0 + kloc);
        cpa16(st + 0 * TILEB + c.sm_off1, c.pAh1 + kloc);
        cpa16(st + 1 * TILEB + c.sm_off0, c.pAl0 + kloc);
        cpa16(st + 1 * TILEB + c.sm_off1, c.pAl1 + kloc);
    };
    auto issueB = [&](int chunk) {
        const int kloc = chunk * BK;
        const uint32_t st = c.base + (chunk & 1) * STG4;
        cpa16(st + 2 * TILEB + c.sm_off0, c.pBh0 + kloc);
        cpa16(st + 2 * TILEB + c.sm_off1, c.pBh1 + kloc);
        cpa16(st + 3 * TILEB + c.sm_off0, c.pBl0 + kloc);
        cpa16(st + 3 * TILEB + c.sm_off1, c.pBl1 + kloc);
    };

    issueA(0); issueB(0); CP_COMMIT();

    for (int chunk = 0; chunk < NK; chunk++) {
        CP_WAIT0();          // drains load(chunk) — the only pending group
        __syncthreads();     // all warps finished compute(chunk-1); load(chunk) visible
        // safe to overwrite buffer (chunk+1)&1: last read in compute(chunk-1), proven done

        const uint32_t st = c.base + (chunk & 1) * STG4;
        const uint32_t tAh = st, tAl = st + TILEB, tBh = st + 2 * TILEB, tBl = st + 3 * TILEB;
        const bool pre = (chunk + 1 < NK);

#pragma unroll
        for (int ks = 0; ks < 2; ks++) {
            if (pre) { if (ks == 0) issueA(chunk + 1); else issueB(chunk + 1); }
            const uint32_t ko = (ks * 2 + lm_kc) * 8;
            uint32_t ah[4][4], al[4][4];
#pragma unroll
            for (int mi = 0; mi < 4; mi++) {
                const uint32_t ro = ((c.wm * 64 + mi * 16 + lm_sub) * PITCH + ko) * 2;
                ldsm4(tAh + ro, ah[mi][0], ah[mi][1], ah[mi][2], ah[mi][3]);
                ldsm4(tAl + ro, al[mi][0], al[mi][1], al[mi][2], al[mi][3]);
            }
            uint32_t bh[4][2], bl[4][2];
#pragma unroll
            for (int nb = 0; nb < 2; nb++) {
                const uint32_t ro = ((c.wn * 32 + nb * 16 + lm_sub) * PITCH + ko) * 2;
                uint32_t r0, r1, r2, r3;
                ldsm4(tBh + ro, r0, r1, r2, r3);
                bh[nb * 2 + 0][0] = r0; bh[nb * 2 + 0][1] = r2;
                bh[nb * 2 + 1][0] = r1; bh[nb * 2 + 1][1] = r3;
                ldsm4(tBl + ro, r0, r1, r2, r3);
                bl[nb * 2 + 0][0] = r0; bl[nb * 2 + 0][1] = r2;
                bl[nb * 2 + 1][0] = r1; bl[nb * 2 + 1][1] = r3;
            }
#pragma unroll
            for (int mi = 0; mi < 4; mi++)
#pragma unroll
                for (int ni = 0; ni < 4; ni++) {
                    mma16816(acc[mi][ni], ah[mi][0], ah[mi][1], ah[mi][2], ah[mi][3],
                             bh[ni][0], bh[ni][1]);
                    mma16816(acc[mi][ni], al[mi][0], al[mi][1], al[mi][2], al[mi][3],
                             bh[ni][0], bh[ni][1]);
                    mma16816(acc[mi][ni], ah[mi][0], ah[mi][1], ah[mi][2], ah[mi][3],
                             bl[ni][0], bl[ni][1]);
                }
        }
        if (pre) CP_COMMIT();
    }
}

__device__ __forceinline__ void gemm_setup(GemmCtx& c, char* gsm,
                                           const __nv_bfloat16* Ah, const __nv_bfloat16* Al,
                                           const __nv_bfloat16* Bh, const __nv_bfloat16* Bl) {
    c.base = smem_u32(gsm);
    c.tid = threadIdx.x;
    c.ln  = c.tid & 31;
    const int wid = c.tid >> 5;
    c.wm  = wid >> 2;
    c.wn  = wid & 3;
    c.m0 = blockIdx.y * 128;
    c.n0 = blockIdx.x * 128;
    const int ld_row0 = c.tid >> 2;
    const int ld_ch0  = c.tid & 3;
    const int ld_row1 = ld_row0 + 64;
    c.sm_off0 = (ld_row0 * PITCH + ld_ch0 * 8) * 2;
    c.sm_off1 = (ld_row1 * PITCH + ld_ch0 * 8) * 2;
    c.pAh0 = Ah + (size_t)(c.m0 + ld_row0) * BDIM + ld_ch0 * 8;
    c.pAh1 = Ah + (size_t)(c.m0 + ld_row1) * BDIM + ld_ch0 * 8;
    c.pAl0 = Al + (size_t)(c.m0 + ld_row0) * BDIM + ld_ch0 * 8;
    c.pAl1 = Al + (size_t)(c.m0 + ld_row1) * BDIM + ld_ch0 * 8;
    c.pBh0 = Bh + (size_t)(c.n0 + ld_row0) * BDIM + ld_ch0 * 8;
    c.pBh1 = Bh + (size_t)(c.n0 + ld_row1) * BDIM + ld_ch0 * 8;
    c.pBl0 = Bl + (size_t)(c.n0 + ld_row0) * BDIM + ld_ch0 * 8;
    c.pBl1 = Bl + (size_t)(c.n0 + ld_row1) * BDIM + ld_ch0 * 8;
}

// fused QKV GEMM: blockIdx.z selects weight matrix + split output
__global__ __launch_bounds__(256, 2) void gemm_qkv(const __nv_bfloat16* __restrict__ xh,
                                                   const __nv_bfloat16* __restrict__ xl,
                                                   const __nv_bfloat16* __restrict__ whB,
                                                   const __nv_bfloat16* __restrict__ wlB,
                                                   __nv_bfloat16* __restrict__ qh,
                                                   __nv_bfloat16* __restrict__ ql,
                                                   __nv_bfloat16* __restrict__ kh,
                                                   __nv_bfloat16* __restrict__ kl,
                                                   __nv_bfloat16* __restrict__ vh,
                                                   __nv_bfloat16* __restrict__ vl) {
    extern __shared__ __align__(16) char gsm[];
    const int z = blockIdx.z;
    __nv_bfloat16* Ch = (z == 0) ? qh : (z == 1) ? kh : vh;
    __nv_bfloat16* Cl = (z == 0) ? ql : (z == 1) ? kl : vl;

    GemmCtx c;
    gemm_setup(c, gsm, xh, xl, whB + (size_t)z * NW, wlB + (size_t)z * NW);

    float acc[4][4][4];
#pragma unroll
    for (int i = 0; i < 4; i++)
#pragma unroll
        for (int j = 0; j < 4; j++)
#pragma unroll
            for (int r = 0; r < 4; r++) acc[i][j][r] = 0.f;

    gemm_mainloop(c, acc);

    const int er = c.ln >> 2, ec = (c.ln & 3) * 2;
#pragma unroll
    for (int mi = 0; mi < 4; mi++)
#pragma unroll
        for (int ni = 0; ni < 4; ni++) {
            const int m = c.m0 + c.wm * 64 + mi * 16 + er;
            const int n = c.n0 + c.wn * 32 + ni * 8 + ec;
            uint32_t h, l;
            split2(acc[mi][ni][0], acc[mi][ni][1], h, l);
            *(uint32_t*)(Ch + (size_t)m * BDIM + n) = h;
            *(uint32_t*)(Cl + (size_t)m * BDIM + n) = l;
            split2(acc[mi][ni][2], acc[mi][ni][3], h, l);
            *(uint32_t*)(Ch + (size_t)(m + 8) * BDIM + n) = h;
            *(uint32_t*)(Cl + (size_t)(m + 8) * BDIM + n) = l;
        }
}

// output projection: fp32 result
__global__ __launch_bounds__(256, 2) void gemm_wo(const __nv_bfloat16* __restrict__ Ah,
                                                  const __nv_bfloat16* __restrict__ Al,
                                                  const __nv_bfloat16* __restrict__ Bh,
                                                  const __nv_bfloat16* __restrict__ Bl,
                                                  float* __restrict__ C) {
    extern __shared__ __align__(16) char gsm[];
    GemmCtx c;
    gemm_setup(c, gsm, Ah, Al, Bh, Bl);

    float acc[4][4][4];
#pragma unroll
    for (int i = 0; i < 4; i++)
#pragma unroll
        for (int j = 0; j < 4; j++)
#pragma unroll
            for (int r = 0; r < 4; r++) acc[i][j][r] = 0.f;

    gemm_mainloop(c, acc);

    const int er = c.ln >> 2, ec = (c.ln & 3) * 2;
#pragma unroll
    for (int mi = 0; mi < 4; mi++)
#pragma unroll
        for (int ni = 0; ni < 4; ni++) {
            const int m = c.m0 + c.wm * 64 + mi * 16 + er;
            const int n = c.n0 + c.wn * 32 + ni * 8 + ec;
            *(float2*)(C + (size_t)m * BDIM + n)       = make_float2(acc[mi][ni][0], acc[mi][ni][1]);
            *(float2*)(C + (size_t)(m + 8) * BDIM + n) = make_float2(acc[mi][ni][2], acc[mi][ni][3]);
        }
}

// ================= HMMA flash attention — single-barrier KV pipeline =================
#define AP     72
#define QBYTES (128 * AP * 2)          // 18432 per Q tile
#define KVT    (64 * AP * 2)           // 9216 per KV tile
#define STAGEB (4 * KVT + 256)         // 37120 per stage (Kh|Kl|Vh|Vl|LG)
#define ASMEM  (2 * QBYTES + 2 * STAGEB)   // 111104

__global__ __launch_bounds__(256) void attn_hmma(const int* __restrict__ active,
                                                 const __nv_bfloat16* __restrict__ Qh,
                                                 const __nv_bfloat16* __restrict__ Ql,
                                                 const __nv_bfloat16* __restrict__ Kh,
                                                 const __nv_bfloat16* __restrict__ Kl,
                                                 const __nv_bfloat16* __restrict__ Vh,
                                                 const __nv_bfloat16* __restrict__ Vl,
                                                 const float* __restrict__ LG,
                                                 __nv_bfloat16* __restrict__ Oh,
                                                 __nv_bfloat16* __restrict__ Ol)
{
    extern __shared__ __align__(16) char asmem[];
    const uint32_t ub = smem_u32(asmem);

    const int tid = threadIdx.x;
    const int ln  = tid & 31;
    const int w   = tid >> 5;
    const int qb  = blockIdx.x;
    const int h   = blockIdx.y;
    const int b   = blockIdx.z;
    const int q0  = qb * 128;
    const size_t gbase = ((size_t)b * SEQ) * BDIM + (size_t)h * DHD;

    if (active[h] == 0) {
#pragma unroll
        for (int i = 0; i < 4; i++) {
            const int idx = tid + i * 256;
            const int row = idx >> 3, ch = idx & 7;
            *(uint4*)(Oh + gbase + (size_t)(q0 + row) * BDIM + ch * 8) = make_uint4(0, 0, 0, 0);
            *(uint4*)(Ol + gbase + (size_t)(q0 + row) * BDIM + ch * 8) = make_uint4(0, 0, 0, 0);
        }
        return;
    }

    const float* lgp = LG + ((size_t)b * NH + h) * SEQ;
    const int ktiles = 2 * qb + 2;

    // Q tile (hi, lo)
#pragma unroll
    for (int i = 0; i < 4; i++) {
        const int idx = tid + i * 256;
        const int row = idx >> 3, ch = idx & 7;
        cpa16(ub + (row * AP + ch * 8) * 2,          Qh + gbase + (size_t)(q0 + row) * BDIM + ch * 8);
        cpa16(ub + QBYTES + (row * AP + ch * 8) * 2, Ql + gbase + (size_t)(q0 + row) * BDIM + ch * 8);
    }
    CP_COMMIT();

    auto issueKV = [&](int t) {
        const int k0 = t * 64;
        const uint32_t sb = ub + 2 * QBYTES + (t & 1) * STAGEB;
#pragma unroll
        for (int i = 0; i < 2; i++) {
            const int idx = tid + i * 256;
            const int row = idx >> 3, ch = idx & 7;
            const size_t g = gbase + (size_t)(k0 + row) * BDIM + ch * 8;
            const uint32_t s = (row * AP + ch * 8) * 2;
            cpa16(sb + 0 * KVT + s, Kh + g);
            cpa16(sb + 1 * KVT + s, Kl + g);
            cpa16(sb + 2 * KVT + s, Vh + g);
            cpa16(sb + 3 * KVT + s, Vl + g);
        }
        if (tid < 16) cpa16(sb + 4 * KVT + tid * 16, lgp + k0 + tid * 4);
        CP_COMMIT();
    };

    issueKV(0);

    const int lm_sub = ((ln >> 3) & 1) * 8 + (ln & 7);
    const int half   = ln >> 4;
    const int er = ln >> 2, ec = (ln & 3) * 2;
    const int rowg0 = q0 + 16 * w + er;
    const int rowg1 = rowg0 + 8;

    float m0 = -INFINITY, m1 = -INFINITY, l0 = 0.f, l1 = 0.f;
    float ofr[8][4];
#pragma unroll
    for (int j = 0; j < 8; j++)
#pragma unroll
        for (int r = 0; r < 4; r++) ofr[j][r] = 0.f;

    for (int t = 0; t < ktiles; t++) {
        const int k0 = t * 64;
        CP_WAIT0();          // drains Q (t=0) + KV(t)
        __syncthreads();     // all warps finished compute(t-1)
        if (t + 1 < ktiles) issueKV(t + 1);   // buffer (t+1)&1 last read at t-1: safe

        const uint32_t sb = ub + 2 * QBYTES + (t & 1) * STAGEB;
        const uint32_t sKH = sb, sKL = sb + KVT, sVH = sb + 2 * KVT, sVL = sb + 3 * KVT;
        float* slg = (float*)(asmem + 2 * QBYTES + (t & 1) * STAGEB + 4 * KVT);

        if (k0 <= q0 + 16 * w + 15) {
            float sf[8][4];
#pragma unroll
            for (int j = 0; j < 8; j++)
#pragma unroll
                for (int r = 0; r < 4; r++) sf[j][r] = 0.f;

#pragma unroll
            for (int kc = 0; kc < 4; kc++) {
                const uint32_t qoff = ((16 * w + lm_sub) * AP + kc * 16 + half * 8) * 2;
                uint32_t ah0, ah1, ah2, ah3, al0, al1, al2, al3;
                ldsm4(ub + qoff, ah0, ah1, ah2, ah3);
                ldsm4(ub + QBYTES + qoff, al0, al1, al2, al3);
#pragma unroll
                for (int g = 0; g < 4; g++) {
                    const uint32_t koff = ((g * 16 + lm_sub) * AP + kc * 16 + half * 8) * 2;
                    uint32_t bh0, bh1, bh2, bh3, bl0, bl1, bl2, bl3;
                    ldsm4(sKH + koff, bh0, bh1, bh2, bh3);
                    ldsm4(sKL + koff, bl0, bl1, bl2, bl3);
                    mma16816(sf[2 * g],     ah0, ah1, ah2, ah3, bh0, bh2);
                    mma16816(sf[2 * g + 1], ah0, ah1, ah2, ah3, bh1, bh3);
                    mma16816(sf[2 * g],     al0, al1, al2, al3, bh0, bh2);
                    mma16816(sf[2 * g + 1], al0, al1, al2, al3, bh1, bh3);
                    mma16816(sf[2 * g],     ah0, ah1, ah2, ah3, bl0, bl2);
                    mma16816(sf[2 * g + 1], ah0, ah1, ah2, ah3, bl1, bl3);
                }
            }

            // scale + gate (+ causal mask only on boundary tiles), online softmax
            float mx0 = -INFINITY, mx1 = -INFINITY;
            if (k0 + 63 <= q0 + 16 * w) {   // warp-uniform: tile fully unmasked
#pragma unroll
                for (int j = 0; j < 8; j++) {
                    const float g0 = slg[8 * j + ec], g1 = slg[8 * j + ec + 1];
                    float v0 = fmaf(sf[j][0], 0.125f, g0);
                    float v1 = fmaf(sf[j][1], 0.125f, g1);
                    float v2 = fmaf(sf[j][2], 0.125f, g0);
                    float v3 = fmaf(sf[j][3], 0.125f, g1);
                    sf[j][0] = v0; sf[j][1] = v1; sf[j][2] = v2; sf[j][3] = v3;
                    mx0 = fmaxf(mx0, fmaxf(v0, v1));
                    mx1 = fmaxf(mx1, fmaxf(v2, v3));
                }
            } else {
#pragma unroll
                for (int j = 0; j < 8; j++) {
                    const int c0 = k0 + 8 * j + ec, c1 = c0 + 1;
                    const float g0 = slg[8 * j + ec], g1 = slg[8 * j + ec + 1];
                    float v0 = fmaf(sf[j][0], 0.125f, g0); if (c0 > rowg0) v0 = -INFINITY;
                    float v1 = fmaf(sf[j][1], 0.125f, g1); if (c1 > rowg0) v1 = -INFINITY;
                    float v2 = fmaf(sf[j][2], 0.125f, g0); if (c0 > rowg1) v2 = -INFINITY;
                    float v3 = fmaf(sf[j][3], 0.125f, g1); if (c1 > rowg1) v3 = -INFINITY;
                    sf[j][0] = v0; sf[j][1] = v1; sf[j][2] = v2; sf[j][3] = v3;
                    mx0 = fmaxf(mx0, fmaxf(v0, v1));
                    mx1 = fmaxf(mx1, fmaxf(v2, v3));
                }
            }
            mx0 = fmaxf(mx0, __shfl_xor_sync(0xffffffffu, mx0, 1));
            mx0 = fmaxf(mx0, __shfl_xor_sync(0xffffffffu, mx0, 2));
            mx1 = fmaxf(mx1, __shfl_xor_sync(0xffffffffu, mx1, 1));
            mx1 = fmaxf(mx1, __shfl_xor_sync(0xffffffffu, mx1, 2));
            const float mn0 = fmaxf(m0, mx0), mn1 = fmaxf(m1, mx1);
            const float fac0 = __expf(m0 - mn0), fac1 = __expf(m1 - mn1);
            m0 = mn0; m1 = mn1;

            float sum0 = 0.f, sum1 = 0.f;
#pragma unroll
            for (int j = 0; j < 8; j++) {
                float p0 = __expf(sf[j][0] - m0), p1 = __expf(sf[j][1] - m0);
                float p2 = __expf(sf[j][2] - m1), p3 = __expf(sf[j][3] - m1);
                sf[j][0] = p0; sf[j][1] = p1; sf[j][2] = p2; sf[j][3] = p3;
                sum0 += p0 + p1; sum1 += p2 + p3;
            }
            sum0 += __shfl_xor_sync(0xffffffffu, sum0, 1);
            sum0 += __shfl_xor_sync(0xffffffffu, sum0, 2);
            sum1 += __shfl_xor_sync(0xffffffffu, sum1, 1);
            sum1 += __shfl_xor_sync(0xffffffffu, sum1, 2);
            l0 = l0 * fac0 + sum0;
            l1 = l1 * fac1 + sum1;
#pragma unroll
            for (int j = 0; j < 8; j++) {
                ofr[j][0] *= fac0; ofr[j][1] *= fac0;
                ofr[j][2] *= fac1; ofr[j][3] *= fac1;
            }

            uint32_t aph[4][4], apl[4][4];
#pragma unroll
            for (int tt = 0; tt < 4; tt++) {
                split2(sf[2 * tt][0],     sf[2 * tt][1],     aph[tt][0], apl[tt][0]);
                split2(sf[2 * tt][2],     sf[2 * tt][3],     aph[tt][1], apl[tt][1]);
                split2(sf[2 * tt + 1][0], sf[2 * tt + 1][1], aph[tt][2], apl[tt][2]);
                split2(sf[2 * tt + 1][2], sf[2 * tt + 1][3], aph[tt][3], apl[tt][3]);
            }

#pragma unroll
            for (int tt = 0; tt < 4; tt++) {
#pragma unroll
                for (int g = 0; g < 4; g++) {
                    const uint32_t voff = ((tt * 16 + lm_sub) * AP + g * 16 + half * 8) * 2;
                    uint32_t vh0, vh1, vh2, vh3, vl0, vl1, vl2, vl3;
                    ldsm4t(sVH + voff, vh0, vh1, vh2, vh3);
                    ldsm4t(sVL + voff, vl0, vl1, vl2, vl3);
                    mma16816(ofr[2 * g],     aph[tt][0], aph[tt][1], aph[tt][2], aph[tt][3], vh0, vh1);
                    mma16816(ofr[2 * g + 1], aph[tt][0], aph[tt][1], aph[tt][2], aph[tt][3], vh2, vh3);
                    mma16816(ofr[2 * g],     apl[tt][0], apl[tt][1], apl[tt][2], apl[tt][3], vh0, vh1);
                    mma16816(ofr[2 * g + 1], apl[tt][0], apl[tt][1], apl[tt][2], apl[tt][3], vh2, vh3);
                    mma16816(ofr[2 * g],     aph[tt][0], aph[tt][1], aph[tt][2], aph[tt][3], vl0, vl1);
                    mma16816(ofr[2 * g + 1], aph[tt][0], aph[tt][1], aph[tt][2], aph[tt][3], vl2, vl3);
                }
            }
        }
    }

    const float inv0 = 1.f / l0, inv1 = 1.f / l1;
#pragma unroll
    for (int j = 0; j < 8; j++) {
        uint32_t hh, ll;
        split2(ofr[j][0] * inv0, ofr[j][1] * inv0, hh, ll);
        *(uint32_t*)(Oh + gbase + (size_t)rowg0 * BDIM + 8 * j + ec) = hh;
        *(uint32_t*)(Ol + gbase + (size_t)rowg0 * BDIM + 8 * j + ec) = ll;
        split2(ofr[j][2] * inv1, ofr[j][3] * inv1, hh, ll);
        *(uint32_t*)(Oh + gbase + (size_t)rowg1 * BDIM + 8 * j + ec) = hh;
        *(uint32_t*)(Ol + gbase + (size_t)rowg1 * BDIM + 8 * j + ec) = ll;
    }
}

// ---------------- launch ----------------
extern "C" void kernel_launch(void* const* d_in, const int* in_sizes, int n_in,
                              void* d_out, int out_size)
{
    const float* x        = (const float*)d_in[0];
    const float* wq       = (const float*)d_in[1];
    const float* wk       = (const float*)d_in[2];
    const float* wv       = (const float*)d_in[3];
    const float* wo       = (const float*)d_in[4];
    const float* w_phase  = (const float*)d_in[5];
    const float* carrier  = (const float*)d_in[6];
    const float* lock     = (const float*)d_in[7];
    const float* bw       = (const float*)d_in[8];
    const int*   amask    = (const int*)d_in[9];
    float* out = (float*)d_out;

    float *LG;
    __nv_bfloat16 *xh, *xl, *qh, *ql, *kh, *kl, *vh, *vl, *oh, *ol, *wh, *wl;
    cudaGetSymbolAddress((void**)&LG, g_LG);
    cudaGetSymbolAddress((void**)&xh, g_xh);
    cudaGetSymbolAddress((void**)&xl, g_xl);
    cudaGetSymbolAddress((void**)&qh, g_qh);
    cudaGetSymbolAddress((void**)&ql, g_ql);
    cudaGetSymbolAddress((void**)&kh, g_kh);
    cudaGetSymbolAddress((void**)&kl, g_kl);
    cudaGetSymbolAddress((void**)&vh, g_vh);
    cudaGetSymbolAddress((void**)&vl, g_vl);
    cudaGetSymbolAddress((void**)&oh, g_oh);
    cudaGetSymbolAddress((void**)&ol, g_ol);
    cudaGetSymbolAddress((void**)&wh, g_wh);
    cudaGetSymbolAddress((void**)&wl, g_wl);

    cudaFuncSetAttribute(attn_hmma, cudaFuncAttributeMaxDynamicSharedMemorySize, ASMEM);
    cudaFuncSetAttribute(gemm_qkv,  cudaFuncAttributeMaxDynamicSharedMemorySize, GSMEM);
    cudaFuncSetAttribute(gemm_wo,   cudaFuncAttributeMaxDynamicSharedMemorySize, GSMEM);

    dim3 gg3(BDIM / 128, MTOT / 128, 3);   // fused QKV
    dim3 gg(BDIM / 128, MTOT / 128);

    split_phase<<<MTOT, 256>>>(x, w_phase, carrier, lock, bw, xh, xl, LG);
    tsplit4<<<dim3(32, 32, 4), dim3(32, 8)>>>(wq, wk, wv, wo, wh, wl);

    gemm_qkv<<<gg3, 256, GSMEM>>>(xh, xl, wh, wl, qh, ql, kh, kl, vh, vl);

    attn_hmma<<<dim3(SEQ / 128, NH, NB), 256, ASMEM>>>(amask, qh, ql, kh, kl, vh, vl, LG, oh, ol);

    gemm_wo<<<gg, 256, GSMEM>>>(oh, ol, wh + 3 * (size_t)NW, wl + 3 * (size_t)NW, out);
}

// round 17
// speedup vs baseline: 2.4130x; 1.0040x over previous
#include <cuda_runtime.h>
#include <cuda_bf16.h>
#include <math.h>
#include <stdint.h>

#define BDIM 1024
#define SEQ  1024
#define NB   4
#define NH   16
#define DHD  64
#define MTOT (NB * SEQ)   // 4096
#define NW   (BDIM * BDIM)

// ---------------- scratch (static device memory: allocation-free) ----------------
__device__ float g_LG[NB * NH * SEQ];
__device__ __nv_bfloat16 g_xh[MTOT * BDIM];
__device__ __nv_bfloat16 g_xl[MTOT * BDIM];
__device__ __nv_bfloat16 g_qh[MTOT * BDIM];
__device__ __nv_bfloat16 g_ql[MTOT * BDIM];
__device__ __nv_bfloat16 g_kh[MTOT * BDIM];
__device__ __nv_bfloat16 g_kl[MTOT * BDIM];
__device__ __nv_bfloat16 g_vh[MTOT * BDIM];
__device__ __nv_bfloat16 g_vl[MTOT * BDIM];
__device__ __nv_bfloat16 g_oh[MTOT * BDIM];
__device__ __nv_bfloat16 g_ol[MTOT * BDIM];
__device__ __nv_bfloat16 g_wh[4][NW];   // transposed [N][K] hi
__device__ __nv_bfloat16 g_wl[4][NW];   // transposed [N][K] lo

// ================= PTX helpers =================
__device__ __forceinline__ uint32_t smem_u32(const void* p) {
    uint32_t a;
    asm("{ .reg .u64 t; cvta.to.shared.u64 t, %1; cvt.u32.u64 %0, t; }" : "=r"(a) : "l"(p));
    return a;
}
__device__ __forceinline__ void cpa16(uint32_t dst, const void* src) {
    asm volatile("cp.async.cg.shared.global [%0], [%1], 16;" :: "r"(dst), "l"(src));
}
#define CP_COMMIT() asm volatile("cp.async.commit_group;" ::: "memory")
#define CP_WAIT0()  asm volatile("cp.async.wait_group 0;" ::: "memory")

__device__ __forceinline__ void ldsm4(uint32_t a, uint32_t& r0, uint32_t& r1,
                                      uint32_t& r2, uint32_t& r3) {
    asm volatile("ldmatrix.sync.aligned.m8n8.x4.shared.b16 {%0,%1,%2,%3}, [%4];"
                 : "=r"(r0), "=r"(r1), "=r"(r2), "=r"(r3) : "r"(a));
}
__device__ __forceinline__ void ldsm4t(uint32_t a, uint32_t& r0, uint32_t& r1,
                                       uint32_t& r2, uint32_t& r3) {
    asm volatile("ldmatrix.sync.aligned.m8n8.x4.trans.shared.b16 {%0,%1,%2,%3}, [%4];"
                 : "=r"(r0), "=r"(r1), "=r"(r2), "=r"(r3) : "r"(a));
}
__device__ __forceinline__ void mma16816(float* d, uint32_t a0, uint32_t a1, uint32_t a2,
                                         uint32_t a3, uint32_t b0, uint32_t b1) {
    asm volatile("mma.sync.aligned.m16n8k16.row.col.f32.bf16.bf16.f32 "
                 "{%0,%1,%2,%3}, {%4,%5,%6,%7}, {%8,%9}, {%0,%1,%2,%3};"
                 : "+f"(d[0]), "+f"(d[1]), "+f"(d[2]), "+f"(d[3])
                 : "r"(a0), "r"(a1), "r"(a2), "r"(a3), "r"(b0), "r"(b1));
}
__device__ __forceinline__ void split2(float a, float b, uint32_t& h, uint32_t& l) {
    __nv_bfloat16 h0 = __float2bfloat16(a), h1 = __float2bfloat16(b);
    __nv_bfloat162 hh(h0, h1); h = *(uint32_t*)&hh;
    __nv_bfloat16 l0 = __float2bfloat16(a - __bfloat162float(h0));
    __nv_bfloat16 l1 = __float2bfloat16(b - __bfloat162float(h1));
    __nv_bfloat162 ll(l0, l1); l = *(uint32_t*)&ll;
}

// ================= fused x-split + phase/log-gate =================
__global__ __launch_bounds__(256) void split_phase(const float* __restrict__ x,
                                                   const float* __restrict__ w_phase,
                                                   const float* __restrict__ carrier,
                                                   const float* __restrict__ lock,
                                                   const float* __restrict__ bwp,
                                                   __nv_bfloat16* __restrict__ hi,
                                                   __nv_bfloat16* __restrict__ lo,
                                                   float* __restrict__ lg)
{
    const int token = blockIdx.x;
    const int tid = threadIdx.x;
    const size_t i = (size_t)token * BDIM + tid * 4;
    float4 v = *(const float4*)(x + i);
    uint32_t h0, l0, h1, l1;
    split2(v.x, v.y, h0, l0);
    split2(v.z, v.w, h1, l1);
    *(uint32_t*)(hi + i)     = h0;  *(uint32_t*)(hi + i + 2) = h1;
    *(uint32_t*)(lo + i)     = l0;  *(uint32_t*)(lo + i + 2) = l1;

    float4 wa = *(const float4*)(w_phase + tid * 8);
    float4 wb = *(const float4*)(w_phase + tid * 8 + 4);
    float p0 = v.x * wa.x + v.y * wa.z + v.z * wb.x + v.w * wb.z;
    float p1 = v.x * wa.y + v.y * wa.w + v.z * wb.y + v.w * wb.w;
#pragma unroll
    for (int o = 16; o > 0; o >>= 1) {
        p0 += __shfl_down_sync(0xffffffffu, p0, o);
        p1 += __shfl_down_sync(0xffffffffu, p1, o);
    }
    __shared__ float s0[8], s1[8];
    __shared__ float phs;
    if ((tid & 31) == 0) { s0[tid >> 5] = p0; s1[tid >> 5] = p1; }
    __syncthreads();
    if (tid == 0) {
        float a = 0.f, b = 0.f;
#pragma unroll
        for (int k = 0; k < 8; k++) { a += s0[k]; b += s1[k]; }
        phs = atan2f(a, b);
    }
    __syncthreads();
    if (tid < NH) {
        float dphi = phs - carrier[tid];
        float w = __expf((cosf(dphi) - 1.f) / bwp[tid]);
        float g = lock[tid] * w + (1.f - lock[tid]);
        const int b2 = token / SEQ, s = token % SEQ;
        lg[((size_t)b2 * NH + tid) * SEQ + s] = __logf(g + 1e-6f);
    }
}

// ================= weight transpose+split (all 4 matrices, z-indexed) =================
__global__ __launch_bounds__(256) void tsplit4(const float* __restrict__ w0,
                                               const float* __restrict__ w1,
                                               const float* __restrict__ w2,
                                               const float* __restrict__ w3,
                                               __nv_bfloat16* __restrict__ ht,
                                               __nv_bfloat16* __restrict__ lt) {
    const float* w = (blockIdx.z == 0) ? w0 : (blockIdx.z == 1) ? w1
                   : (blockIdx.z == 2) ? w2 : w3;
    __nv_bfloat16* hb = ht + (size_t)blockIdx.z * NW;
    __nv_bfloat16* lb = lt + (size_t)blockIdx.z * NW;
    __shared__ float t[32][33];
    const int k0 = blockIdx.y * 32, n0 = blockIdx.x * 32;
    const int tx = threadIdx.x, ty = threadIdx.y;
#pragma unroll
    for (int r = ty; r < 32; r += 8)
        t[r][tx] = w[(size_t)(k0 + r) * BDIM + n0 + tx];
    __syncthreads();
#pragma unroll
    for (int r = ty; r < 32; r += 8) {
        float x = t[tx][r];
        __nv_bfloat16 h = __float2bfloat16(x);
        __nv_bfloat16 l = __float2bfloat16(x - __bfloat162float(h));
        hb[(size_t)(n0 + r) * BDIM + k0 + tx] = h;
        lb[(size_t)(n0 + r) * BDIM + k0 + tx] = l;
    }
}

// ================= HMMA bf16x3 GEMM — single-barrier pipeline, issue-under-compute ====
#define BK     32
#define NK     32                   // 1024/32
#define PITCH  40
#define TILEB  (128 * PITCH * 2)    // 10240 B per tile
#define STG4   (4 * TILEB)          // 40960 B per stage (Ah|Al|Bh|Bl)
#define GSMEM  (2 * STG4)           // 81920 B

struct GemmCtx {
    uint32_t base;
    int tid, ln, wm, wn, m0, n0;
    uint32_t sm_off0, sm_off1;
    const __nv_bfloat16 *pAh0, *pAh1, *pAl0, *pAl1, *pBh0, *pBh1, *pBl0, *pBl1;
};

__device__ __forceinline__ void gemm_mainloop(GemmCtx& c, float acc[4][4][4]) {
    const int ln = c.ln;
    const int lm_sub = ((ln >> 3) & 1) * 8 + (ln & 7);
    const int lm_kc  = ln >> 4;

    auto issueA = [&](int chunk) {
        const int kloc = chunk * BK;
        const uint32_t st = c.base + (chunk & 1) * STG4;
        cpa16(st + 0 * TILEB + c.sm_off0, c.pAh0 + kloc);
        cpa16(st + 0 * TILEB + c.sm_off1, c.pAh1 + kloc);
        cpa16(st + 1 * TILEB + c.sm_off0, c.pAl0 + kloc);
        cpa16(st + 1 * TILEB + c.sm_off1, c.pAl1 + kloc);
    };
    auto issueB = [&](int chunk) {
        const int kloc = chunk * BK;
        const uint32_t st = c.base + (chunk & 1) * STG4;
        cpa16(st + 2 * TILEB + c.sm_off0, c.pBh0 + kloc);
        cpa16(st + 2 * TILEB + c.sm_off1, c.pBh1 + kloc);
        cpa16(st + 3 * TILEB + c.sm_off0, c.pBl0 + kloc);
        cpa16(st + 3 * TILEB + c.sm_off1, c.pBl1 + kloc);
    };

    issueA(0); issueB(0); CP_COMMIT();

    for (int chunk = 0; chunk < NK; chunk++) {
        CP_WAIT0();          // drains load(chunk) — the only pending group
        __syncthreads();     // all warps finished compute(chunk-1); load(chunk) visible

        const uint32_t st = c.base + (chunk & 1) * STG4;
        const uint32_t tAh = st, tAl = st + TILEB, tBh = st + 2 * TILEB, tBl = st + 3 * TILEB;
        const bool pre = (chunk + 1 < NK);

#pragma unroll
        for (int ks = 0; ks < 2; ks++) {
            if (pre) { if (ks == 0) issueA(chunk + 1); else issueB(chunk + 1); }
            const uint32_t ko = (ks * 2 + lm_kc) * 8;
            uint32_t ah[4][4], al[4][4];
#pragma unroll
            for (int mi = 0; mi < 4; mi++) {
                const uint32_t ro = ((c.wm * 64 + mi * 16 + lm_sub) * PITCH + ko) * 2;
                ldsm4(tAh + ro, ah[mi][0], ah[mi][1], ah[mi][2], ah[mi][3]);
                ldsm4(tAl + ro, al[mi][0], al[mi][1], al[mi][2], al[mi][3]);
            }
            uint32_t bh[4][2], bl[4][2];
#pragma unroll
            for (int nb = 0; nb < 2; nb++) {
                const uint32_t ro = ((c.wn * 32 + nb * 16 + lm_sub) * PITCH + ko) * 2;
                uint32_t r0, r1, r2, r3;
                ldsm4(tBh + ro, r0, r1, r2, r3);
                bh[nb * 2 + 0][0] = r0; bh[nb * 2 + 0][1] = r2;
                bh[nb * 2 + 1][0] = r1; bh[nb * 2 + 1][1] = r3;
                ldsm4(tBl + ro, r0, r1, r2, r3);
                bl[nb * 2 + 0][0] = r0; bl[nb * 2 + 0][1] = r2;
                bl[nb * 2 + 1][0] = r1; bl[nb * 2 + 1][1] = r3;
            }
#pragma unroll
            for (int mi = 0; mi < 4; mi++)
#pragma unroll
                for (int ni = 0; ni < 4; ni++) {
                    mma16816(acc[mi][ni], ah[mi][0], ah[mi][1], ah[mi][2], ah[mi][3],
                             bh[ni][0], bh[ni][1]);
                    mma16816(acc[mi][ni], al[mi][0], al[mi][1], al[mi][2], al[mi][3],
                             bh[ni][0], bh[ni][1]);
                    mma16816(acc[mi][ni], ah[mi][0], ah[mi][1], ah[mi][2], ah[mi][3],
                             bl[ni][0], bl[ni][1]);
                }
        }
        if (pre) CP_COMMIT();
    }
}

__device__ __forceinline__ void gemm_setup(GemmCtx& c, char* gsm,
                                           const __nv_bfloat16* Ah, const __nv_bfloat16* Al,
                                           const __nv_bfloat16* Bh, const __nv_bfloat16* Bl) {
    c.base = smem_u32(gsm);
    c.tid = threadIdx.x;
    c.ln  = c.tid & 31;
    const int wid = c.tid >> 5;
    c.wm  = wid >> 2;
    c.wn  = wid & 3;
    c.m0 = blockIdx.y * 128;
    c.n0 = blockIdx.x * 128;
    const int ld_row0 = c.tid >> 2;
    const int ld_ch0  = c.tid & 3;
    const int ld_row1 = ld_row0 + 64;
    c.sm_off0 = (ld_row0 * PITCH + ld_ch0 * 8) * 2;
    c.sm_off1 = (ld_row1 * PITCH + ld_ch0 * 8) * 2;
    c.pAh0 = Ah + (size_t)(c.m0 + ld_row0) * BDIM + ld_ch0 * 8;
    c.pAh1 = Ah + (size_t)(c.m0 + ld_row1) * BDIM + ld_ch0 * 8;
    c.pAl0 = Al + (size_t)(c.m0 + ld_row0) * BDIM + ld_ch0 * 8;
    c.pAl1 = Al + (size_t)(c.m0 + ld_row1) * BDIM + ld_ch0 * 8;
    c.pBh0 = Bh + (size_t)(c.n0 + ld_row0) * BDIM + ld_ch0 * 8;
    c.pBh1 = Bh + (size_t)(c.n0 + ld_row1) * BDIM + ld_ch0 * 8;
    c.pBl0 = Bl + (size_t)(c.n0 + ld_row0) * BDIM + ld_ch0 * 8;
    c.pBl1 = Bl + (size_t)(c.n0 + ld_row1) * BDIM + ld_ch0 * 8;
}

// fused QKV GEMM: blockIdx.z selects weight matrix + split output
__global__ __launch_bounds__(256, 2) void gemm_qkv(const __nv_bfloat16* __restrict__ xh,
                                                   const __nv_bfloat16* __restrict__ xl,
                                                   const __nv_bfloat16* __restrict__ whB,
                                                   const __nv_bfloat16* __restrict__ wlB,
                                                   __nv_bfloat16* __restrict__ qh,
                                                   __nv_bfloat16* __restrict__ ql,
                                                   __nv_bfloat16* __restrict__ kh,
                                                   __nv_bfloat16* __restrict__ kl,
                                                   __nv_bfloat16* __restrict__ vh,
                                                   __nv_bfloat16* __restrict__ vl) {
    extern __shared__ __align__(16) char gsm[];
    const int z = blockIdx.z;
    __nv_bfloat16* Ch = (z == 0) ? qh : (z == 1) ? kh : vh;
    __nv_bfloat16* Cl = (z == 0) ? ql : (z == 1) ? kl : vl;

    GemmCtx c;
    gemm_setup(c, gsm, xh, xl, whB + (size_t)z * NW, wlB + (size_t)z * NW);

    float acc[4][4][4];
#pragma unroll
    for (int i = 0; i < 4; i++)
#pragma unroll
        for (int j = 0; j < 4; j++)
#pragma unroll
            for (int r = 0; r < 4; r++) acc[i][j][r] = 0.f;

    gemm_mainloop(c, acc);

    const int er = c.ln >> 2, ec = (c.ln & 3) * 2;
#pragma unroll
    for (int mi = 0; mi < 4; mi++)
#pragma unroll
        for (int ni = 0; ni < 4; ni++) {
            const int m = c.m0 + c.wm * 64 + mi * 16 + er;
            const int n = c.n0 + c.wn * 32 + ni * 8 + ec;
            uint32_t h, l;
            split2(acc[mi][ni][0], acc[mi][ni][1], h, l);
            *(uint32_t*)(Ch + (size_t)m * BDIM + n) = h;
            *(uint32_t*)(Cl + (size_t)m * BDIM + n) = l;
            split2(acc[mi][ni][2], acc[mi][ni][3], h, l);
            *(uint32_t*)(Ch + (size_t)(m + 8) * BDIM + n) = h;
            *(uint32_t*)(Cl + (size_t)(m + 8) * BDIM + n) = l;
        }
}

// output projection: fp32 result
__global__ __launch_bounds__(256, 2) void gemm_wo(const __nv_bfloat16* __restrict__ Ah,
                                                  const __nv_bfloat16* __restrict__ Al,
                                                  const __nv_bfloat16* __restrict__ Bh,
                                                  const __nv_bfloat16* __restrict__ Bl,
                                                  float* __restrict__ C) {
    extern __shared__ __align__(16) char gsm[];
    GemmCtx c;
    gemm_setup(c, gsm, Ah, Al, Bh, Bl);

    float acc[4][4][4];
#pragma unroll
    for (int i = 0; i < 4; i++)
#pragma unroll
        for (int j = 0; j < 4; j++)
#pragma unroll
            for (int r = 0; r < 4; r++) acc[i][j][r] = 0.f;

    gemm_mainloop(c, acc);

    const int er = c.ln >> 2, ec = (c.ln & 3) * 2;
#pragma unroll
    for (int mi = 0; mi < 4; mi++)
#pragma unroll
        for (int ni = 0; ni < 4; ni++) {
            const int m = c.m0 + c.wm * 64 + mi * 16 + er;
            const int n = c.n0 + c.wn * 32 + ni * 8 + ec;
            *(float2*)(C + (size_t)m * BDIM + n)       = make_float2(acc[mi][ni][0], acc[mi][ni][1]);
            *(float2*)(C + (size_t)(m + 8) * BDIM + n) = make_float2(acc[mi][ni][2], acc[mi][ni][3]);
        }
}

// ================= HMMA flash attention — single-barrier KV pipeline, LPT order =======
#define AP     72
#define QBYTES (128 * AP * 2)          // 18432 per Q tile
#define KVT    (64 * AP * 2)           // 9216 per KV tile
#define STAGEB (4 * KVT + 256)         // 37120 per stage (Kh|Kl|Vh|Vl|LG)
#define ASMEM  (2 * QBYTES + 2 * STAGEB)   // 111104

__global__ __launch_bounds__(256) void attn_hmma(const int* __restrict__ active,
                                                 const __nv_bfloat16* __restrict__ Qh,
                                                 const __nv_bfloat16* __restrict__ Ql,
                                                 const __nv_bfloat16* __restrict__ Kh,
                                                 const __nv_bfloat16* __restrict__ Kl,
                                                 const __nv_bfloat16* __restrict__ Vh,
                                                 const __nv_bfloat16* __restrict__ Vl,
                                                 const float* __restrict__ LG,
                                                 __nv_bfloat16* __restrict__ Oh,
                                                 __nv_bfloat16* __restrict__ Ol)
{
    extern __shared__ __align__(16) char asmem[];
    const uint32_t ub = smem_u32(asmem);

    const int tid = threadIdx.x;
    const int ln  = tid & 31;
    const int w   = tid >> 5;
    // LPT: longest CTAs (largest qb -> most k-tiles) get lowest blockIdx, start first
    const int qb  = (gridDim.x - 1) - blockIdx.x;
    const int h   = blockIdx.y;
    const int b   = blockIdx.z;
    const int q0  = qb * 128;
    const size_t gbase = ((size_t)b * SEQ) * BDIM + (size_t)h * DHD;

    if (active[h] == 0) {
#pragma unroll
        for (int i = 0; i < 4; i++) {
            const int idx = tid + i * 256;
            const int row = idx >> 3, ch = idx & 7;
            *(uint4*)(Oh + gbase + (size_t)(q0 + row) * BDIM + ch * 8) = make_uint4(0, 0, 0, 0);
            *(uint4*)(Ol + gbase + (size_t)(q0 + row) * BDIM + ch * 8) = make_uint4(0, 0, 0, 0);
        }
        return;
    }

    const float* lgp = LG + ((size_t)b * NH + h) * SEQ;
    const int ktiles = 2 * qb + 2;

    // Q tile (hi, lo)
#pragma unroll
    for (int i = 0; i < 4; i++) {
        const int idx = tid + i * 256;
        const int row = idx >> 3, ch = idx & 7;
        cpa16(ub + (row * AP + ch * 8) * 2,          Qh + gbase + (size_t)(q0 + row) * BDIM + ch * 8);
        cpa16(ub + QBYTES + (row * AP + ch * 8) * 2, Ql + gbase + (size_t)(q0 + row) * BDIM + ch * 8);
    }
    CP_COMMIT();

    auto issueKV = [&](int t) {
        const int k0 = t * 64;
        const uint32_t sb = ub + 2 * QBYTES + (t & 1) * STAGEB;
#pragma unroll
        for (int i = 0; i < 2; i++) {
            const int idx = tid + i * 256;
            const int row = idx >> 3, ch = idx & 7;
            const size_t g = gbase + (size_t)(k0 + row) * BDIM + ch * 8;
            const uint32_t s = (row * AP + ch * 8) * 2;
            cpa16(sb + 0 * KVT + s, Kh + g);
            cpa16(sb + 1 * KVT + s, Kl + g);
            cpa16(sb + 2 * KVT + s, Vh + g);
            cpa16(sb + 3 * KVT + s, Vl + g);
        }
        if (tid < 16) cpa16(sb + 4 * KVT + tid * 16, lgp + k0 + tid * 4);
        CP_COMMIT();
    };

    issueKV(0);

    const int lm_sub = ((ln >> 3) & 1) * 8 + (ln & 7);
    const int half   = ln >> 4;
    const int er = ln >> 2, ec = (ln & 3) * 2;
    const int rowg0 = q0 + 16 * w + er;
    const int rowg1 = rowg0 + 8;

    float m0 = -INFINITY, m1 = -INFINITY, l0 = 0.f, l1 = 0.f;
    float ofr[8][4];
#pragma unroll
    for (int j = 0; j < 8; j++)
#pragma unroll
        for (int r = 0; r < 4; r++) ofr[j][r] = 0.f;

    for (int t = 0; t < ktiles; t++) {
        const int k0 = t * 64;
        CP_WAIT0();          // drains Q (t=0) + KV(t)
        __syncthreads();     // all warps finished compute(t-1)
        if (t + 1 < ktiles) issueKV(t + 1);   // buffer (t+1)&1 last read at t-1: safe

        const uint32_t sb = ub + 2 * QBYTES + (t & 1) * STAGEB;
        const uint32_t sKH = sb, sKL = sb + KVT, sVH = sb + 2 * KVT, sVL = sb + 3 * KVT;
        float* slg = (float*)(asmem + 2 * QBYTES + (t & 1) * STAGEB + 4 * KVT);

        if (k0 <= q0 + 16 * w + 15) {
            float sf[8][4];
#pragma unroll
            for (int j = 0; j < 8; j++)
#pragma unroll
                for (int r = 0; r < 4; r++) sf[j][r] = 0.f;

#pragma unroll
            for (int kc = 0; kc < 4; kc++) {
                const uint32_t qoff = ((16 * w + lm_sub) * AP + kc * 16 + half * 8) * 2;
                uint32_t ah0, ah1, ah2, ah3, al0, al1, al2, al3;
                ldsm4(ub + qoff, ah0, ah1, ah2, ah3);
                ldsm4(ub + QBYTES + qoff, al0, al1, al2, al3);
#pragma unroll
                for (int g = 0; g < 4; g++) {
                    const uint32_t koff = ((g * 16 + lm_sub) * AP + kc * 16 + half * 8) * 2;
                    uint32_t bh0, bh1, bh2, bh3, bl0, bl1, bl2, bl3;
                    ldsm4(sKH + koff, bh0, bh1, bh2, bh3);
                    ldsm4(sKL + koff, bl0, bl1, bl2, bl3);
                    mma16816(sf[2 * g],     ah0, ah1, ah2, ah3, bh0, bh2);
                    mma16816(sf[2 * g + 1], ah0, ah1, ah2, ah3, bh1, bh3);
                    mma16816(sf[2 * g],     al0, al1, al2, al3, bh0, bh2);
                    mma16816(sf[2 * g + 1], al0, al1, al2, al3, bh1, bh3);
                    mma16816(sf[2 * g],     ah0, ah1, ah2, ah3, bl0, bl2);
                    mma16816(sf[2 * g + 1], ah0, ah1, ah2, ah3, bl1, bl3);
                }
            }

            // scale + gate (+ causal mask only on boundary tiles), online softmax
            float mx0 = -INFINITY, mx1 = -INFINITY;
            if (k0 + 63 <= q0 + 16 * w) {   // warp-uniform: tile fully unmasked
#pragma unroll
                for (int j = 0; j < 8; j++) {
                    const float g0 = slg[8 * j + ec], g1 = slg[8 * j + ec + 1];
                    float v0 = fmaf(sf[j][0], 0.125f, g0);
                    float v1 = fmaf(sf[j][1], 0.125f, g1);
                    float v2 = fmaf(sf[j][2], 0.125f, g0);
                    float v3 = fmaf(sf[j][3], 0.125f, g1);
                    sf[j][0] = v0; sf[j][1] = v1; sf[j][2] = v2; sf[j][3] = v3;
                    mx0 = fmaxf(mx0, fmaxf(v0, v1));
                    mx1 = fmaxf(mx1, fmaxf(v2, v3));
                }
            } else {
#pragma unroll
                for (int j = 0; j < 8; j++) {
                    const int c0 = k0 + 8 * j + ec, c1 = c0 + 1;
                    const float g0 = slg[8 * j + ec], g1 = slg[8 * j + ec + 1];
                    float v0 = fmaf(sf[j][0], 0.125f, g0); if (c0 > rowg0) v0 = -INFINITY;
                    float v1 = fmaf(sf[j][1], 0.125f, g1); if (c1 > rowg0) v1 = -INFINITY;
                    float v2 = fmaf(sf[j][2], 0.125f, g0); if (c0 > rowg1) v2 = -INFINITY;
                    float v3 = fmaf(sf[j][3], 0.125f, g1); if (c1 > rowg1) v3 = -INFINITY;
                    sf[j][0] = v0; sf[j][1] = v1; sf[j][2] = v2; sf[j][3] = v3;
                    mx0 = fmaxf(mx0, fmaxf(v0, v1));
                    mx1 = fmaxf(mx1, fmaxf(v2, v3));
                }
            }
            mx0 = fmaxf(mx0, __shfl_xor_sync(0xffffffffu, mx0, 1));
            mx0 = fmaxf(mx0, __shfl_xor_sync(0xffffffffu, mx0, 2));
            mx1 = fmaxf(mx1, __shfl_xor_sync(0xffffffffu, mx1, 1));
            mx1 = fmaxf(mx1, __shfl_xor_sync(0xffffffffu, mx1, 2));
            const float mn0 = fmaxf(m0, mx0), mn1 = fmaxf(m1, mx1);
            const float fac0 = __expf(m0 - mn0), fac1 = __expf(m1 - mn1);
            m0 = mn0; m1 = mn1;

            float sum0 = 0.f, sum1 = 0.f;
#pragma unroll
            for (int j = 0; j < 8; j++) {
                float p0 = __expf(sf[j][0] - m0), p1 = __expf(sf[j][1] - m0);
                float p2 = __expf(sf[j][2] - m1), p3 = __expf(sf[j][3] - m1);
                sf[j][0] = p0; sf[j][1] = p1; sf[j][2] = p2; sf[j][3] = p3;
                sum0 += p0 + p1; sum1 += p2 + p3;
            }
            sum0 += __shfl_xor_sync(0xffffffffu, sum0, 1);
            sum0 += __shfl_xor_sync(0xffffffffu, sum0, 2);
            sum1 += __shfl_xor_sync(0xffffffffu, sum1, 1);
            sum1 += __shfl_xor_sync(0xffffffffu, sum1, 2);
            l0 = l0 * fac0 + sum0;
            l1 = l1 * fac1 + sum1;
#pragma unroll
            for (int j = 0; j < 8; j++) {
                ofr[j][0] *= fac0; ofr[j][1] *= fac0;
                ofr[j][2] *= fac1; ofr[j][3] *= fac1;
            }

            uint32_t aph[4][4], apl[4][4];
#pragma unroll
            for (int tt = 0; tt < 4; tt++) {
                split2(sf[2 * tt][0],     sf[2 * tt][1],     aph[tt][0], apl[tt][0]);
                split2(sf[2 * tt][2],     sf[2 * tt][3],     aph[tt][1], apl[tt][1]);
                split2(sf[2 * tt + 1][0], sf[2 * tt + 1][1], aph[tt][2], apl[tt][2]);
                split2(sf[2 * tt + 1][2], sf[2 * tt + 1][3], aph[tt][3], apl[tt][3]);
            }

#pragma unroll
            for (int tt = 0; tt < 4; tt++) {
#pragma unroll
                for (int g = 0; g < 4; g++) {
                    const uint32_t voff = ((tt * 16 + lm_sub) * AP + g * 16 + half * 8) * 2;
                    uint32_t vh0, vh1, vh2, vh3, vl0, vl1, vl2, vl3;
                    ldsm4t(sVH + voff, vh0, vh1, vh2, vh3);
                    ldsm4t(sVL + voff, vl0, vl1, vl2, vl3);
                    mma16816(ofr[2 * g],     aph[tt][0], aph[tt][1], aph[tt][2], aph[tt][3], vh0, vh1);
                    mma16816(ofr[2 * g + 1], aph[tt][0], aph[tt][1], aph[tt][2], aph[tt][3], vh2, vh3);
                    mma16816(ofr[2 * g],     apl[tt][0], apl[tt][1], apl[tt][2], apl[tt][3], vh0, vh1);
                    mma16816(ofr[2 * g + 1], apl[tt][0], apl[tt][1], apl[tt][2], apl[tt][3], vh2, vh3);
                    mma16816(ofr[2 * g],     aph[tt][0], aph[tt][1], aph[tt][2], aph[tt][3], vl0, vl1);
                    mma16816(ofr[2 * g + 1], aph[tt][0], aph[tt][1], aph[tt][2], aph[tt][3], vl2, vl3);
                }
            }
        }
    }

    const float inv0 = 1.f / l0, inv1 = 1.f / l1;
#pragma unroll
    for (int j = 0; j < 8; j++) {
        uint32_t hh, ll;
        split2(ofr[j][0] * inv0, ofr[j][1] * inv0, hh, ll);
        *(uint32_t*)(Oh + gbase + (size_t)rowg0 * BDIM + 8 * j + ec) = hh;
        *(uint32_t*)(Ol + gbase + (size_t)rowg0 * BDIM + 8 * j + ec) = ll;
        split2(ofr[j][2] * inv1, ofr[j][3] * inv1, hh, ll);
        *(uint32_t*)(Oh + gbase + (size_t)rowg1 * BDIM + 8 * j + ec) = hh;
        *(uint32_t*)(Ol + gbase + (size_t)rowg1 * BDIM + 8 * j + ec) = ll;
    }
}

// ---------------- launch ----------------
extern "C" void kernel_launch(void* const* d_in, const int* in_sizes, int n_in,
                              void* d_out, int out_size)
{
    const float* x        = (const float*)d_in[0];
    const float* wq       = (const float*)d_in[1];
    const float* wk       = (const float*)d_in[2];
    const float* wv       = (const float*)d_in[3];
    const float* wo       = (const float*)d_in[4];
    const float* w_phase  = (const float*)d_in[5];
    const float* carrier  = (const float*)d_in[6];
    const float* lock     = (const float*)d_in[7];
    const float* bw       = (const float*)d_in[8];
    const int*   amask    = (const int*)d_in[9];
    float* out = (float*)d_out;

    float *LG;
    __nv_bfloat16 *xh, *xl, *qh, *ql, *kh, *kl, *vh, *vl, *oh, *ol, *wh, *wl;
    cudaGetSymbolAddress((void**)&LG, g_LG);
    cudaGetSymbolAddress((void**)&xh, g_xh);
    cudaGetSymbolAddress((void**)&xl, g_xl);
    cudaGetSymbolAddress((void**)&qh, g_qh);
    cudaGetSymbolAddress((void**)&ql, g_ql);
    cudaGetSymbolAddress((void**)&kh, g_kh);
    cudaGetSymbolAddress((void**)&kl, g_kl);
    cudaGetSymbolAddress((void**)&vh, g_vh);
    cudaGetSymbolAddress((void**)&vl, g_vl);
    cudaGetSymbolAddress((void**)&oh, g_oh);
    cudaGetSymbolAddress((void**)&ol, g_ol);
    cudaGetSymbolAddress((void**)&wh, g_wh);
    cudaGetSymbolAddress((void**)&wl, g_wl);

    cudaFuncSetAttribute(attn_hmma, cudaFuncAttributeMaxDynamicSharedMemorySize, ASMEM);
    cudaFuncSetAttribute(gemm_qkv,  cudaFuncAttributeMaxDynamicSharedMemorySize, GSMEM);
    cudaFuncSetAttribute(gemm_wo,   cudaFuncAttributeMaxDynamicSharedMemorySize, GSMEM);

    dim3 gg3(BDIM / 128, MTOT / 128, 3);   // fused QKV
    dim3 gg(BDIM / 128, MTOT / 128);

    split_phase<<<MTOT, 256>>>(x, w_phase, carrier, lock, bw, xh, xl, LG);
    tsplit4<<<dim3(32, 32, 4), dim3(32, 8)>>>(wq, wk, wv, wo, wh, wl);

    gemm_qkv<<<gg3, 256, GSMEM>>>(xh, xl, wh, wl, qh, ql, kh, kl, vh, vl);

    attn_hmma<<<dim3(SEQ / 128, NH, NB), 256, ASMEM>>>(amask, qh, ql, kh, kl, vh, vl, LG, oh, ol);

    gemm_wo<<<gg, 256, GSMEM>>>(oh, ol, wh + 3 * (size_t)NW, wl + 3 * (size_t)NW, out);
}